// round 1
// baseline (speedup 1.0000x reference)
#include <cuda_runtime.h>
#include <cstdint>

#define NPTS 65536
#define HN 32
#define CIN 256
#define CMID 64
#define COUT 256
#define KP 15
#define SLOPE 0.1f
#define EPSV 1e-5f

using ull = unsigned long long;

// ---- packed f32x2 helpers (Blackwell fma.rn.f32x2: 2x FFMA throughput) ----
__device__ __forceinline__ ull pk2(float lo, float hi) {
    ull r; asm("mov.b64 %0, {%1,%2};" : "=l"(r) : "f"(lo), "f"(hi)); return r;
}
__device__ __forceinline__ ull dup2(float v) { return pk2(v, v); }
__device__ __forceinline__ void fma2(ull& d, ull a, ull b) {
    asm("fma.rn.f32x2 %0, %1, %2, %3;" : "=l"(d) : "l"(a), "l"(b), "l"(d));
}
__device__ __forceinline__ float2 up2(ull v) {
    float lo, hi; asm("mov.b64 {%0,%1}, %2;" : "=f"(lo), "=f"(hi) : "l"(v));
    return make_float2(lo, hi);
}

// ---- scratch (device globals; no runtime allocation allowed) ----
__device__ float g_x1[NPTS * CMID];     // 16 MB  (stage-1 features, normalized in place)
__device__ float g_out2[NPTS * CMID];   // 16 MB  (kpconv output, pre-norm)
__device__ float g_y[NPTS * COUT];      // 64 MB  (gemm2 output, pre-norm)
__device__ double g_sum1[CMID], g_sq1[CMID];
__device__ double g_sum2[CMID], g_sq2[CMID];
__device__ double g_sum3[COUT], g_sq3[COUT];
__device__ float g_a1[CMID], g_b1v[CMID];
__device__ float g_a2[CMID], g_b2v[CMID];
__device__ float g_a3[COUT], g_b3v[COUT];

// ---- zero stat accumulators (must run each launch: graph replays) ----
__global__ void k_zero() {
    int t = threadIdx.x;
    if (t < CMID) { g_sum1[t] = 0.0; g_sq1[t] = 0.0; g_sum2[t] = 0.0; g_sq2[t] = 0.0; }
    if (t < COUT) { g_sum3[t] = 0.0; g_sq3[t] = 0.0; }
}

// ---- GEMM1: x1 = s_feats(65536x256) @ W1(256x64) + b1 ; accumulate GN1 stats ----
__global__ __launch_bounds__(256) void k_gemm1(const float* __restrict__ A,
                                               const float* __restrict__ W,
                                               const float* __restrict__ bias) {
    __shared__ float As[128][33];
    __shared__ __align__(16) float Bs[32][64];
    __shared__ float ssum[CMID], ssq[CMID];
    int t = threadIdx.x;
    int tr = t >> 4, tc = t & 15;        // 16x16 thread grid: 8 rows x 4 cols each
    int row0 = blockIdx.x * 128;
    ull acc[8][2];
#pragma unroll
    for (int i = 0; i < 8; i++) { acc[i][0] = 0ull; acc[i][1] = 0ull; }
    if (t < CMID) { ssum[t] = 0.f; ssq[t] = 0.f; }

    for (int kk = 0; kk < CIN; kk += 32) {
        __syncthreads();
        for (int e = t; e < 128 * 32; e += 256) {
            int r = e >> 5, c = e & 31;
            As[r][c] = A[(size_t)(row0 + r) * CIN + kk + c];
        }
        for (int e = t; e < 32 * 64; e += 256) {
            int r = e >> 6, c = e & 63;
            Bs[r][c] = W[(kk + r) * CMID + c];
        }
        __syncthreads();
#pragma unroll
        for (int k = 0; k < 32; k++) {
            ulonglong2 bb = *(const ulonglong2*)&Bs[k][tc * 4];
#pragma unroll
            for (int i = 0; i < 8; i++) {
                ull ad = dup2(As[tr * 8 + i][k]);
                fma2(acc[i][0], ad, bb.x);
                fma2(acc[i][1], ad, bb.y);
            }
        }
    }
    float cs[4] = {0, 0, 0, 0}, cq[4] = {0, 0, 0, 0};
#pragma unroll
    for (int i = 0; i < 8; i++) {
        int r = row0 + tr * 8 + i;
        float2 v01 = up2(acc[i][0]);
        float2 v23 = up2(acc[i][1]);
        float v[4] = {v01.x, v01.y, v23.x, v23.y};
#pragma unroll
        for (int j = 0; j < 4; j++) {
            int c = tc * 4 + j;
            float x = v[j] + bias[c];
            g_x1[(size_t)r * CMID + c] = x;
            cs[j] += x; cq[j] += x * x;
        }
    }
#pragma unroll
    for (int j = 0; j < 4; j++) {
        atomicAdd(&ssum[tc * 4 + j], cs[j]);
        atomicAdd(&ssq[tc * 4 + j], cq[j]);
    }
    __syncthreads();
    if (t < CMID) {
        atomicAdd(&g_sum1[t], (double)ssum[t]);
        atomicAdd(&g_sq1[t], (double)ssq[t]);
    }
}

// ---- finalize GN stats -> per-channel scale/shift ----
__global__ void k_finalize(int stage, const float* __restrict__ gamma,
                           const float* __restrict__ beta) {
    int c = threadIdx.x;
    if (stage < 2) {
        if (c >= CMID) return;
        const double* sum = (stage == 0) ? g_sum1 : g_sum2;
        const double* sq  = (stage == 0) ? g_sq1  : g_sq2;
        float* a = (stage == 0) ? g_a1 : g_a2;
        float* b = (stage == 0) ? g_b1v : g_b2v;
        int g = c >> 1;   // 32 groups of 2 channels
        double s = sum[g * 2] + sum[g * 2 + 1];
        double q = sq[g * 2] + sq[g * 2 + 1];
        double cnt = 2.0 * (double)NPTS;
        double mean = s / cnt;
        double var = q / cnt - mean * mean;
        float inv = rsqrtf((float)var + EPSV);
        float av = gamma[c] * inv;
        a[c] = av;
        b[c] = beta[c] - (float)mean * av;
    } else {
        if (c >= COUT) return;
        int g = c >> 3;   // 32 groups of 8 channels
        double s = 0.0, q = 0.0;
#pragma unroll
        for (int i = 0; i < 8; i++) { s += g_sum3[g * 8 + i]; q += g_sq3[g * 8 + i]; }
        double cnt = 8.0 * (double)NPTS;
        double mean = s / cnt;
        double var = q / cnt - mean * mean;
        float inv = rsqrtf((float)var + EPSV);
        float av = gamma[c] * inv;
        g_a3[c] = av;
        g_b3v[c] = beta[c] - (float)mean * av;
    }
}

// ---- apply GN1 + leaky in place on x1 ----
__global__ __launch_bounds__(256) void k_apply1() {
    int i = blockIdx.x * 256 + threadIdx.x;   // over NPTS*CMID/4 float4s
    float4 v = ((const float4*)g_x1)[i];
    int c = (i & 15) * 4;
    float4 r;
    r.x = g_a1[c + 0] * v.x + g_b1v[c + 0];
    r.y = g_a1[c + 1] * v.y + g_b1v[c + 1];
    r.z = g_a1[c + 2] * v.z + g_b1v[c + 2];
    r.w = g_a1[c + 3] * v.w + g_b1v[c + 3];
    r.x = r.x >= 0.f ? r.x : SLOPE * r.x;
    r.y = r.y >= 0.f ? r.y : SLOPE * r.y;
    r.z = r.z >= 0.f ? r.z : SLOPE * r.z;
    r.w = r.w >= 0.f ? r.w : SLOPE * r.w;
    ((float4*)g_x1)[i] = r;
}

// ---- KPConv: 32 points/block, 512 threads ----
// smem layout (floats): kp 48 | w 32*32*16 | A 32*960 | Wt 64*64 | sum 64 | sq 64 | [ints] nbr 1024 | nn 32
#define SMEM_D_BYTES ((48 + 32*32*16 + 32*960 + 64*64 + 64 + 64) * 4 + (1024 + 32) * 4)

__global__ __launch_bounds__(512, 1) void k_kpconv(
        const float* __restrict__ qp, const float* __restrict__ sp,
        const int* __restrict__ nbr, const float* __restrict__ kpts,
        const float* __restrict__ kw, const float* __restrict__ kb) {
    extern __shared__ float sh[];
    float* s_kp  = sh;                         // 48
    float* s_w   = sh + 48;                    // 16384 (w[p][h][k], padded to 16)
    float* s_A   = s_w + 16384;                // 30720 (weighted[p][k*64+c])
    float* s_Wt  = s_A + 30720;                // 4096
    float* s_sum = s_Wt + 4096;                // 64
    float* s_sq  = s_sum + 64;                 // 64
    int* s_nbr   = (int*)(s_sq + 64);          // 1024
    int* s_nn    = s_nbr + 1024;               // 32

    int t = threadIdx.x;
    int p0 = blockIdx.x * 32;

    if (t < 45) s_kp[t] = kpts[t];
    if (t < 64) { s_sum[t] = 0.f; s_sq[t] = 0.f; }
    if (t < 32) s_nn[t] = 0;
    __syncthreads();

    // phase 1: influence weights w[p][h][k] = max(1 - |s[idx] - q[p] - kp[k]|, 0)
    for (int id = t; id < 1024; id += 512) {
        int p = id >> 5, h = id & 31;
        int idx = nbr[(p0 + p) * HN + h];
        s_nbr[id] = idx;
        float dx, dy, dz;
        if ((unsigned)idx < NPTS) {
            dx = sp[idx * 3 + 0] - qp[(p0 + p) * 3 + 0];
            dy = sp[idx * 3 + 1] - qp[(p0 + p) * 3 + 1];
            dz = sp[idx * 3 + 2] - qp[(p0 + p) * 3 + 2];
            atomicAdd(&s_nn[p], 1);
        } else { dx = dy = dz = 1e10f; }
#pragma unroll
        for (int k = 0; k < KP; k++) {
            float ex = dx - s_kp[k * 3 + 0];
            float ey = dy - s_kp[k * 3 + 1];
            float ez = dz - s_kp[k * 3 + 2];
            float dist = sqrtf(ex * ex + ey * ey + ez * ez);
            s_w[id * 16 + k] = fmaxf(1.0f - dist, 0.0f);
        }
        s_w[id * 16 + 15] = 0.f;   // pad for k-pair loads
    }
    __syncthreads();

    // phase 2: weighted[p][k][c] = sum_h w[p][h][k] * x1n[idx[h]][c]
    // thread = (point p, 4 channels); k paired into f32x2 (w pairs are contiguous in smem)
    {
        int c4 = (t & 15) * 4;
        int p = t >> 4;
        ull acc[8][4];
#pragma unroll
        for (int a = 0; a < 8; a++)
#pragma unroll
            for (int b = 0; b < 4; b++) acc[a][b] = 0ull;
        for (int h = 0; h < HN; h++) {
            int idx = s_nbr[p * 32 + h];
            float4 f;
            if ((unsigned)idx < NPTS) f = *(const float4*)&g_x1[(size_t)idx * CMID + c4];
            else f = make_float4(0.f, 0.f, 0.f, 0.f);
            ull fd0 = dup2(f.x), fd1 = dup2(f.y), fd2 = dup2(f.z), fd3 = dup2(f.w);
            const ull* w2 = (const ull*)&s_w[(p * 32 + h) * 16];
#pragma unroll
            for (int kp2 = 0; kp2 < 8; kp2++) {
                ull wv = w2[kp2];
                fma2(acc[kp2][0], wv, fd0);
                fma2(acc[kp2][1], wv, fd1);
                fma2(acc[kp2][2], wv, fd2);
                fma2(acc[kp2][3], wv, fd3);
            }
        }
#pragma unroll
        for (int kp2 = 0; kp2 < 8; kp2++) {
#pragma unroll
            for (int j = 0; j < 4; j++) {
                float2 v = up2(acc[kp2][j]);
                int k0 = kp2 * 2;
                s_A[p * 960 + k0 * 64 + c4 + j] = v.x;
                if (k0 + 1 < KP) s_A[p * 960 + (k0 + 1) * 64 + c4 + j] = v.y;
            }
        }
    }
    __syncthreads();

    // phase 3: out[32][64] = A[32][960] @ kw[960][64], streaming kw tiles through smem
    int tc = t & 15;    // cols tc*4..+3
    int row = t >> 4;   // 0..31
    ull outp[2] = {0ull, 0ull};
    for (int kc0 = 0; kc0 < 960; kc0 += 64) {
        for (int e = t; e < 4096; e += 512)
            s_Wt[e] = kw[(kc0 + (e >> 6)) * CMID + (e & 63)];
        __syncthreads();
#pragma unroll 4
        for (int i = 0; i < 64; i += 4) {
            float4 a4 = *(const float4*)&s_A[row * 960 + kc0 + i];
            float av[4] = {a4.x, a4.y, a4.z, a4.w};
#pragma unroll
            for (int ii = 0; ii < 4; ii++) {
                ulonglong2 wv = *(const ulonglong2*)&s_Wt[(i + ii) * 64 + tc * 4];
                ull ad = dup2(av[ii]);
                fma2(outp[0], ad, wv.x);
                fma2(outp[1], ad, wv.y);
            }
        }
        __syncthreads();
    }
    // epilogue: /nnum + bias, write, GN2 stats
    {
        int nn = s_nn[row];
        float inv = 1.0f / (float)(nn > 1 ? nn : 1);
        float2 o01 = up2(outp[0]);
        float2 o23 = up2(outp[1]);
        float vals[4] = {o01.x, o01.y, o23.x, o23.y};
#pragma unroll
        for (int j = 0; j < 4; j++) {
            int cc = tc * 4 + j;
            float v = vals[j] * inv + kb[cc];
            g_out2[(size_t)(p0 + row) * CMID + cc] = v;
            atomicAdd(&s_sum[cc], v);
            atomicAdd(&s_sq[cc], v * v);
        }
    }
    __syncthreads();
    if (t < 64) {
        atomicAdd(&g_sum2[t], (double)s_sum[t]);
        atomicAdd(&g_sq2[t], (double)s_sq[t]);
    }
}

// ---- GEMM2: y = leaky(GN2(out2)) @ W2(64x256) + b2 ; accumulate GN3 stats ----
#define SMEM_F_BYTES ((64*256 + 64*68 + 256 + 256) * 4)

__global__ __launch_bounds__(256) void k_gemm2(const float* __restrict__ W2,
                                               const float* __restrict__ b2) {
    extern __shared__ float sh[];
    float* s_W   = sh;             // 16384 (full W2)
    float* s_A   = sh + 16384;     // 64*68 (padded)
    float* s_sum = s_A + 64 * 68;  // 256
    float* s_sq  = s_sum + 256;    // 256
    int t = threadIdx.x;
    int row0 = blockIdx.x * 64;

    for (int e = t; e < 64 * 256; e += 256) s_W[e] = W2[e];
    for (int e = t; e < 64 * 64; e += 256) {
        int r = e >> 6, c = e & 63;
        float v = g_out2[(size_t)(row0 + r) * CMID + c];
        v = g_a2[c] * v + g_b2v[c];
        v = v >= 0.f ? v : SLOPE * v;
        s_A[r * 68 + c] = v;
    }
    s_sum[t] = 0.f; s_sq[t] = 0.f;
    __syncthreads();

    int tr = t >> 5;   // rows tr*8..+7
    int tc = t & 31;   // cols tc*8..+7
    ull acc[8][4];
#pragma unroll
    for (int i = 0; i < 8; i++)
#pragma unroll
        for (int j = 0; j < 4; j++) acc[i][j] = 0ull;

    for (int k = 0; k < 64; k++) {
        ulonglong2 w0 = *(const ulonglong2*)&s_W[k * 256 + tc * 8];
        ulonglong2 w1 = *(const ulonglong2*)&s_W[k * 256 + tc * 8 + 4];
#pragma unroll
        for (int i = 0; i < 8; i++) {
            ull ad = dup2(s_A[(tr * 8 + i) * 68 + k]);
            fma2(acc[i][0], ad, w0.x);
            fma2(acc[i][1], ad, w0.y);
            fma2(acc[i][2], ad, w1.x);
            fma2(acc[i][3], ad, w1.y);
        }
    }
    float cs[8] = {0}, cq[8] = {0};
#pragma unroll
    for (int i = 0; i < 8; i++) {
        int r = row0 + tr * 8 + i;
        float2 v0 = up2(acc[i][0]), v1 = up2(acc[i][1]);
        float2 v2 = up2(acc[i][2]), v3 = up2(acc[i][3]);
        float v[8] = {v0.x, v0.y, v1.x, v1.y, v2.x, v2.y, v3.x, v3.y};
#pragma unroll
        for (int j = 0; j < 8; j++) {
            int cc = tc * 8 + j;
            v[j] += b2[cc];
            cs[j] += v[j]; cq[j] += v[j] * v[j];
        }
        float4* dst = (float4*)&g_y[(size_t)r * COUT + tc * 8];
        dst[0] = make_float4(v[0], v[1], v[2], v[3]);
        dst[1] = make_float4(v[4], v[5], v[6], v[7]);
    }
#pragma unroll
    for (int j = 0; j < 8; j++) {
        atomicAdd(&s_sum[tc * 8 + j], cs[j]);
        atomicAdd(&s_sq[tc * 8 + j], cq[j]);
    }
    __syncthreads();
    atomicAdd(&g_sum3[t], (double)s_sum[t]);
    atomicAdd(&g_sq3[t], (double)s_sq[t]);
}

// ---- final: out = leaky(GN3(y) + s_feats) ----
__global__ __launch_bounds__(256) void k_final(const float* __restrict__ sf,
                                               float* __restrict__ out) {
    int i = blockIdx.x * 256 + threadIdx.x;   // over NPTS*COUT/4 float4s
    float4 y = ((const float4*)g_y)[i];
    float4 s = ((const float4*)sf)[i];
    int c = (i & 63) * 4;
    float4 r;
    r.x = g_a3[c + 0] * y.x + g_b3v[c + 0] + s.x;
    r.y = g_a3[c + 1] * y.y + g_b3v[c + 1] + s.y;
    r.z = g_a3[c + 2] * y.z + g_b3v[c + 2] + s.z;
    r.w = g_a3[c + 3] * y.w + g_b3v[c + 3] + s.w;
    r.x = r.x >= 0.f ? r.x : SLOPE * r.x;
    r.y = r.y >= 0.f ? r.y : SLOPE * r.y;
    r.z = r.z >= 0.f ? r.z : SLOPE * r.z;
    r.w = r.w >= 0.f ? r.w : SLOPE * r.w;
    ((float4*)out)[i] = r;
}

extern "C" void kernel_launch(void* const* d_in, const int* in_sizes, int n_in,
                              void* d_out, int out_size) {
    const float* s_feats  = (const float*)d_in[0];
    const float* q_points = (const float*)d_in[1];
    const float* s_points = (const float*)d_in[2];
    const int*   nbr      = (const int*)d_in[3];
    const float* W1       = (const float*)d_in[4];
    const float* b1       = (const float*)d_in[5];
    const float* g1       = (const float*)d_in[6];
    const float* beta1    = (const float*)d_in[7];
    const float* kpw      = (const float*)d_in[8];
    const float* kpb      = (const float*)d_in[9];
    const float* kpts     = (const float*)d_in[10];
    const float* gg       = (const float*)d_in[11];
    const float* gb       = (const float*)d_in[12];
    const float* W2       = (const float*)d_in[13];
    const float* b2       = (const float*)d_in[14];
    const float* g2       = (const float*)d_in[15];
    const float* beta2    = (const float*)d_in[16];
    float* out = (float*)d_out;

    cudaFuncSetAttribute(k_kpconv, cudaFuncAttributeMaxDynamicSharedMemorySize, SMEM_D_BYTES);
    cudaFuncSetAttribute(k_gemm2,  cudaFuncAttributeMaxDynamicSharedMemorySize, SMEM_F_BYTES);

    k_zero<<<1, 256>>>();
    k_gemm1<<<NPTS / 128, 256>>>(s_feats, W1, b1);
    k_finalize<<<1, 256>>>(0, g1, beta1);
    k_apply1<<<NPTS * CMID / 4 / 256, 256>>>();
    k_kpconv<<<NPTS / 32, 512, SMEM_D_BYTES>>>(q_points, s_points, nbr, kpts, kpw, kpb);
    k_finalize<<<1, 256>>>(1, gg, gb);
    k_gemm2<<<NPTS / 64, 256, SMEM_F_BYTES>>>(W2, b2);
    k_finalize<<<1, 256>>>(2, g2, beta2);
    k_final<<<NPTS * COUT / 4 / 256, 256>>>(s_feats, out);
}

// round 3
// speedup vs baseline: 1.4498x; 1.4498x over previous
#include <cuda_runtime.h>
#include <cstdint>

#define NPTS 65536
#define HN 32
#define CIN 256
#define CMID 64
#define COUT 256
#define KP 15
#define SLOPE 0.1f
#define EPSV 1e-5f

using ull = unsigned long long;

// ---- packed f32x2 helpers (Blackwell fma.rn.f32x2: 2x FFMA throughput) ----
__device__ __forceinline__ ull pk2(float lo, float hi) {
    ull r; asm("mov.b64 %0, {%1,%2};" : "=l"(r) : "f"(lo), "f"(hi)); return r;
}
__device__ __forceinline__ ull dup2(float v) { return pk2(v, v); }
__device__ __forceinline__ void fma2(ull& d, ull a, ull b) {
    asm("fma.rn.f32x2 %0, %1, %2, %3;" : "=l"(d) : "l"(a), "l"(b), "l"(d));
}
__device__ __forceinline__ float2 up2(ull v) {
    float lo, hi; asm("mov.b64 {%0,%1}, %2;" : "=f"(lo), "=f"(hi) : "l"(v));
    return make_float2(lo, hi);
}

// ---- scratch (device globals; no runtime allocation allowed) ----
__device__ float g_x1[NPTS * CMID];     // 16 MB
__device__ float g_out2[NPTS * CMID];   // 16 MB
__device__ float g_y[NPTS * COUT];      // 64 MB
__device__ double g_sum1[CMID], g_sq1[CMID];
__device__ double g_sum2[CMID], g_sq2[CMID];
__device__ double g_sum3[COUT], g_sq3[COUT];
__device__ float g_a1[CMID], g_b1v[CMID];
__device__ float g_a2[CMID], g_b2v[CMID];
__device__ float g_a3[COUT], g_b3v[COUT];

__global__ void k_zero() {
    int t = threadIdx.x;
    if (t < CMID) { g_sum1[t] = 0.0; g_sq1[t] = 0.0; g_sum2[t] = 0.0; g_sq2[t] = 0.0; }
    if (t < COUT) { g_sum3[t] = 0.0; g_sq3[t] = 0.0; }
}

// ---- GEMM1: x1 = s_feats(65536x256) @ W1(256x64) + b1 ; accumulate GN1 stats ----
__global__ __launch_bounds__(256) void k_gemm1(const float* __restrict__ A,
                                               const float* __restrict__ W,
                                               const float* __restrict__ bias) {
    __shared__ __align__(16) float As[32][132];   // [k][row], padded
    __shared__ __align__(16) float Bs[32][64];
    __shared__ float ssum[CMID], ssq[CMID];
    int t = threadIdx.x;
    int tr = t >> 4, tc = t & 15;        // 16x16: 8 rows x 4 cols per thread
    int row0 = blockIdx.x * 128;
    ull acc[8][2];
#pragma unroll
    for (int i = 0; i < 8; i++) { acc[i][0] = 0ull; acc[i][1] = 0ull; }
    if (t < CMID) { ssum[t] = 0.f; ssq[t] = 0.f; }

    for (int kk = 0; kk < CIN; kk += 32) {
        __syncthreads();
        for (int e = t; e < 128 * 32; e += 256) {
            int r = e >> 5, c = e & 31;
            As[c][r] = A[(size_t)(row0 + r) * CIN + kk + c];
        }
        for (int e = t; e < 32 * 64; e += 256) {
            int r = e >> 6, c = e & 63;
            Bs[r][c] = W[(kk + r) * CMID + c];
        }
        __syncthreads();
#pragma unroll
        for (int k = 0; k < 32; k++) {
            float4 a0 = *(const float4*)&As[k][tr * 8];
            float4 a1 = *(const float4*)&As[k][tr * 8 + 4];
            ulonglong2 bb = *(const ulonglong2*)&Bs[k][tc * 4];
            ull d;
            d = dup2(a0.x); fma2(acc[0][0], d, bb.x); fma2(acc[0][1], d, bb.y);
            d = dup2(a0.y); fma2(acc[1][0], d, bb.x); fma2(acc[1][1], d, bb.y);
            d = dup2(a0.z); fma2(acc[2][0], d, bb.x); fma2(acc[2][1], d, bb.y);
            d = dup2(a0.w); fma2(acc[3][0], d, bb.x); fma2(acc[3][1], d, bb.y);
            d = dup2(a1.x); fma2(acc[4][0], d, bb.x); fma2(acc[4][1], d, bb.y);
            d = dup2(a1.y); fma2(acc[5][0], d, bb.x); fma2(acc[5][1], d, bb.y);
            d = dup2(a1.z); fma2(acc[6][0], d, bb.x); fma2(acc[6][1], d, bb.y);
            d = dup2(a1.w); fma2(acc[7][0], d, bb.x); fma2(acc[7][1], d, bb.y);
        }
    }
    float cs[4] = {0, 0, 0, 0}, cq[4] = {0, 0, 0, 0};
#pragma unroll
    for (int i = 0; i < 8; i++) {
        int r = row0 + tr * 8 + i;
        float2 v01 = up2(acc[i][0]);
        float2 v23 = up2(acc[i][1]);
        float v[4] = {v01.x, v01.y, v23.x, v23.y};
#pragma unroll
        for (int j = 0; j < 4; j++) {
            int c = tc * 4 + j;
            float x = v[j] + bias[c];
            g_x1[(size_t)r * CMID + c] = x;
            cs[j] += x; cq[j] += x * x;
        }
    }
#pragma unroll
    for (int j = 0; j < 4; j++) {
        atomicAdd(&ssum[tc * 4 + j], cs[j]);
        atomicAdd(&ssq[tc * 4 + j], cq[j]);
    }
    __syncthreads();
    if (t < CMID) {
        atomicAdd(&g_sum1[t], (double)ssum[t]);
        atomicAdd(&g_sq1[t], (double)ssq[t]);
    }
}

// ---- finalize GN stats -> per-channel scale/shift ----
__global__ void k_finalize(int stage, const float* __restrict__ gamma,
                           const float* __restrict__ beta) {
    int c = threadIdx.x;
    if (stage < 2) {
        if (c >= CMID) return;
        const double* sum = (stage == 0) ? g_sum1 : g_sum2;
        const double* sq  = (stage == 0) ? g_sq1  : g_sq2;
        float* a = (stage == 0) ? g_a1 : g_a2;
        float* b = (stage == 0) ? g_b1v : g_b2v;
        int g = c >> 1;
        double s = sum[g * 2] + sum[g * 2 + 1];
        double q = sq[g * 2] + sq[g * 2 + 1];
        double cnt = 2.0 * (double)NPTS;
        double mean = s / cnt;
        double var = q / cnt - mean * mean;
        float inv = rsqrtf((float)var + EPSV);
        float av = gamma[c] * inv;
        a[c] = av;
        b[c] = beta[c] - (float)mean * av;
    } else {
        if (c >= COUT) return;
        int g = c >> 3;
        double s = 0.0, q = 0.0;
#pragma unroll
        for (int i = 0; i < 8; i++) { s += g_sum3[g * 8 + i]; q += g_sq3[g * 8 + i]; }
        double cnt = 8.0 * (double)NPTS;
        double mean = s / cnt;
        double var = q / cnt - mean * mean;
        float inv = rsqrtf((float)var + EPSV);
        float av = gamma[c] * inv;
        g_a3[c] = av;
        g_b3v[c] = beta[c] - (float)mean * av;
    }
}

// ---- apply GN1 + leaky in place on x1 ----
__global__ __launch_bounds__(256) void k_apply1() {
    int i = blockIdx.x * 256 + threadIdx.x;
    float4 v = ((const float4*)g_x1)[i];
    int c = (i & 15) * 4;
    float4 r;
    r.x = g_a1[c + 0] * v.x + g_b1v[c + 0];
    r.y = g_a1[c + 1] * v.y + g_b1v[c + 1];
    r.z = g_a1[c + 2] * v.z + g_b1v[c + 2];
    r.w = g_a1[c + 3] * v.w + g_b1v[c + 3];
    r.x = r.x >= 0.f ? r.x : SLOPE * r.x;
    r.y = r.y >= 0.f ? r.y : SLOPE * r.y;
    r.z = r.z >= 0.f ? r.z : SLOPE * r.z;
    r.w = r.w >= 0.f ? r.w : SLOPE * r.w;
    ((float4*)g_x1)[i] = r;
}

// ---- KPConv: 32 points/block, 512 threads ----
// smem floats: kp 48 | w 16384 | A 32*968 | Wt 4096 | sum 64 | sq 64 | ints: nbr 1024 | nn 32
#define A_STRIDE 968
#define SMEM_D_BYTES ((48 + 16384 + 32*A_STRIDE + 4096 + 64 + 64) * 4 + (1024 + 32) * 4)

__global__ __launch_bounds__(512, 1) void k_kpconv(
        const float* __restrict__ qp, const float* __restrict__ sp,
        const int* __restrict__ nbr, const float* __restrict__ kpts,
        const float* __restrict__ kw, const float* __restrict__ kb) {
    extern __shared__ float sh[];
    float* s_kp  = sh;                          // 48
    float* s_w   = sh + 48;                     // 16384 (w[p][h][16]); reused as partials
    float* s_A   = s_w + 16384;                 // 32*968
    float* s_Wt  = s_A + 32 * A_STRIDE;         // 4096
    float* s_sum = s_Wt + 4096;                 // 64
    float* s_sq  = s_sum + 64;                  // 64
    int* s_nbr   = (int*)(s_sq + 64);           // 1024
    int* s_nn    = s_nbr + 1024;                // 32

    int t = threadIdx.x;
    int p0 = blockIdx.x * 32;

    if (t < 45) s_kp[t] = kpts[t];
    if (t < 64) { s_sum[t] = 0.f; s_sq[t] = 0.f; }
    __syncthreads();

    // phase 1: influence weights w[p][h][k]; warp == one point -> ballot for nnum
    for (int id = t; id < 1024; id += 512) {
        int p = id >> 5, h = id & 31;
        int idx = nbr[(p0 + p) * HN + h];
        s_nbr[id] = idx;
        float dx, dy, dz;
        bool valid = (unsigned)idx < NPTS;
        if (valid) {
            dx = sp[idx * 3 + 0] - qp[(p0 + p) * 3 + 0];
            dy = sp[idx * 3 + 1] - qp[(p0 + p) * 3 + 1];
            dz = sp[idx * 3 + 2] - qp[(p0 + p) * 3 + 2];
        } else { dx = dy = dz = 1e10f; }
        unsigned m = __ballot_sync(0xffffffffu, valid);
        if ((t & 31) == 0) s_nn[p] = __popc(m);
#pragma unroll
        for (int k = 0; k < KP; k++) {
            float ex = dx - s_kp[k * 3 + 0];
            float ey = dy - s_kp[k * 3 + 1];
            float ez = dz - s_kp[k * 3 + 2];
            float dist = sqrtf(ex * ex + ey * ey + ez * ez);
            s_w[id * 16 + k] = fmaxf(1.0f - dist, 0.0f);
        }
        s_w[id * 16 + 15] = 0.f;
    }
    __syncthreads();

    // phase 2: A[p][k*64+c] = sum_h w[p][h][k] * x1[idx][c]   (thread = point p, 4 channels)
    {
        int c4 = (t & 15) * 4;
        int p = t >> 4;
        ull acc[8][4];
#pragma unroll
        for (int a = 0; a < 8; a++)
#pragma unroll
            for (int b = 0; b < 4; b++) acc[a][b] = 0ull;
#pragma unroll 4
        for (int h = 0; h < HN; h++) {
            int idx = s_nbr[p * 32 + h];
            float4 f;
            if ((unsigned)idx < NPTS) f = *(const float4*)&g_x1[(size_t)idx * CMID + c4];
            else f = make_float4(0.f, 0.f, 0.f, 0.f);
            ull fd0 = dup2(f.x), fd1 = dup2(f.y), fd2 = dup2(f.z), fd3 = dup2(f.w);
            const ull* w2 = (const ull*)&s_w[(p * 32 + h) * 16];
#pragma unroll
            for (int kp2 = 0; kp2 < 8; kp2++) {
                ull wv = w2[kp2];
                fma2(acc[kp2][0], wv, fd0);
                fma2(acc[kp2][1], wv, fd1);
                fma2(acc[kp2][2], wv, fd2);
                fma2(acc[kp2][3], wv, fd3);
            }
        }
        __syncthreads();   // s_w reads done block-wide before any partials overwrite (safety)
#pragma unroll
        for (int kp2 = 0; kp2 < 8; kp2++) {
#pragma unroll
            for (int j = 0; j < 4; j++) {
                float2 v = up2(acc[kp2][j]);
                int k0 = kp2 * 2;
                s_A[p * A_STRIDE + k0 * 64 + c4 + j] = v.x;
                if (k0 + 1 < KP) s_A[p * A_STRIDE + (k0 + 1) * 64 + c4 + j] = v.y;
            }
        }
    }
    __syncthreads();

    // phase 3: out[32][64] = A[32][960] @ kw[960][64], 8-way K-split register tiling
    // thread = (kq 0..7, rg 0..3, cg 0..15): rows rg*8..+7, cols cg*4..+3, kc ≡ kq*8+jj per tile
    {
        int kq = t >> 6;
        int rg = (t >> 4) & 3;
        int cg = t & 15;
        ull acc[8][2];
#pragma unroll
        for (int i = 0; i < 8; i++) { acc[i][0] = 0ull; acc[i][1] = 0ull; }

        for (int t0 = 0; t0 < 960; t0 += 64) {
            __syncthreads();
            for (int e = t; e < 1024; e += 512)
                ((float4*)s_Wt)[e] = ((const float4*)(kw + t0 * 64))[e];
            __syncthreads();
#pragma unroll
            for (int jj = 0; jj < 8; jj++) {
                int kc = kq * 8 + jj;
                ulonglong2 wv = *(const ulonglong2*)&s_Wt[kc * 64 + cg * 4];
                const float* arow = &s_A[rg * 8 * A_STRIDE + t0 + kc];
#pragma unroll
                for (int i = 0; i < 8; i++) {
                    ull ad = dup2(arow[i * A_STRIDE]);
                    fma2(acc[i][0], ad, wv.x);
                    fma2(acc[i][1], ad, wv.y);
                }
            }
        }

        // write partials into s_w region (dead after phase 2): [kq][row][col]
        float* s_part = s_w;
#pragma unroll
        for (int i = 0; i < 8; i++) {
            float2 v0 = up2(acc[i][0]);
            float2 v1 = up2(acc[i][1]);
            *(float4*)&s_part[kq * 2048 + (rg * 8 + i) * 64 + cg * 4] =
                make_float4(v0.x, v0.y, v1.x, v1.y);
        }
    }
    __syncthreads();

    // reduction + epilogue: thread t owns row=t>>4, cols (t&15)*4..+3
    {
        float* s_part = s_w;
        int row = t >> 4, tc = t & 15;
        float4 o = make_float4(0.f, 0.f, 0.f, 0.f);
#pragma unroll
        for (int q = 0; q < 8; q++) {
            float4 pv = *(const float4*)&s_part[q * 2048 + row * 64 + tc * 4];
            o.x += pv.x; o.y += pv.y; o.z += pv.z; o.w += pv.w;
        }
        int nn = s_nn[row];
        float inv = 1.0f / (float)(nn > 1 ? nn : 1);
        float vals[4] = {o.x, o.y, o.z, o.w};
#pragma unroll
        for (int j = 0; j < 4; j++) {
            int cc = tc * 4 + j;
            float v = vals[j] * inv + kb[cc];
            g_out2[(size_t)(p0 + row) * CMID + cc] = v;
            atomicAdd(&s_sum[cc], v);
            atomicAdd(&s_sq[cc], v * v);
        }
    }
    __syncthreads();
    if (t < 64) {
        atomicAdd(&g_sum2[t], (double)s_sum[t]);
        atomicAdd(&g_sq2[t], (double)s_sq[t]);
    }
}

// ---- GEMM2: y = leaky(GN2(out2)) @ W2(64x256) + b2 ; accumulate GN3 stats ----
#define SMEM_F_BYTES ((16384 + 64*68 + 256 + 256) * 4)

__global__ __launch_bounds__(256) void k_gemm2(const float* __restrict__ W2,
                                               const float* __restrict__ b2) {
    extern __shared__ float sh[];
    float* s_W   = sh;               // 16384 (full W2)
    float* s_At  = sh + 16384;       // [k][row] 64x68
    float* s_sum = s_At + 64 * 68;   // 256
    float* s_sq  = s_sum + 256;      // 256
    int t = threadIdx.x;
    int row0 = blockIdx.x * 64;

    for (int e = t; e < 64 * 256; e += 256) s_W[e] = W2[e];
    for (int e = t; e < 64 * 64; e += 256) {
        int r = e >> 6, c = e & 63;
        float v = g_out2[(size_t)(row0 + r) * CMID + c];
        v = g_a2[c] * v + g_b2v[c];
        v = v >= 0.f ? v : SLOPE * v;
        s_At[c * 68 + r] = v;
    }
    s_sum[t] = 0.f; s_sq[t] = 0.f;
    __syncthreads();

    int tr = t >> 5;   // rows tr*8..+7
    int tc = t & 31;   // cols tc*8..+7
    ull acc[8][4];
#pragma unroll
    for (int i = 0; i < 8; i++)
#pragma unroll
        for (int j = 0; j < 4; j++) acc[i][j] = 0ull;

#pragma unroll 4
    for (int k = 0; k < 64; k++) {
        float4 a0 = *(const float4*)&s_At[k * 68 + tr * 8];
        float4 a1 = *(const float4*)&s_At[k * 68 + tr * 8 + 4];
        ulonglong2 w0 = *(const ulonglong2*)&s_W[k * 256 + tc * 8];
        ulonglong2 w1 = *(const ulonglong2*)&s_W[k * 256 + tc * 8 + 4];
        ull d;
        d = dup2(a0.x); fma2(acc[0][0], d, w0.x); fma2(acc[0][1], d, w0.y); fma2(acc[0][2], d, w1.x); fma2(acc[0][3], d, w1.y);
        d = dup2(a0.y); fma2(acc[1][0], d, w0.x); fma2(acc[1][1], d, w0.y); fma2(acc[1][2], d, w1.x); fma2(acc[1][3], d, w1.y);
        d = dup2(a0.z); fma2(acc[2][0], d, w0.x); fma2(acc[2][1], d, w0.y); fma2(acc[2][2], d, w1.x); fma2(acc[2][3], d, w1.y);
        d = dup2(a0.w); fma2(acc[3][0], d, w0.x); fma2(acc[3][1], d, w0.y); fma2(acc[3][2], d, w1.x); fma2(acc[3][3], d, w1.y);
        d = dup2(a1.x); fma2(acc[4][0], d, w0.x); fma2(acc[4][1], d, w0.y); fma2(acc[4][2], d, w1.x); fma2(acc[4][3], d, w1.y);
        d = dup2(a1.y); fma2(acc[5][0], d, w0.x); fma2(acc[5][1], d, w0.y); fma2(acc[5][2], d, w1.x); fma2(acc[5][3], d, w1.y);
        d = dup2(a1.z); fma2(acc[6][0], d, w0.x); fma2(acc[6][1], d, w0.y); fma2(acc[6][2], d, w1.x); fma2(acc[6][3], d, w1.y);
        d = dup2(a1.w); fma2(acc[7][0], d, w0.x); fma2(acc[7][1], d, w0.y); fma2(acc[7][2], d, w1.x); fma2(acc[7][3], d, w1.y);
    }
    float cs[8] = {0}, cq[8] = {0};
#pragma unroll
    for (int i = 0; i < 8; i++) {
        int r = row0 + tr * 8 + i;
        float2 v0 = up2(acc[i][0]), v1 = up2(acc[i][1]);
        float2 v2 = up2(acc[i][2]), v3 = up2(acc[i][3]);
        float v[8] = {v0.x, v0.y, v1.x, v1.y, v2.x, v2.y, v3.x, v3.y};
#pragma unroll
        for (int j = 0; j < 8; j++) {
            int cc = tc * 8 + j;
            v[j] += b2[cc];
            cs[j] += v[j]; cq[j] += v[j] * v[j];
        }
        float4* dst = (float4*)&g_y[(size_t)r * COUT + tc * 8];
        dst[0] = make_float4(v[0], v[1], v[2], v[3]);
        dst[1] = make_float4(v[4], v[5], v[6], v[7]);
    }
#pragma unroll
    for (int j = 0; j < 8; j++) {
        atomicAdd(&s_sum[tc * 8 + j], cs[j]);
        atomicAdd(&s_sq[tc * 8 + j], cq[j]);
    }
    __syncthreads();
    atomicAdd(&g_sum3[t], (double)s_sum[t]);
    atomicAdd(&g_sq3[t], (double)s_sq[t]);
}

// ---- final: out = leaky(GN3(y) + s_feats) ----
__global__ __launch_bounds__(256) void k_final(const float* __restrict__ sf,
                                               float* __restrict__ out) {
    int i = blockIdx.x * 256 + threadIdx.x;
    float4 y = ((const float4*)g_y)[i];
    float4 s = ((const float4*)sf)[i];
    int c = (i & 63) * 4;
    float4 r;
    r.x = g_a3[c + 0] * y.x + g_b3v[c + 0] + s.x;
    r.y = g_a3[c + 1] * y.y + g_b3v[c + 1] + s.y;
    r.z = g_a3[c + 2] * y.z + g_b3v[c + 2] + s.z;
    r.w = g_a3[c + 3] * y.w + g_b3v[c + 3] + s.w;
    r.x = r.x >= 0.f ? r.x : SLOPE * r.x;
    r.y = r.y >= 0.f ? r.y : SLOPE * r.y;
    r.z = r.z >= 0.f ? r.z : SLOPE * r.z;
    r.w = r.w >= 0.f ? r.w : SLOPE * r.w;
    ((float4*)out)[i] = r;
}

extern "C" void kernel_launch(void* const* d_in, const int* in_sizes, int n_in,
                              void* d_out, int out_size) {
    const float* s_feats  = (const float*)d_in[0];
    const float* q_points = (const float*)d_in[1];
    const float* s_points = (const float*)d_in[2];
    const int*   nbr      = (const int*)d_in[3];
    const float* W1       = (const float*)d_in[4];
    const float* b1       = (const float*)d_in[5];
    const float* g1       = (const float*)d_in[6];
    const float* beta1    = (const float*)d_in[7];
    const float* kpw      = (const float*)d_in[8];
    const float* kpb      = (const float*)d_in[9];
    const float* kpts     = (const float*)d_in[10];
    const float* gg       = (const float*)d_in[11];
    const float* gb       = (const float*)d_in[12];
    const float* W2       = (const float*)d_in[13];
    const float* b2       = (const float*)d_in[14];
    const float* g2       = (const float*)d_in[15];
    const float* beta2    = (const float*)d_in[16];
    float* out = (float*)d_out;

    cudaFuncSetAttribute(k_kpconv, cudaFuncAttributeMaxDynamicSharedMemorySize, SMEM_D_BYTES);
    cudaFuncSetAttribute(k_gemm2,  cudaFuncAttributeMaxDynamicSharedMemorySize, SMEM_F_BYTES);

    k_zero<<<1, 256>>>();
    k_gemm1<<<NPTS / 128, 256>>>(s_feats, W1, b1);
    k_finalize<<<1, 256>>>(0, g1, beta1);
    k_apply1<<<NPTS * CMID / 4 / 256, 256>>>();
    k_kpconv<<<NPTS / 32, 512, SMEM_D_BYTES>>>(q_points, s_points, nbr, kpts, kpw, kpb);
    k_finalize<<<1, 256>>>(1, gg, gb);
    k_gemm2<<<NPTS / 64, 256, SMEM_F_BYTES>>>(W2, b2);
    k_finalize<<<1, 256>>>(2, g2, beta2);
    k_final<<<NPTS * COUT / 4 / 256, 256>>>(s_feats, out);
}

// round 4
// speedup vs baseline: 1.6447x; 1.1344x over previous
#include <cuda_runtime.h>
#include <cstdint>

#define NPTS 65536
#define HN 32
#define CIN 256
#define CMID 64
#define COUT 256
#define KP 15
#define SLOPE 0.1f
#define EPSV 1e-5f

using ull = unsigned long long;

// ---- packed f32x2 helpers (fma.rn.f32x2: 2x FFMA throughput) ----
__device__ __forceinline__ ull pk2(float lo, float hi) {
    ull r; asm("mov.b64 %0, {%1,%2};" : "=l"(r) : "f"(lo), "f"(hi)); return r;
}
__device__ __forceinline__ ull dup2(float v) { return pk2(v, v); }
__device__ __forceinline__ void fma2(ull& d, ull a, ull b) {
    asm("fma.rn.f32x2 %0, %1, %2, %3;" : "=l"(d) : "l"(a), "l"(b), "l"(d));
}
__device__ __forceinline__ float2 up2(ull v) {
    float lo, hi; asm("mov.b64 {%0,%1}, %2;" : "=f"(lo), "=f"(hi) : "l"(v));
    return make_float2(lo, hi);
}

// ---- scratch (device globals; no runtime allocation allowed) ----
__device__ float g_x1[NPTS * CMID];     // 16 MB
__device__ float g_out2[NPTS * CMID];   // 16 MB
__device__ float g_y[NPTS * COUT];      // 64 MB
__device__ double g_sum1[CMID], g_sq1[CMID];
__device__ double g_sum2[CMID], g_sq2[CMID];
__device__ double g_sum3[COUT], g_sq3[COUT];
__device__ float g_a1[CMID], g_b1v[CMID];
__device__ float g_a2[CMID], g_b2v[CMID];
__device__ float g_a3[COUT], g_b3v[COUT];

__global__ void k_zero() {
    int t = threadIdx.x;
    if (t < CMID) { g_sum1[t] = 0.0; g_sq1[t] = 0.0; g_sum2[t] = 0.0; g_sq2[t] = 0.0; }
    if (t < COUT) { g_sum3[t] = 0.0; g_sq3[t] = 0.0; }
}

// ---- GEMM1: x1 = s_feats(65536x256) @ W1(256x64) + b1 ; accumulate GN1 stats ----
__global__ __launch_bounds__(256) void k_gemm1(const float* __restrict__ A,
                                               const float* __restrict__ W,
                                               const float* __restrict__ bias) {
    __shared__ __align__(16) float As[32][132];   // [k][row], padded
    __shared__ __align__(16) float Bs[32][64];
    __shared__ float ssum[CMID], ssq[CMID];
    int t = threadIdx.x;
    int tr = t >> 4, tc = t & 15;        // 16x16: 8 rows x 4 cols per thread
    int row0 = blockIdx.x * 128;
    ull acc[8][2];
#pragma unroll
    for (int i = 0; i < 8; i++) { acc[i][0] = 0ull; acc[i][1] = 0ull; }
    if (t < CMID) { ssum[t] = 0.f; ssq[t] = 0.f; }

    for (int kk = 0; kk < CIN; kk += 32) {
        __syncthreads();
        for (int e = t; e < 128 * 32; e += 256) {
            int r = e >> 5, c = e & 31;
            As[c][r] = A[(size_t)(row0 + r) * CIN + kk + c];
        }
        for (int e = t; e < 32 * 64; e += 256) {
            int r = e >> 6, c = e & 63;
            Bs[r][c] = W[(kk + r) * CMID + c];
        }
        __syncthreads();
#pragma unroll
        for (int k = 0; k < 32; k++) {
            float4 a0 = *(const float4*)&As[k][tr * 8];
            float4 a1 = *(const float4*)&As[k][tr * 8 + 4];
            ulonglong2 bb = *(const ulonglong2*)&Bs[k][tc * 4];
            ull d;
            d = dup2(a0.x); fma2(acc[0][0], d, bb.x); fma2(acc[0][1], d, bb.y);
            d = dup2(a0.y); fma2(acc[1][0], d, bb.x); fma2(acc[1][1], d, bb.y);
            d = dup2(a0.z); fma2(acc[2][0], d, bb.x); fma2(acc[2][1], d, bb.y);
            d = dup2(a0.w); fma2(acc[3][0], d, bb.x); fma2(acc[3][1], d, bb.y);
            d = dup2(a1.x); fma2(acc[4][0], d, bb.x); fma2(acc[4][1], d, bb.y);
            d = dup2(a1.y); fma2(acc[5][0], d, bb.x); fma2(acc[5][1], d, bb.y);
            d = dup2(a1.z); fma2(acc[6][0], d, bb.x); fma2(acc[6][1], d, bb.y);
            d = dup2(a1.w); fma2(acc[7][0], d, bb.x); fma2(acc[7][1], d, bb.y);
        }
    }
    float cs[4] = {0, 0, 0, 0}, cq[4] = {0, 0, 0, 0};
#pragma unroll
    for (int i = 0; i < 8; i++) {
        int r = row0 + tr * 8 + i;
        float2 v01 = up2(acc[i][0]);
        float2 v23 = up2(acc[i][1]);
        float v[4] = {v01.x, v01.y, v23.x, v23.y};
#pragma unroll
        for (int j = 0; j < 4; j++) {
            int c = tc * 4 + j;
            float x = v[j] + bias[c];
            g_x1[(size_t)r * CMID + c] = x;
            cs[j] += x; cq[j] += x * x;
        }
    }
#pragma unroll
    for (int j = 0; j < 4; j++) {
        atomicAdd(&ssum[tc * 4 + j], cs[j]);
        atomicAdd(&ssq[tc * 4 + j], cq[j]);
    }
    __syncthreads();
    if (t < CMID) {
        atomicAdd(&g_sum1[t], (double)ssum[t]);
        atomicAdd(&g_sq1[t], (double)ssq[t]);
    }
}

// ---- finalize GN stats -> per-channel scale/shift ----
__global__ void k_finalize(int stage, const float* __restrict__ gamma,
                           const float* __restrict__ beta) {
    int c = threadIdx.x;
    if (stage < 2) {
        if (c >= CMID) return;
        const double* sum = (stage == 0) ? g_sum1 : g_sum2;
        const double* sq  = (stage == 0) ? g_sq1  : g_sq2;
        float* a = (stage == 0) ? g_a1 : g_a2;
        float* b = (stage == 0) ? g_b1v : g_b2v;
        int g = c >> 1;
        double s = sum[g * 2] + sum[g * 2 + 1];
        double q = sq[g * 2] + sq[g * 2 + 1];
        double cnt = 2.0 * (double)NPTS;
        double mean = s / cnt;
        double var = q / cnt - mean * mean;
        float inv = rsqrtf((float)var + EPSV);
        float av = gamma[c] * inv;
        a[c] = av;
        b[c] = beta[c] - (float)mean * av;
    } else {
        if (c >= COUT) return;
        int g = c >> 3;
        double s = 0.0, q = 0.0;
#pragma unroll
        for (int i = 0; i < 8; i++) { s += g_sum3[g * 8 + i]; q += g_sq3[g * 8 + i]; }
        double cnt = 8.0 * (double)NPTS;
        double mean = s / cnt;
        double var = q / cnt - mean * mean;
        float inv = rsqrtf((float)var + EPSV);
        float av = gamma[c] * inv;
        g_a3[c] = av;
        g_b3v[c] = beta[c] - (float)mean * av;
    }
}

// ---- apply GN1 + leaky in place on x1 ----
__global__ __launch_bounds__(256) void k_apply1() {
    int i = blockIdx.x * 256 + threadIdx.x;
    float4 v = ((const float4*)g_x1)[i];
    int c = (i & 15) * 4;
    float4 r;
    r.x = g_a1[c + 0] * v.x + g_b1v[c + 0];
    r.y = g_a1[c + 1] * v.y + g_b1v[c + 1];
    r.z = g_a1[c + 2] * v.z + g_b1v[c + 2];
    r.w = g_a1[c + 3] * v.w + g_b1v[c + 3];
    r.x = r.x >= 0.f ? r.x : SLOPE * r.x;
    r.y = r.y >= 0.f ? r.y : SLOPE * r.y;
    r.z = r.z >= 0.f ? r.z : SLOPE * r.z;
    r.w = r.w >= 0.f ? r.w : SLOPE * r.w;
    ((float4*)g_x1)[i] = r;
}

// ---- KPConv: 16 points/block, 256 threads, 2 CTAs/SM ----
// smem floats: kp 48 | w 8192 (16*32*16; reused as partials 4*1024) | A 16*968 | Wt 4096 | sum 64 | sq 64
// ints: nbr 512 | nn 16
#define PPB 16
#define A_STRIDE 968
#define SMEM_D_BYTES ((48 + 8192 + PPB*A_STRIDE + 4096 + 64 + 64) * 4 + (512 + 16) * 4)

__global__ __launch_bounds__(256, 2) void k_kpconv(
        const float* __restrict__ qp, const float* __restrict__ sp,
        const int* __restrict__ nbr, const float* __restrict__ kpts,
        const float* __restrict__ kw, const float* __restrict__ kb) {
    extern __shared__ float sh[];
    float* s_kp  = sh;                          // 48
    float* s_w   = sh + 48;                     // 8192 (w[p][h][16]); reused as partials
    float* s_A   = s_w + 8192;                  // 16*968
    float* s_Wt  = s_A + PPB * A_STRIDE;        // 4096
    float* s_sum = s_Wt + 4096;                 // 64
    float* s_sq  = s_sum + 64;                  // 64
    int* s_nbr   = (int*)(s_sq + 64);           // 512
    int* s_nn    = s_nbr + 512;                 // 16

    int t = threadIdx.x;
    int p0 = blockIdx.x * PPB;

    if (t < 45) s_kp[t] = kpts[t];
    if (t < 64) { s_sum[t] = 0.f; s_sq[t] = 0.f; }
    __syncthreads();

    // phase 1: influence weights w[p][h][k]; warp == one point per iter -> ballot for nnum
    for (int id = t; id < PPB * 32; id += 256) {
        int p = id >> 5, h = id & 31;
        int idx = nbr[(p0 + p) * HN + h];
        s_nbr[id] = idx;
        float dx, dy, dz;
        bool valid = (unsigned)idx < NPTS;
        if (valid) {
            dx = sp[idx * 3 + 0] - qp[(p0 + p) * 3 + 0];
            dy = sp[idx * 3 + 1] - qp[(p0 + p) * 3 + 1];
            dz = sp[idx * 3 + 2] - qp[(p0 + p) * 3 + 2];
        } else { dx = dy = dz = 1e10f; }
        unsigned m = __ballot_sync(0xffffffffu, valid);
        if ((t & 31) == 0) s_nn[p] = __popc(m);
#pragma unroll
        for (int k = 0; k < KP; k++) {
            float ex = dx - s_kp[k * 3 + 0];
            float ey = dy - s_kp[k * 3 + 1];
            float ez = dz - s_kp[k * 3 + 2];
            float dist = sqrtf(ex * ex + ey * ey + ez * ez);
            s_w[id * 16 + k] = fmaxf(1.0f - dist, 0.0f);
        }
        s_w[id * 16 + 15] = 0.f;
    }
    __syncthreads();

    // phase 2: A[p][k*64+c] = sum_h w[p][h][k] * x1[idx][c]   (thread = point p, 4 channels)
    {
        int c4 = (t & 15) * 4;
        int p = t >> 4;        // 0..15
        ull acc[8][4];
#pragma unroll
        for (int a = 0; a < 8; a++)
#pragma unroll
            for (int b = 0; b < 4; b++) acc[a][b] = 0ull;
#pragma unroll 4
        for (int h = 0; h < HN; h++) {
            int idx = s_nbr[p * 32 + h];
            float4 f;
            if ((unsigned)idx < NPTS) f = *(const float4*)&g_x1[(size_t)idx * CMID + c4];
            else f = make_float4(0.f, 0.f, 0.f, 0.f);
            ull fd0 = dup2(f.x), fd1 = dup2(f.y), fd2 = dup2(f.z), fd3 = dup2(f.w);
            const ull* w2 = (const ull*)&s_w[(p * 32 + h) * 16];
#pragma unroll
            for (int kp2 = 0; kp2 < 8; kp2++) {
                ull wv = w2[kp2];
                fma2(acc[kp2][0], wv, fd0);
                fma2(acc[kp2][1], wv, fd1);
                fma2(acc[kp2][2], wv, fd2);
                fma2(acc[kp2][3], wv, fd3);
            }
        }
#pragma unroll
        for (int kp2 = 0; kp2 < 8; kp2++) {
#pragma unroll
            for (int j = 0; j < 4; j++) {
                float2 v = up2(acc[kp2][j]);
                int k0 = kp2 * 2;
                s_A[p * A_STRIDE + k0 * 64 + c4 + j] = v.x;
                if (k0 + 1 < KP) s_A[p * A_STRIDE + (k0 + 1) * 64 + c4 + j] = v.y;
            }
        }
    }
    __syncthreads();

    // phase 3: out[16][64] = A[16][960] @ kw[960][64], 4-way K-split + kw tile reg-prefetch
    // thread = (kq 0..3, rg 0..3, cg 0..15): rows rg*4..+3, cols cg*4..+3
    {
        int kq = t >> 6;
        int rg = (t >> 4) & 3;
        int cg = t & 15;
        ull acc[4][2];
#pragma unroll
        for (int i = 0; i < 4; i++) { acc[i][0] = 0ull; acc[i][1] = 0ull; }

        const float4* kw4 = (const float4*)kw;
        float4 pf[4];
#pragma unroll
        for (int j = 0; j < 4; j++) pf[j] = kw4[t + j * 256];

        for (int it = 0; it < 15; it++) {
            __syncthreads();
#pragma unroll
            for (int j = 0; j < 4; j++) ((float4*)s_Wt)[t + j * 256] = pf[j];
            __syncthreads();
            if (it < 14) {
#pragma unroll
                for (int j = 0; j < 4; j++) pf[j] = kw4[(it + 1) * 1024 + t + j * 256];
            }
            int t0 = it * 64;
#pragma unroll
            for (int jj = 0; jj < 16; jj++) {
                int kc = kq * 16 + jj;
                ulonglong2 wv = *(const ulonglong2*)&s_Wt[kc * 64 + cg * 4];
                const float* arow = &s_A[rg * 4 * A_STRIDE + t0 + kc];
#pragma unroll
                for (int i = 0; i < 4; i++) {
                    ull ad = dup2(arow[i * A_STRIDE]);
                    fma2(acc[i][0], ad, wv.x);
                    fma2(acc[i][1], ad, wv.y);
                }
            }
        }

        // write partials into s_w region (dead after phase 2): [kq][row][col]
        float* s_part = s_w;
#pragma unroll
        for (int i = 0; i < 4; i++) {
            float2 v0 = up2(acc[i][0]);
            float2 v1 = up2(acc[i][1]);
            *(float4*)&s_part[kq * 1024 + (rg * 4 + i) * 64 + cg * 4] =
                make_float4(v0.x, v0.y, v1.x, v1.y);
        }
    }
    __syncthreads();

    // reduction + epilogue: thread t owns row=t>>4 (0..15), cols (t&15)*4..+3
    {
        float* s_part = s_w;
        int row = t >> 4, tc = t & 15;
        float4 o = make_float4(0.f, 0.f, 0.f, 0.f);
#pragma unroll
        for (int q = 0; q < 4; q++) {
            float4 pv = *(const float4*)&s_part[q * 1024 + row * 64 + tc * 4];
            o.x += pv.x; o.y += pv.y; o.z += pv.z; o.w += pv.w;
        }
        int nn = s_nn[row];
        float inv = 1.0f / (float)(nn > 1 ? nn : 1);
        float vals[4] = {o.x, o.y, o.z, o.w};
#pragma unroll
        for (int j = 0; j < 4; j++) {
            int cc = tc * 4 + j;
            float v = vals[j] * inv + kb[cc];
            g_out2[(size_t)(p0 + row) * CMID + cc] = v;
            atomicAdd(&s_sum[cc], v);
            atomicAdd(&s_sq[cc], v * v);
        }
    }
    __syncthreads();
    if (t < 64) {
        atomicAdd(&g_sum2[t], (double)s_sum[t]);
        atomicAdd(&g_sq2[t], (double)s_sq[t]);
    }
}

// ---- GEMM2: y = leaky(GN2(out2)) @ W2(64x256) + b2 ; accumulate GN3 stats ----
#define SMEM_F_BYTES ((16384 + 64*68 + 256 + 256) * 4)

__global__ __launch_bounds__(256) void k_gemm2(const float* __restrict__ W2,
                                               const float* __restrict__ b2) {
    extern __shared__ float sh[];
    float* s_W   = sh;               // 16384 (full W2)
    float* s_At  = sh + 16384;       // [k][row] 64x68
    float* s_sum = s_At + 64 * 68;   // 256
    float* s_sq  = s_sum + 256;      // 256
    int t = threadIdx.x;
    int row0 = blockIdx.x * 64;

    for (int e = t; e < 64 * 256; e += 256) s_W[e] = W2[e];
    for (int e = t; e < 64 * 64; e += 256) {
        int r = e >> 6, c = e & 63;
        float v = g_out2[(size_t)(row0 + r) * CMID + c];
        v = g_a2[c] * v + g_b2v[c];
        v = v >= 0.f ? v : SLOPE * v;
        s_At[c * 68 + r] = v;
    }
    s_sum[t] = 0.f; s_sq[t] = 0.f;
    __syncthreads();

    int tr = t >> 5;   // rows tr*8..+7
    int tc = t & 31;   // cols tc*8..+7
    ull acc[8][4];
#pragma unroll
    for (int i = 0; i < 8; i++)
#pragma unroll
        for (int j = 0; j < 4; j++) acc[i][j] = 0ull;

#pragma unroll 4
    for (int k = 0; k < 64; k++) {
        float4 a0 = *(const float4*)&s_At[k * 68 + tr * 8];
        float4 a1 = *(const float4*)&s_At[k * 68 + tr * 8 + 4];
        ulonglong2 w0 = *(const ulonglong2*)&s_W[k * 256 + tc * 8];
        ulonglong2 w1 = *(const ulonglong2*)&s_W[k * 256 + tc * 8 + 4];
        ull d;
        d = dup2(a0.x); fma2(acc[0][0], d, w0.x); fma2(acc[0][1], d, w0.y); fma2(acc[0][2], d, w1.x); fma2(acc[0][3], d, w1.y);
        d = dup2(a0.y); fma2(acc[1][0], d, w0.x); fma2(acc[1][1], d, w0.y); fma2(acc[1][2], d, w1.x); fma2(acc[1][3], d, w1.y);
        d = dup2(a0.z); fma2(acc[2][0], d, w0.x); fma2(acc[2][1], d, w0.y); fma2(acc[2][2], d, w1.x); fma2(acc[2][3], d, w1.y);
        d = dup2(a0.w); fma2(acc[3][0], d, w0.x); fma2(acc[3][1], d, w0.y); fma2(acc[3][2], d, w1.x); fma2(acc[3][3], d, w1.y);
        d = dup2(a1.x); fma2(acc[4][0], d, w0.x); fma2(acc[4][1], d, w0.y); fma2(acc[4][2], d, w1.x); fma2(acc[4][3], d, w1.y);
        d = dup2(a1.y); fma2(acc[5][0], d, w0.x); fma2(acc[5][1], d, w0.y); fma2(acc[5][2], d, w1.x); fma2(acc[5][3], d, w1.y);
        d = dup2(a1.z); fma2(acc[6][0], d, w0.x); fma2(acc[6][1], d, w0.y); fma2(acc[6][2], d, w1.x); fma2(acc[6][3], d, w1.y);
        d = dup2(a1.w); fma2(acc[7][0], d, w0.x); fma2(acc[7][1], d, w0.y); fma2(acc[7][2], d, w1.x); fma2(acc[7][3], d, w1.y);
    }
    float cs[8] = {0}, cq[8] = {0};
#pragma unroll
    for (int i = 0; i < 8; i++) {
        int r = row0 + tr * 8 + i;
        float2 v0 = up2(acc[i][0]), v1 = up2(acc[i][1]);
        float2 v2 = up2(acc[i][2]), v3 = up2(acc[i][3]);
        float v[8] = {v0.x, v0.y, v1.x, v1.y, v2.x, v2.y, v3.x, v3.y};
#pragma unroll
        for (int j = 0; j < 8; j++) {
            int cc = tc * 8 + j;
            v[j] += b2[cc];
            cs[j] += v[j]; cq[j] += v[j] * v[j];
        }
        float4* dst = (float4*)&g_y[(size_t)r * COUT + tc * 8];
        dst[0] = make_float4(v[0], v[1], v[2], v[3]);
        dst[1] = make_float4(v[4], v[5], v[6], v[7]);
    }
#pragma unroll
    for (int j = 0; j < 8; j++) {
        atomicAdd(&s_sum[tc * 8 + j], cs[j]);
        atomicAdd(&s_sq[tc * 8 + j], cq[j]);
    }
    __syncthreads();
    atomicAdd(&g_sum3[t], (double)s_sum[t]);
    atomicAdd(&g_sq3[t], (double)s_sq[t]);
}

// ---- final: out = leaky(GN3(y) + s_feats) ----
__global__ __launch_bounds__(256) void k_final(const float* __restrict__ sf,
                                               float* __restrict__ out) {
    int i = blockIdx.x * 256 + threadIdx.x;
    float4 y = ((const float4*)g_y)[i];
    float4 s = ((const float4*)sf)[i];
    int c = (i & 63) * 4;
    float4 r;
    r.x = g_a3[c + 0] * y.x + g_b3v[c + 0] + s.x;
    r.y = g_a3[c + 1] * y.y + g_b3v[c + 1] + s.y;
    r.z = g_a3[c + 2] * y.z + g_b3v[c + 2] + s.z;
    r.w = g_a3[c + 3] * y.w + g_b3v[c + 3] + s.w;
    r.x = r.x >= 0.f ? r.x : SLOPE * r.x;
    r.y = r.y >= 0.f ? r.y : SLOPE * r.y;
    r.z = r.z >= 0.f ? r.z : SLOPE * r.z;
    r.w = r.w >= 0.f ? r.w : SLOPE * r.w;
    ((float4*)out)[i] = r;
}

extern "C" void kernel_launch(void* const* d_in, const int* in_sizes, int n_in,
                              void* d_out, int out_size) {
    const float* s_feats  = (const float*)d_in[0];
    const float* q_points = (const float*)d_in[1];
    const float* s_points = (const float*)d_in[2];
    const int*   nbr      = (const int*)d_in[3];
    const float* W1       = (const float*)d_in[4];
    const float* b1       = (const float*)d_in[5];
    const float* g1       = (const float*)d_in[6];
    const float* beta1    = (const float*)d_in[7];
    const float* kpw      = (const float*)d_in[8];
    const float* kpb      = (const float*)d_in[9];
    const float* kpts     = (const float*)d_in[10];
    const float* gg       = (const float*)d_in[11];
    const float* gb       = (const float*)d_in[12];
    const float* W2       = (const float*)d_in[13];
    const float* b2       = (const float*)d_in[14];
    const float* g2       = (const float*)d_in[15];
    const float* beta2    = (const float*)d_in[16];
    float* out = (float*)d_out;

    cudaFuncSetAttribute(k_kpconv, cudaFuncAttributeMaxDynamicSharedMemorySize, SMEM_D_BYTES);
    cudaFuncSetAttribute(k_gemm2,  cudaFuncAttributeMaxDynamicSharedMemorySize, SMEM_F_BYTES);

    k_zero<<<1, 256>>>();
    k_gemm1<<<NPTS / 128, 256>>>(s_feats, W1, b1);
    k_finalize<<<1, 256>>>(0, g1, beta1);
    k_apply1<<<NPTS * CMID / 4 / 256, 256>>>();
    k_kpconv<<<NPTS / PPB, 256, SMEM_D_BYTES>>>(q_points, s_points, nbr, kpts, kpw, kpb);
    k_finalize<<<1, 256>>>(1, gg, gb);
    k_gemm2<<<NPTS / 64, 256, SMEM_F_BYTES>>>(W2, b2);
    k_finalize<<<1, 256>>>(2, g2, beta2);
    k_final<<<NPTS * COUT / 4 / 256, 256>>>(s_feats, out);
}

// round 8
// speedup vs baseline: 2.0065x; 1.2200x over previous
#include <cuda_runtime.h>
#include <cuda_bf16.h>
#include <mma.h>
#include <cstdint>

#define NPTS 65536
#define HN 32
#define CIN 256
#define CMID 64
#define COUT 256
#define KP 15
#define SLOPE 0.1f
#define EPSV 1e-5f

using ull = unsigned long long;
using namespace nvcuda;

// ---- packed f32x2 helpers ----
__device__ __forceinline__ ull pk2(float lo, float hi) {
    ull r; asm("mov.b64 %0, {%1,%2};" : "=l"(r) : "f"(lo), "f"(hi)); return r;
}
__device__ __forceinline__ ull dup2(float v) { return pk2(v, v); }
__device__ __forceinline__ void fma2(ull& d, ull a, ull b) {
    asm("fma.rn.f32x2 %0, %1, %2, %3;" : "=l"(d) : "l"(a), "l"(b), "l"(d));
}
__device__ __forceinline__ float2 up2(ull v) {
    float lo, hi; asm("mov.b64 {%0,%1}, %2;" : "=f"(lo), "=f"(hi) : "l"(v));
    return make_float2(lo, hi);
}

// ---- scratch (device globals; aligned for vector-cast access) ----
__device__ __align__(256) float g_x1[NPTS * CMID];            // 16 MB
__device__ __align__(256) float g_out2[NPTS * CMID];          // 16 MB
__device__ __align__(256) float g_y[NPTS * COUT];             // 64 MB
__device__ __align__(256) __nv_bfloat16 g_Ahi[NPTS * 960];    // 126 MB
__device__ __align__(256) __nv_bfloat16 g_Alo[NPTS * 960];    // 126 MB
__device__ __align__(256) __nv_bfloat16 g_BhiT[64 * 960];
__device__ __align__(256) __nv_bfloat16 g_BloT[64 * 960];
__device__ float g_nnr[NPTS];
__device__ double g_sum1[CMID], g_sq1[CMID];
__device__ double g_sum2[CMID], g_sq2[CMID];
__device__ double g_sum3[COUT], g_sq3[COUT];
__device__ float g_a1[CMID], g_b1v[CMID];
__device__ float g_a2[CMID], g_b2v[CMID];
__device__ float g_a3[COUT], g_b3v[COUT];

__global__ void k_zero() {
    int t = threadIdx.x;
    if (t < CMID) { g_sum1[t] = 0.0; g_sq1[t] = 0.0; g_sum2[t] = 0.0; g_sq2[t] = 0.0; }
    if (t < COUT) { g_sum3[t] = 0.0; g_sq3[t] = 0.0; }
}

// ---- GEMM1: x1 = s_feats @ W1 + b1 ; accumulate GN1 stats ----
__global__ __launch_bounds__(256) void k_gemm1(const float* __restrict__ A,
                                               const float* __restrict__ W,
                                               const float* __restrict__ bias) {
    __shared__ __align__(16) float As[32][132];
    __shared__ __align__(16) float Bs[32][64];
    __shared__ float ssum[CMID], ssq[CMID];
    int t = threadIdx.x;
    int tr = t >> 4, tc = t & 15;
    int row0 = blockIdx.x * 128;
    ull acc[8][2];
#pragma unroll
    for (int i = 0; i < 8; i++) { acc[i][0] = 0ull; acc[i][1] = 0ull; }
    if (t < CMID) { ssum[t] = 0.f; ssq[t] = 0.f; }

    for (int kk = 0; kk < CIN; kk += 32) {
        __syncthreads();
        for (int e = t; e < 128 * 32; e += 256) {
            int r = e >> 5, c = e & 31;
            As[c][r] = A[(size_t)(row0 + r) * CIN + kk + c];
        }
        for (int e = t; e < 32 * 64; e += 256) {
            int r = e >> 6, c = e & 63;
            Bs[r][c] = W[(kk + r) * CMID + c];
        }
        __syncthreads();
#pragma unroll
        for (int k = 0; k < 32; k++) {
            float4 a0 = *(const float4*)&As[k][tr * 8];
            float4 a1 = *(const float4*)&As[k][tr * 8 + 4];
            ulonglong2 bb = *(const ulonglong2*)&Bs[k][tc * 4];
            ull d;
            d = dup2(a0.x); fma2(acc[0][0], d, bb.x); fma2(acc[0][1], d, bb.y);
            d = dup2(a0.y); fma2(acc[1][0], d, bb.x); fma2(acc[1][1], d, bb.y);
            d = dup2(a0.z); fma2(acc[2][0], d, bb.x); fma2(acc[2][1], d, bb.y);
            d = dup2(a0.w); fma2(acc[3][0], d, bb.x); fma2(acc[3][1], d, bb.y);
            d = dup2(a1.x); fma2(acc[4][0], d, bb.x); fma2(acc[4][1], d, bb.y);
            d = dup2(a1.y); fma2(acc[5][0], d, bb.x); fma2(acc[5][1], d, bb.y);
            d = dup2(a1.z); fma2(acc[6][0], d, bb.x); fma2(acc[6][1], d, bb.y);
            d = dup2(a1.w); fma2(acc[7][0], d, bb.x); fma2(acc[7][1], d, bb.y);
        }
    }
    float cs[4] = {0, 0, 0, 0}, cq[4] = {0, 0, 0, 0};
#pragma unroll
    for (int i = 0; i < 8; i++) {
        int r = row0 + tr * 8 + i;
        float2 v01 = up2(acc[i][0]);
        float2 v23 = up2(acc[i][1]);
        float v[4] = {v01.x, v01.y, v23.x, v23.y};
#pragma unroll
        for (int j = 0; j < 4; j++) {
            int c = tc * 4 + j;
            float x = v[j] + bias[c];
            g_x1[(size_t)r * CMID + c] = x;
            cs[j] += x; cq[j] += x * x;
        }
    }
#pragma unroll
    for (int j = 0; j < 4; j++) {
        atomicAdd(&ssum[tc * 4 + j], cs[j]);
        atomicAdd(&ssq[tc * 4 + j], cq[j]);
    }
    __syncthreads();
    if (t < CMID) {
        atomicAdd(&g_sum1[t], (double)ssum[t]);
        atomicAdd(&g_sq1[t], (double)ssq[t]);
    }
}

// ---- finalize GN stats ----
__global__ void k_finalize(int stage, const float* __restrict__ gamma,
                           const float* __restrict__ beta) {
    int c = threadIdx.x;
    if (stage < 2) {
        if (c >= CMID) return;
        const double* sum = (stage == 0) ? g_sum1 : g_sum2;
        const double* sq  = (stage == 0) ? g_sq1  : g_sq2;
        float* a = (stage == 0) ? g_a1 : g_a2;
        float* b = (stage == 0) ? g_b1v : g_b2v;
        int g = c >> 1;
        double s = sum[g * 2] + sum[g * 2 + 1];
        double q = sq[g * 2] + sq[g * 2 + 1];
        double cnt = 2.0 * (double)NPTS;
        double mean = s / cnt;
        double var = q / cnt - mean * mean;
        float inv = rsqrtf((float)var + EPSV);
        float av = gamma[c] * inv;
        a[c] = av;
        b[c] = beta[c] - (float)mean * av;
    } else {
        if (c >= COUT) return;
        int g = c >> 3;
        double s = 0.0, q = 0.0;
#pragma unroll
        for (int i = 0; i < 8; i++) { s += g_sum3[g * 8 + i]; q += g_sq3[g * 8 + i]; }
        double cnt = 8.0 * (double)NPTS;
        double mean = s / cnt;
        double var = q / cnt - mean * mean;
        float inv = rsqrtf((float)var + EPSV);
        float av = gamma[c] * inv;
        g_a3[c] = av;
        g_b3v[c] = beta[c] - (float)mean * av;
    }
}

// ---- apply GN1 + leaky in place ----
__global__ __launch_bounds__(256) void k_apply1() {
    int i = blockIdx.x * 256 + threadIdx.x;
    float4 v = ((const float4*)g_x1)[i];
    int c = (i & 15) * 4;
    float4 r;
    r.x = g_a1[c + 0] * v.x + g_b1v[c + 0];
    r.y = g_a1[c + 1] * v.y + g_b1v[c + 1];
    r.z = g_a1[c + 2] * v.z + g_b1v[c + 2];
    r.w = g_a1[c + 3] * v.w + g_b1v[c + 3];
    r.x = r.x >= 0.f ? r.x : SLOPE * r.x;
    r.y = r.y >= 0.f ? r.y : SLOPE * r.y;
    r.z = r.z >= 0.f ? r.z : SLOPE * r.z;
    r.w = r.w >= 0.f ? r.w : SLOPE * r.w;
    ((float4*)g_x1)[i] = r;
}

// ---- kw transpose+split prep: B^T[d][k*64+c] as bf16 hi/lo ----
__global__ __launch_bounds__(256) void k_prepB(const float* __restrict__ kw) {
    int idx = blockIdx.x * 256 + threadIdx.x;
    if (idx >= 64 * 960) return;
    int d = idx / 960;
    int r = idx % 960;      // k*64+c
    float v = kw[r * 64 + d];
    __nv_bfloat16 h = __float2bfloat16(v);
    float hf = __bfloat162float(h);
    g_BhiT[d * 960 + r] = h;
    g_BloT[d * 960 + r] = __float2bfloat16(v - hf);
}

// ---- k_gather: KPConv phases 1+2; writes weighted A as bf16 hi/lo ----
__global__ __launch_bounds__(256, 3) void k_gather(
        const float* __restrict__ qp, const float* __restrict__ sp,
        const int* __restrict__ nbr, const float* __restrict__ kpts) {
    __shared__ float s_kp[48];
    __shared__ float s_w[8 * 32 * 16];     // w[p][h][16]
    __shared__ int s_nbr[256];

    int t = threadIdx.x;
    int p0 = blockIdx.x * 8;

    if (t < 45) s_kp[t] = kpts[t];
    __syncthreads();

    // phase 1: warp == point
    {
        int p = t >> 5, h = t & 31;
        int idx = nbr[(p0 + p) * HN + h];
        s_nbr[t] = idx;
        float dx, dy, dz;
        bool valid = (unsigned)idx < NPTS;
        if (valid) {
            dx = sp[idx * 3 + 0] - qp[(p0 + p) * 3 + 0];
            dy = sp[idx * 3 + 1] - qp[(p0 + p) * 3 + 1];
            dz = sp[idx * 3 + 2] - qp[(p0 + p) * 3 + 2];
        } else { dx = dy = dz = 1e10f; }
        unsigned m = __ballot_sync(0xffffffffu, valid);
        if ((t & 31) == 0) {
            int nn = __popc(m);
            g_nnr[p0 + p] = 1.0f / (float)(nn > 1 ? nn : 1);
        }
#pragma unroll
        for (int k = 0; k < KP; k++) {
            float ex = dx - s_kp[k * 3 + 0];
            float ey = dy - s_kp[k * 3 + 1];
            float ez = dz - s_kp[k * 3 + 2];
            float dist = sqrtf(ex * ex + ey * ey + ez * ez);
            s_w[t * 16 + k] = fmaxf(1.0f - dist, 0.0f);
        }
        s_w[t * 16 + 15] = 0.f;
    }
    __syncthreads();

    // phase 2: thread = (p, 2 channels)
    {
        int p = t >> 5;
        int c2 = (t & 31) * 2;
        ull acc[8][2];
#pragma unroll
        for (int a = 0; a < 8; a++) { acc[a][0] = 0ull; acc[a][1] = 0ull; }
#pragma unroll 4
        for (int h = 0; h < HN; h++) {
            int idx = s_nbr[p * 32 + h];
            float2 f;
            if ((unsigned)idx < NPTS) f = *(const float2*)&g_x1[(size_t)idx * CMID + c2];
            else f = make_float2(0.f, 0.f);
            ull fd0 = dup2(f.x), fd1 = dup2(f.y);
            const ull* w2 = (const ull*)&s_w[(p * 32 + h) * 16];
#pragma unroll
            for (int kp2 = 0; kp2 < 8; kp2++) {
                ull wv = w2[kp2];
                fma2(acc[kp2][0], wv, fd0);
                fma2(acc[kp2][1], wv, fd1);
            }
        }
        int n = p0 + p;
        uint32_t* hiw = (uint32_t*)g_Ahi;
        uint32_t* low = (uint32_t*)g_Alo;
        int base = n * 480 + (c2 >> 1);     // bf162 index: n*480 + k*32 + c/2
#pragma unroll
        for (int kp2 = 0; kp2 < 8; kp2++) {
            float2 a0 = up2(acc[kp2][0]);   // channel c2:   k0, k0+1
            float2 a1 = up2(acc[kp2][1]);   // channel c2+1: k0, k0+1
            int k0 = kp2 * 2;
            {
                __nv_bfloat162 h = __floats2bfloat162_rn(a0.x, a1.x);
                float hx = __bfloat162float(h.x), hy = __bfloat162float(h.y);
                __nv_bfloat162 l = __floats2bfloat162_rn(a0.x - hx, a1.x - hy);
                hiw[base + k0 * 32] = *(uint32_t*)&h;
                low[base + k0 * 32] = *(uint32_t*)&l;
            }
            if (k0 + 1 < KP) {
                __nv_bfloat162 h = __floats2bfloat162_rn(a0.y, a1.y);
                float hx = __bfloat162float(h.x), hy = __bfloat162float(h.y);
                __nv_bfloat162 l = __floats2bfloat162_rn(a0.y - hx, a1.y - hy);
                hiw[base + (k0 + 1) * 32] = *(uint32_t*)&h;
                low[base + (k0 + 1) * 32] = *(uint32_t*)&l;
            }
        }
    }
}

// ---- k_pgemm: out2[128x64 tile] = A(bf16 hi/lo)[128x960] @ B^T via WMMA ----
// dynamic smem (bf16 elts, stride 80): Ahi[128*80]@0 | Alo@10240 | Bhi[64*80]@20480 | Blo@25600
// epilogue reuses region as float[128*80]
#define PGS 80
#define PG_SMEM (30720 * 2)

__global__ __launch_bounds__(256, 2) void k_pgemm(const float* __restrict__ kb) {
    extern __shared__ __nv_bfloat16 sb[];
    __nv_bfloat16* sAhi = sb;
    __nv_bfloat16* sAlo = sb + 10240;
    __nv_bfloat16* sBhi = sb + 20480;
    __nv_bfloat16* sBlo = sb + 25600;
    float* sOut = (float*)sb;

    int t = threadIdx.x;
    int warp = t >> 5;
    int wr = warp >> 1;      // 0..3: rows wr*32..+31
    int wc = warp & 1;       // 0..1: cols wc*32..+31
    int row0 = blockIdx.x * 128;

    wmma::fragment<wmma::accumulator, 16, 16, 16, float> acc[2][2];
#pragma unroll
    for (int i = 0; i < 2; i++)
#pragma unroll
        for (int j = 0; j < 2; j++) wmma::fill_fragment(acc[i][j], 0.0f);

    const __nv_bfloat16* Ahi = g_Ahi + (size_t)row0 * 960;
    const __nv_bfloat16* Alo = g_Alo + (size_t)row0 * 960;

    for (int ch = 0; ch < 15; ch++) {
        __syncthreads();
        // A chunk: 128 rows x 64 cols (hi + lo); 1024 uint4 each
#pragma unroll
        for (int i = 0; i < 4; i++) {
            int e = t + i * 256;
            int r = e >> 3, j = e & 7;
            *(uint4*)&sAhi[r * PGS + j * 8] = *(const uint4*)(Ahi + (size_t)r * 960 + ch * 64 + j * 8);
            *(uint4*)&sAlo[r * PGS + j * 8] = *(const uint4*)(Alo + (size_t)r * 960 + ch * 64 + j * 8);
        }
        // B chunk: 64 rows x 64 cols; 512 uint4 each
#pragma unroll
        for (int i = 0; i < 2; i++) {
            int e = t + i * 256;
            int r = e >> 3, j = e & 7;
            *(uint4*)&sBhi[r * PGS + j * 8] = *(const uint4*)(g_BhiT + (size_t)r * 960 + ch * 64 + j * 8);
            *(uint4*)&sBlo[r * PGS + j * 8] = *(const uint4*)(g_BloT + (size_t)r * 960 + ch * 64 + j * 8);
        }
        __syncthreads();

#pragma unroll
        for (int kk = 0; kk < 4; kk++) {
            wmma::fragment<wmma::matrix_a, 16, 16, 16, __nv_bfloat16, wmma::row_major> a_hi[2], a_lo[2];
            wmma::fragment<wmma::matrix_b, 16, 16, 16, __nv_bfloat16, wmma::col_major> b_hi[2], b_lo[2];
#pragma unroll
            for (int i = 0; i < 2; i++) {
                wmma::load_matrix_sync(a_hi[i], &sAhi[(wr * 32 + i * 16) * PGS + kk * 16], PGS);
                wmma::load_matrix_sync(a_lo[i], &sAlo[(wr * 32 + i * 16) * PGS + kk * 16], PGS);
            }
#pragma unroll
            for (int j = 0; j < 2; j++) {
                wmma::load_matrix_sync(b_hi[j], &sBhi[(wc * 32 + j * 16) * PGS + kk * 16], PGS);
                wmma::load_matrix_sync(b_lo[j], &sBlo[(wc * 32 + j * 16) * PGS + kk * 16], PGS);
            }
#pragma unroll
            for (int i = 0; i < 2; i++)
#pragma unroll
                for (int j = 0; j < 2; j++) {
                    wmma::mma_sync(acc[i][j], a_hi[i], b_hi[j], acc[i][j]);
                    wmma::mma_sync(acc[i][j], a_lo[i], b_hi[j], acc[i][j]);
                    wmma::mma_sync(acc[i][j], a_hi[i], b_lo[j], acc[i][j]);
                }
        }
    }

    // epilogue: stage through smem (reuse bf16 region as float tile)
    __syncthreads();
#pragma unroll
    for (int i = 0; i < 2; i++)
#pragma unroll
        for (int j = 0; j < 2; j++)
            wmma::store_matrix_sync(&sOut[(wr * 32 + i * 16) * PGS + wc * 32 + j * 16],
                                    acc[i][j], PGS, wmma::mem_row_major);
    __syncthreads();

    for (int e = t; e < 128 * 16; e += 256) {
        int r = e >> 4, c4 = e & 15;
        float nnr = g_nnr[row0 + r];
        float4 v = *(const float4*)&sOut[r * PGS + c4 * 4];
        float4 o;
        o.x = v.x * nnr + kb[c4 * 4 + 0];
        o.y = v.y * nnr + kb[c4 * 4 + 1];
        o.z = v.z * nnr + kb[c4 * 4 + 2];
        o.w = v.w * nnr + kb[c4 * 4 + 3];
        *(float4*)&g_out2[(size_t)(row0 + r) * CMID + c4 * 4] = o;
    }
}

// ---- GN2 stats over g_out2 ----
__global__ __launch_bounds__(256) void k_stats64() {
    __shared__ float s_s[64], s_q[64];
    int t = threadIdx.x;
    if (t < 64) { s_s[t] = 0.f; s_q[t] = 0.f; }
    __syncthreads();
    int tid = blockIdx.x * 256 + t;
    float cs[4] = {0, 0, 0, 0}, cq[4] = {0, 0, 0, 0};
#pragma unroll 4
    for (int j = 0; j < 16; j++) {
        float4 v = ((const float4*)g_out2)[tid + j * 65536];
        cs[0] += v.x; cq[0] += v.x * v.x;
        cs[1] += v.y; cq[1] += v.y * v.y;
        cs[2] += v.z; cq[2] += v.z * v.z;
        cs[3] += v.w; cq[3] += v.w * v.w;
    }
    int c = (tid & 15) * 4;
#pragma unroll
    for (int j = 0; j < 4; j++) {
        atomicAdd(&s_s[c + j], cs[j]);
        atomicAdd(&s_q[c + j], cq[j]);
    }
    __syncthreads();
    if (t < 64) {
        atomicAdd(&g_sum2[t], (double)s_s[t]);
        atomicAdd(&g_sq2[t], (double)s_q[t]);
    }
}

// ---- GEMM2 ----
#define SMEM_F_BYTES ((16384 + 64*68 + 256 + 256) * 4)

__global__ __launch_bounds__(256) void k_gemm2(const float* __restrict__ W2,
                                               const float* __restrict__ b2) {
    extern __shared__ float sh[];
    float* s_W   = sh;
    float* s_At  = sh + 16384;
    float* s_sum = s_At + 64 * 68;
    float* s_sq  = s_sum + 256;
    int t = threadIdx.x;
    int row0 = blockIdx.x * 64;

    for (int e = t; e < 64 * 256; e += 256) s_W[e] = W2[e];
    for (int e = t; e < 64 * 64; e += 256) {
        int r = e >> 6, c = e & 63;
        float v = g_out2[(size_t)(row0 + r) * CMID + c];
        v = g_a2[c] * v + g_b2v[c];
        v = v >= 0.f ? v : SLOPE * v;
        s_At[c * 68 + r] = v;
    }
    s_sum[t] = 0.f; s_sq[t] = 0.f;
    __syncthreads();

    int tr = t >> 5;
    int tc = t & 31;
    ull acc[8][4];
#pragma unroll
    for (int i = 0; i < 8; i++)
#pragma unroll
        for (int j = 0; j < 4; j++) acc[i][j] = 0ull;

#pragma unroll 4
    for (int k = 0; k < 64; k++) {
        float4 a0 = *(const float4*)&s_At[k * 68 + tr * 8];
        float4 a1 = *(const float4*)&s_At[k * 68 + tr * 8 + 4];
        ulonglong2 w0 = *(const ulonglong2*)&s_W[k * 256 + tc * 8];
        ulonglong2 w1 = *(const ulonglong2*)&s_W[k * 256 + tc * 8 + 4];
        ull d;
        d = dup2(a0.x); fma2(acc[0][0], d, w0.x); fma2(acc[0][1], d, w0.y); fma2(acc[0][2], d, w1.x); fma2(acc[0][3], d, w1.y);
        d = dup2(a0.y); fma2(acc[1][0], d, w0.x); fma2(acc[1][1], d, w0.y); fma2(acc[1][2], d, w1.x); fma2(acc[1][3], d, w1.y);
        d = dup2(a0.z); fma2(acc[2][0], d, w0.x); fma2(acc[2][1], d, w0.y); fma2(acc[2][2], d, w1.x); fma2(acc[2][3], d, w1.y);
        d = dup2(a0.w); fma2(acc[3][0], d, w0.x); fma2(acc[3][1], d, w0.y); fma2(acc[3][2], d, w1.x); fma2(acc[3][3], d, w1.y);
        d = dup2(a1.x); fma2(acc[4][0], d, w0.x); fma2(acc[4][1], d, w0.y); fma2(acc[4][2], d, w1.x); fma2(acc[4][3], d, w1.y);
        d = dup2(a1.y); fma2(acc[5][0], d, w0.x); fma2(acc[5][1], d, w0.y); fma2(acc[5][2], d, w1.x); fma2(acc[5][3], d, w1.y);
        d = dup2(a1.z); fma2(acc[6][0], d, w0.x); fma2(acc[6][1], d, w0.y); fma2(acc[6][2], d, w1.x); fma2(acc[6][3], d, w1.y);
        d = dup2(a1.w); fma2(acc[7][0], d, w0.x); fma2(acc[7][1], d, w0.y); fma2(acc[7][2], d, w1.x); fma2(acc[7][3], d, w1.y);
    }
    float cs[8] = {0}, cq[8] = {0};
#pragma unroll
    for (int i = 0; i < 8; i++) {
        int r = row0 + tr * 8 + i;
        float2 v0 = up2(acc[i][0]), v1 = up2(acc[i][1]);
        float2 v2 = up2(acc[i][2]), v3 = up2(acc[i][3]);
        float v[8] = {v0.x, v0.y, v1.x, v1.y, v2.x, v2.y, v3.x, v3.y};
#pragma unroll
        for (int j = 0; j < 8; j++) {
            int cc = tc * 8 + j;
            v[j] += b2[cc];
            cs[j] += v[j]; cq[j] += v[j] * v[j];
        }
        float4* dst = (float4*)&g_y[(size_t)r * COUT + tc * 8];
        dst[0] = make_float4(v[0], v[1], v[2], v[3]);
        dst[1] = make_float4(v[4], v[5], v[6], v[7]);
    }
#pragma unroll
    for (int j = 0; j < 8; j++) {
        atomicAdd(&s_sum[tc * 8 + j], cs[j]);
        atomicAdd(&s_sq[tc * 8 + j], cq[j]);
    }
    __syncthreads();
    atomicAdd(&g_sum3[t], (double)s_sum[t]);
    atomicAdd(&g_sq3[t], (double)s_sq[t]);
}

// ---- final: out = leaky(GN3(y) + s_feats) ----
__global__ __launch_bounds__(256) void k_final(const float* __restrict__ sf,
                                               float* __restrict__ out) {
    int i = blockIdx.x * 256 + threadIdx.x;
    float4 y = ((const float4*)g_y)[i];
    float4 s = ((const float4*)sf)[i];
    int c = (i & 63) * 4;
    float4 r;
    r.x = g_a3[c + 0] * y.x + g_b3v[c + 0] + s.x;
    r.y = g_a3[c + 1] * y.y + g_b3v[c + 1] + s.y;
    r.z = g_a3[c + 2] * y.z + g_b3v[c + 2] + s.z;
    r.w = g_a3[c + 3] * y.w + g_b3v[c + 3] + s.w;
    r.x = r.x >= 0.f ? r.x : SLOPE * r.x;
    r.y = r.y >= 0.f ? r.y : SLOPE * r.y;
    r.z = r.z >= 0.f ? r.z : SLOPE * r.z;
    r.w = r.w >= 0.f ? r.w : SLOPE * r.w;
    ((float4*)out)[i] = r;
}

extern "C" void kernel_launch(void* const* d_in, const int* in_sizes, int n_in,
                              void* d_out, int out_size) {
    const float* s_feats  = (const float*)d_in[0];
    const float* q_points = (const float*)d_in[1];
    const float* s_points = (const float*)d_in[2];
    const int*   nbr      = (const int*)d_in[3];
    const float* W1       = (const float*)d_in[4];
    const float* b1       = (const float*)d_in[5];
    const float* g1       = (const float*)d_in[6];
    const float* beta1    = (const float*)d_in[7];
    const float* kpw      = (const float*)d_in[8];
    const float* kpb      = (const float*)d_in[9];
    const float* kpts     = (const float*)d_in[10];
    const float* gg       = (const float*)d_in[11];
    const float* gb       = (const float*)d_in[12];
    const float* W2       = (const float*)d_in[13];
    const float* b2       = (const float*)d_in[14];
    const float* g2       = (const float*)d_in[15];
    const float* beta2    = (const float*)d_in[16];
    float* out = (float*)d_out;

    cudaFuncSetAttribute(k_pgemm, cudaFuncAttributeMaxDynamicSharedMemorySize, PG_SMEM);
    cudaFuncSetAttribute(k_gemm2, cudaFuncAttributeMaxDynamicSharedMemorySize, SMEM_F_BYTES);

    k_zero<<<1, 256>>>();
    k_prepB<<<(64 * 960 + 255) / 256, 256>>>(kpw);
    k_gemm1<<<NPTS / 128, 256>>>(s_feats, W1, b1);
    k_finalize<<<1, 256>>>(0, g1, beta1);
    k_apply1<<<NPTS * CMID / 4 / 256, 256>>>();
    k_gather<<<NPTS / 8, 256>>>(q_points, s_points, nbr, kpts);
    k_pgemm<<<NPTS / 128, 256, PG_SMEM>>>(kpb);
    k_stats64<<<256, 256>>>();
    k_finalize<<<1, 256>>>(1, gg, gb);
    k_gemm2<<<NPTS / 64, 256, SMEM_F_BYTES>>>(W2, b2);
    k_finalize<<<1, 256>>>(2, g2, beta2);
    k_final<<<NPTS * COUT / 4 / 256, 256>>>(s_feats, out);
}

// round 9
// speedup vs baseline: 2.1935x; 1.0932x over previous
#include <cuda_runtime.h>
#include <cuda_bf16.h>
#include <mma.h>
#include <cstdint>

#define NPTS 65536
#define HN 32
#define CIN 256
#define CMID 64
#define COUT 256
#define KP 15
#define SLOPE 0.1f
#define EPSV 1e-5f

using ull = unsigned long long;
using namespace nvcuda;

// ---- packed f32x2 helpers ----
__device__ __forceinline__ ull pk2(float lo, float hi) {
    ull r; asm("mov.b64 %0, {%1,%2};" : "=l"(r) : "f"(lo), "f"(hi)); return r;
}
__device__ __forceinline__ ull dup2(float v) { return pk2(v, v); }
__device__ __forceinline__ void fma2(ull& d, ull a, ull b) {
    asm("fma.rn.f32x2 %0, %1, %2, %3;" : "=l"(d) : "l"(a), "l"(b), "l"(d));
}
__device__ __forceinline__ float2 up2(ull v) {
    float lo, hi; asm("mov.b64 {%0,%1}, %2;" : "=f"(lo), "=f"(hi) : "l"(v));
    return make_float2(lo, hi);
}

// ---- cp.async helpers ----
__device__ __forceinline__ void cp16(void* sdst, const void* gsrc) {
    uint32_t s = (uint32_t)__cvta_generic_to_shared(sdst);
    asm volatile("cp.async.cg.shared.global [%0], [%1], 16;" :: "r"(s), "l"(gsrc));
}
#define CP_COMMIT() asm volatile("cp.async.commit_group;" ::: "memory")
#define CP_WAIT(n)  asm volatile("cp.async.wait_group %0;" :: "n"(n) : "memory")

// ---- scratch (device globals; aligned for vector-cast access) ----
__device__ __align__(256) float g_x1[NPTS * CMID];            // 16 MB
__device__ __align__(256) float g_out2[NPTS * CMID];          // 16 MB
__device__ __align__(256) float g_y[NPTS * COUT];             // 64 MB
__device__ __align__(256) __nv_bfloat16 g_Ahi[NPTS * 960];    // 126 MB
__device__ __align__(256) __nv_bfloat16 g_Alo[NPTS * 960];    // 126 MB
__device__ __align__(256) __nv_bfloat16 g_BhiT[64 * 960];
__device__ __align__(256) __nv_bfloat16 g_BloT[64 * 960];
__device__ float g_nnr[NPTS];
__device__ double g_sum1[CMID], g_sq1[CMID];
__device__ double g_sum2[CMID], g_sq2[CMID];
__device__ double g_sum3[COUT], g_sq3[COUT];
__device__ float g_a1[CMID], g_b1v[CMID];
__device__ float g_a2[CMID], g_b2v[CMID];
__device__ float g_a3[COUT], g_b3v[COUT];

__global__ void k_zero() {
    int t = threadIdx.x;
    if (t < CMID) { g_sum1[t] = 0.0; g_sq1[t] = 0.0; g_sum2[t] = 0.0; g_sq2[t] = 0.0; }
    if (t < COUT) { g_sum3[t] = 0.0; g_sq3[t] = 0.0; }
}

// ---- GEMM1 (WMMA bf16 hi/lo): x1 = s_feats @ W1 + b1 ; GN1 stats ----
// smem bf16 elts (stride 72): sAhi 128*72 | sAlo | sBhi 64*72 | sBlo | stats 512B
#define G1S 72
#define G1_SMEM (55296 + 512)

__global__ __launch_bounds__(256) void k_gemm1(const float* __restrict__ A,
                                               const float* __restrict__ W,
                                               const float* __restrict__ bias) {
    extern __shared__ __nv_bfloat16 sb1[];
    __nv_bfloat16* sAhi = sb1;                  // 9216 elts
    __nv_bfloat16* sAlo = sb1 + 9216;
    __nv_bfloat16* sBhi = sb1 + 18432;          // 4608 elts
    __nv_bfloat16* sBlo = sb1 + 23040;
    float* s_stats = (float*)(sb1 + 27648);     // 128 floats
    float* sOut = (float*)sb1;                  // epilogue reuse (36864 B = A region)

    int t = threadIdx.x;
    int warp = t >> 5;
    int wr = warp >> 1, wc = warp & 1;
    int row0 = blockIdx.x * 128;
    if (t < 128) s_stats[t] = 0.f;

    wmma::fragment<wmma::accumulator, 16, 16, 16, float> acc[2][2];
#pragma unroll
    for (int i = 0; i < 2; i++)
#pragma unroll
        for (int j = 0; j < 2; j++) wmma::fill_fragment(acc[i][j], 0.0f);

    for (int ch = 0; ch < 4; ch++) {
        __syncthreads();
        // A chunk 128x64 fp32 -> hi/lo bf16
#pragma unroll
        for (int i = 0; i < 8; i++) {
            int e = t + i * 256;            // float4 units, 2048 total
            int r = e >> 4, j = e & 15;
            float4 v = *(const float4*)&A[(size_t)(row0 + r) * CIN + ch * 64 + j * 4];
            __nv_bfloat162 h0 = __floats2bfloat162_rn(v.x, v.y);
            __nv_bfloat162 h1 = __floats2bfloat162_rn(v.z, v.w);
            __nv_bfloat162 l0 = __floats2bfloat162_rn(v.x - __bfloat162float(h0.x),
                                                      v.y - __bfloat162float(h0.y));
            __nv_bfloat162 l1 = __floats2bfloat162_rn(v.z - __bfloat162float(h1.x),
                                                      v.w - __bfloat162float(h1.y));
            *(uint2*)&sAhi[r * G1S + j * 4] = make_uint2(*(uint32_t*)&h0, *(uint32_t*)&h1);
            *(uint2*)&sAlo[r * G1S + j * 4] = make_uint2(*(uint32_t*)&l0, *(uint32_t*)&l1);
        }
        // B chunk: W1 rows ch*64..+63 x 64 cols
#pragma unroll
        for (int i = 0; i < 4; i++) {
            int e = t + i * 256;            // 1024 float4 units
            int r = e >> 4, j = e & 15;
            float4 v = *(const float4*)&W[(size_t)(ch * 64 + r) * CMID + j * 4];
            __nv_bfloat162 h0 = __floats2bfloat162_rn(v.x, v.y);
            __nv_bfloat162 h1 = __floats2bfloat162_rn(v.z, v.w);
            __nv_bfloat162 l0 = __floats2bfloat162_rn(v.x - __bfloat162float(h0.x),
                                                      v.y - __bfloat162float(h0.y));
            __nv_bfloat162 l1 = __floats2bfloat162_rn(v.z - __bfloat162float(h1.x),
                                                      v.w - __bfloat162float(h1.y));
            *(uint2*)&sBhi[r * G1S + j * 4] = make_uint2(*(uint32_t*)&h0, *(uint32_t*)&h1);
            *(uint2*)&sBlo[r * G1S + j * 4] = make_uint2(*(uint32_t*)&l0, *(uint32_t*)&l1);
        }
        __syncthreads();

#pragma unroll
        for (int kk = 0; kk < 4; kk++) {
            wmma::fragment<wmma::matrix_a, 16, 16, 16, __nv_bfloat16, wmma::row_major> a_hi[2], a_lo[2];
            wmma::fragment<wmma::matrix_b, 16, 16, 16, __nv_bfloat16, wmma::row_major> b_hi[2], b_lo[2];
#pragma unroll
            for (int i = 0; i < 2; i++) {
                wmma::load_matrix_sync(a_hi[i], &sAhi[(wr * 32 + i * 16) * G1S + kk * 16], G1S);
                wmma::load_matrix_sync(a_lo[i], &sAlo[(wr * 32 + i * 16) * G1S + kk * 16], G1S);
            }
#pragma unroll
            for (int j = 0; j < 2; j++) {
                wmma::load_matrix_sync(b_hi[j], &sBhi[(kk * 16) * G1S + wc * 32 + j * 16], G1S);
                wmma::load_matrix_sync(b_lo[j], &sBlo[(kk * 16) * G1S + wc * 32 + j * 16], G1S);
            }
#pragma unroll
            for (int i = 0; i < 2; i++)
#pragma unroll
                for (int j = 0; j < 2; j++) {
                    wmma::mma_sync(acc[i][j], a_hi[i], b_hi[j], acc[i][j]);
                    wmma::mma_sync(acc[i][j], a_lo[i], b_hi[j], acc[i][j]);
                    wmma::mma_sync(acc[i][j], a_hi[i], b_lo[j], acc[i][j]);
                }
        }
    }

    __syncthreads();
#pragma unroll
    for (int i = 0; i < 2; i++)
#pragma unroll
        for (int j = 0; j < 2; j++)
            wmma::store_matrix_sync(&sOut[(wr * 32 + i * 16) * G1S + wc * 32 + j * 16],
                                    acc[i][j], G1S, wmma::mem_row_major);
    __syncthreads();

    // epilogue: fixed channel quad per thread (c4 = t & 15), 8 rows
    {
        int c4 = t & 15;
        float b0 = bias[c4 * 4 + 0], b1 = bias[c4 * 4 + 1];
        float b2 = bias[c4 * 4 + 2], b3 = bias[c4 * 4 + 3];
        float cs[4] = {0, 0, 0, 0}, cq[4] = {0, 0, 0, 0};
#pragma unroll
        for (int i = 0; i < 8; i++) {
            int r = (t >> 4) + i * 16;
            float4 v = *(const float4*)&sOut[r * G1S + c4 * 4];
            v.x += b0; v.y += b1; v.z += b2; v.w += b3;
            *(float4*)&g_x1[(size_t)(row0 + r) * CMID + c4 * 4] = v;
            cs[0] += v.x; cq[0] += v.x * v.x;
            cs[1] += v.y; cq[1] += v.y * v.y;
            cs[2] += v.z; cq[2] += v.z * v.z;
            cs[3] += v.w; cq[3] += v.w * v.w;
        }
#pragma unroll
        for (int j = 0; j < 4; j++) {
            atomicAdd(&s_stats[c4 * 4 + j], cs[j]);
            atomicAdd(&s_stats[64 + c4 * 4 + j], cq[j]);
        }
    }
    __syncthreads();
    if (t < 64) {
        atomicAdd(&g_sum1[t], (double)s_stats[t]);
        atomicAdd(&g_sq1[t], (double)s_stats[64 + t]);
    }
}

// ---- finalize GN stats ----
__global__ void k_finalize(int stage, const float* __restrict__ gamma,
                           const float* __restrict__ beta) {
    int c = threadIdx.x;
    if (stage < 2) {
        if (c >= CMID) return;
        const double* sum = (stage == 0) ? g_sum1 : g_sum2;
        const double* sq  = (stage == 0) ? g_sq1  : g_sq2;
        float* a = (stage == 0) ? g_a1 : g_a2;
        float* b = (stage == 0) ? g_b1v : g_b2v;
        int g = c >> 1;
        double s = sum[g * 2] + sum[g * 2 + 1];
        double q = sq[g * 2] + sq[g * 2 + 1];
        double cnt = 2.0 * (double)NPTS;
        double mean = s / cnt;
        double var = q / cnt - mean * mean;
        float inv = rsqrtf((float)var + EPSV);
        float av = gamma[c] * inv;
        a[c] = av;
        b[c] = beta[c] - (float)mean * av;
    } else {
        if (c >= COUT) return;
        int g = c >> 3;
        double s = 0.0, q = 0.0;
#pragma unroll
        for (int i = 0; i < 8; i++) { s += g_sum3[g * 8 + i]; q += g_sq3[g * 8 + i]; }
        double cnt = 8.0 * (double)NPTS;
        double mean = s / cnt;
        double var = q / cnt - mean * mean;
        float inv = rsqrtf((float)var + EPSV);
        float av = gamma[c] * inv;
        g_a3[c] = av;
        g_b3v[c] = beta[c] - (float)mean * av;
    }
}

// ---- apply GN1 + leaky in place ----
__global__ __launch_bounds__(256) void k_apply1() {
    int i = blockIdx.x * 256 + threadIdx.x;
    float4 v = ((const float4*)g_x1)[i];
    int c = (i & 15) * 4;
    float4 r;
    r.x = g_a1[c + 0] * v.x + g_b1v[c + 0];
    r.y = g_a1[c + 1] * v.y + g_b1v[c + 1];
    r.z = g_a1[c + 2] * v.z + g_b1v[c + 2];
    r.w = g_a1[c + 3] * v.w + g_b1v[c + 3];
    r.x = r.x >= 0.f ? r.x : SLOPE * r.x;
    r.y = r.y >= 0.f ? r.y : SLOPE * r.y;
    r.z = r.z >= 0.f ? r.z : SLOPE * r.z;
    r.w = r.w >= 0.f ? r.w : SLOPE * r.w;
    ((float4*)g_x1)[i] = r;
}

// ---- kw transpose+split prep ----
__global__ __launch_bounds__(256) void k_prepB(const float* __restrict__ kw) {
    int idx = blockIdx.x * 256 + threadIdx.x;
    if (idx >= 64 * 960) return;
    int d = idx / 960;
    int r = idx % 960;
    float v = kw[r * 64 + d];
    __nv_bfloat16 h = __float2bfloat16(v);
    float hf = __bfloat162float(h);
    g_BhiT[d * 960 + r] = h;
    g_BloT[d * 960 + r] = __float2bfloat16(v - hf);
}

// ---- k_gather: KPConv phases 1+2 (unchanged) ----
__global__ __launch_bounds__(256, 3) void k_gather(
        const float* __restrict__ qp, const float* __restrict__ sp,
        const int* __restrict__ nbr, const float* __restrict__ kpts) {
    __shared__ float s_kp[48];
    __shared__ float s_w[8 * 32 * 16];
    __shared__ int s_nbr[256];

    int t = threadIdx.x;
    int p0 = blockIdx.x * 8;

    if (t < 45) s_kp[t] = kpts[t];
    __syncthreads();

    {
        int p = t >> 5, h = t & 31;
        int idx = nbr[(p0 + p) * HN + h];
        s_nbr[t] = idx;
        float dx, dy, dz;
        bool valid = (unsigned)idx < NPTS;
        if (valid) {
            dx = sp[idx * 3 + 0] - qp[(p0 + p) * 3 + 0];
            dy = sp[idx * 3 + 1] - qp[(p0 + p) * 3 + 1];
            dz = sp[idx * 3 + 2] - qp[(p0 + p) * 3 + 2];
        } else { dx = dy = dz = 1e10f; }
        unsigned m = __ballot_sync(0xffffffffu, valid);
        if ((t & 31) == 0) {
            int nn = __popc(m);
            g_nnr[p0 + p] = 1.0f / (float)(nn > 1 ? nn : 1);
        }
#pragma unroll
        for (int k = 0; k < KP; k++) {
            float ex = dx - s_kp[k * 3 + 0];
            float ey = dy - s_kp[k * 3 + 1];
            float ez = dz - s_kp[k * 3 + 2];
            float dist = sqrtf(ex * ex + ey * ey + ez * ez);
            s_w[t * 16 + k] = fmaxf(1.0f - dist, 0.0f);
        }
        s_w[t * 16 + 15] = 0.f;
    }
    __syncthreads();

    {
        int p = t >> 5;
        int c2 = (t & 31) * 2;
        ull acc[8][2];
#pragma unroll
        for (int a = 0; a < 8; a++) { acc[a][0] = 0ull; acc[a][1] = 0ull; }
#pragma unroll 4
        for (int h = 0; h < HN; h++) {
            int idx = s_nbr[p * 32 + h];
            float2 f;
            if ((unsigned)idx < NPTS) f = *(const float2*)&g_x1[(size_t)idx * CMID + c2];
            else f = make_float2(0.f, 0.f);
            ull fd0 = dup2(f.x), fd1 = dup2(f.y);
            const ull* w2 = (const ull*)&s_w[(p * 32 + h) * 16];
#pragma unroll
            for (int kp2 = 0; kp2 < 8; kp2++) {
                ull wv = w2[kp2];
                fma2(acc[kp2][0], wv, fd0);
                fma2(acc[kp2][1], wv, fd1);
            }
        }
        int n = p0 + p;
        uint32_t* hiw = (uint32_t*)g_Ahi;
        uint32_t* low = (uint32_t*)g_Alo;
        int base = n * 480 + (c2 >> 1);
#pragma unroll
        for (int kp2 = 0; kp2 < 8; kp2++) {
            float2 a0 = up2(acc[kp2][0]);
            float2 a1 = up2(acc[kp2][1]);
            int k0 = kp2 * 2;
            {
                __nv_bfloat162 h = __floats2bfloat162_rn(a0.x, a1.x);
                float hx = __bfloat162float(h.x), hy = __bfloat162float(h.y);
                __nv_bfloat162 l = __floats2bfloat162_rn(a0.x - hx, a1.x - hy);
                hiw[base + k0 * 32] = *(uint32_t*)&h;
                low[base + k0 * 32] = *(uint32_t*)&l;
            }
            if (k0 + 1 < KP) {
                __nv_bfloat162 h = __floats2bfloat162_rn(a0.y, a1.y);
                float hx = __bfloat162float(h.x), hy = __bfloat162float(h.y);
                __nv_bfloat162 l = __floats2bfloat162_rn(a0.y - hx, a1.y - hy);
                hiw[base + (k0 + 1) * 32] = *(uint32_t*)&h;
                low[base + (k0 + 1) * 32] = *(uint32_t*)&l;
            }
        }
    }
}

// ---- k_pgemm: WMMA + cp.async double buffering + fused GN2 stats ----
// smem bf16 elts (stride 72): Ahi[2] 9216 ea | Alo[2] | Bhi[2] 4608 ea | Blo[2] | stats 512B
#define PGS 72
#define PG_A(h, b) (sbp + (h) * 18432 + (b) * 9216)
#define PG_B(h, b) (sbp + 36864 + (h) * 9216 + (b) * 4608)
#define PG_SMEM (110592 + 512)

__global__ __launch_bounds__(256, 2) void k_pgemm(const float* __restrict__ kb) {
    extern __shared__ __nv_bfloat16 sbp[];
    float* s_stats = (float*)(sbp + 55296);   // byte 110592, 128 floats
    float* sOut = (float*)sbp;                // epilogue reuse (36864 B in Ahi region)

    int t = threadIdx.x;
    int warp = t >> 5;
    int wr = warp >> 1, wc = warp & 1;
    int row0 = blockIdx.x * 128;
    if (t < 128) s_stats[t] = 0.f;

    wmma::fragment<wmma::accumulator, 16, 16, 16, float> acc[2][2];
#pragma unroll
    for (int i = 0; i < 2; i++)
#pragma unroll
        for (int j = 0; j < 2; j++) wmma::fill_fragment(acc[i][j], 0.0f);

    const __nv_bfloat16* Ahi = g_Ahi + (size_t)row0 * 960;
    const __nv_bfloat16* Alo = g_Alo + (size_t)row0 * 960;

    // async fill of chunk ch into buffer b
    auto fill = [&](int ch, int b) {
#pragma unroll
        for (int i = 0; i < 4; i++) {
            int e = t + i * 256;            // 1024 uint4 units (A)
            int r = e >> 3, j = e & 7;
            cp16(PG_A(0, b) + r * PGS + j * 8, Ahi + (size_t)r * 960 + ch * 64 + j * 8);
            cp16(PG_A(1, b) + r * PGS + j * 8, Alo + (size_t)r * 960 + ch * 64 + j * 8);
        }
#pragma unroll
        for (int i = 0; i < 2; i++) {
            int e = t + i * 256;            // 512 uint4 units (B)
            int r = e >> 3, j = e & 7;
            cp16(PG_B(0, b) + r * PGS + j * 8, g_BhiT + (size_t)r * 960 + ch * 64 + j * 8);
            cp16(PG_B(1, b) + r * PGS + j * 8, g_BloT + (size_t)r * 960 + ch * 64 + j * 8);
        }
    };

    fill(0, 0);
    CP_COMMIT();

    for (int ch = 0; ch < 15; ch++) {
        int buf = ch & 1;
        if (ch < 14) {
            fill(ch + 1, buf ^ 1);
            CP_COMMIT();
            CP_WAIT(1);
        } else {
            CP_WAIT(0);
        }
        __syncthreads();

        __nv_bfloat16* sAhi = PG_A(0, buf);
        __nv_bfloat16* sAlo = PG_A(1, buf);
        __nv_bfloat16* sBhi = PG_B(0, buf);
        __nv_bfloat16* sBlo = PG_B(1, buf);
#pragma unroll
        for (int kk = 0; kk < 4; kk++) {
            wmma::fragment<wmma::matrix_a, 16, 16, 16, __nv_bfloat16, wmma::row_major> a_hi[2], a_lo[2];
            wmma::fragment<wmma::matrix_b, 16, 16, 16, __nv_bfloat16, wmma::col_major> b_hi[2], b_lo[2];
#pragma unroll
            for (int i = 0; i < 2; i++) {
                wmma::load_matrix_sync(a_hi[i], &sAhi[(wr * 32 + i * 16) * PGS + kk * 16], PGS);
                wmma::load_matrix_sync(a_lo[i], &sAlo[(wr * 32 + i * 16) * PGS + kk * 16], PGS);
            }
#pragma unroll
            for (int j = 0; j < 2; j++) {
                wmma::load_matrix_sync(b_hi[j], &sBhi[(wc * 32 + j * 16) * PGS + kk * 16], PGS);
                wmma::load_matrix_sync(b_lo[j], &sBlo[(wc * 32 + j * 16) * PGS + kk * 16], PGS);
            }
#pragma unroll
            for (int i = 0; i < 2; i++)
#pragma unroll
                for (int j = 0; j < 2; j++) {
                    wmma::mma_sync(acc[i][j], a_hi[i], b_hi[j], acc[i][j]);
                    wmma::mma_sync(acc[i][j], a_lo[i], b_hi[j], acc[i][j]);
                    wmma::mma_sync(acc[i][j], a_hi[i], b_lo[j], acc[i][j]);
                }
        }
        __syncthreads();
    }

    // epilogue: store acc, then /nnum + bias, write, GN2 stats
#pragma unroll
    for (int i = 0; i < 2; i++)
#pragma unroll
        for (int j = 0; j < 2; j++)
            wmma::store_matrix_sync(&sOut[(wr * 32 + i * 16) * PGS + wc * 32 + j * 16],
                                    acc[i][j], PGS, wmma::mem_row_major);
    __syncthreads();

    {
        int c4 = t & 15;
        float b0 = kb[c4 * 4 + 0], b1 = kb[c4 * 4 + 1];
        float b2 = kb[c4 * 4 + 2], b3 = kb[c4 * 4 + 3];
        float cs[4] = {0, 0, 0, 0}, cq[4] = {0, 0, 0, 0};
#pragma unroll
        for (int i = 0; i < 8; i++) {
            int r = (t >> 4) + i * 16;
            float nnr = g_nnr[row0 + r];
            float4 v = *(const float4*)&sOut[r * PGS + c4 * 4];
            v.x = v.x * nnr + b0;
            v.y = v.y * nnr + b1;
            v.z = v.z * nnr + b2;
            v.w = v.w * nnr + b3;
            *(float4*)&g_out2[(size_t)(row0 + r) * CMID + c4 * 4] = v;
            cs[0] += v.x; cq[0] += v.x * v.x;
            cs[1] += v.y; cq[1] += v.y * v.y;
            cs[2] += v.z; cq[2] += v.z * v.z;
            cs[3] += v.w; cq[3] += v.w * v.w;
        }
#pragma unroll
        for (int j = 0; j < 4; j++) {
            atomicAdd(&s_stats[c4 * 4 + j], cs[j]);
            atomicAdd(&s_stats[64 + c4 * 4 + j], cq[j]);
        }
    }
    __syncthreads();
    if (t < 64) {
        atomicAdd(&g_sum2[t], (double)s_stats[t]);
        atomicAdd(&g_sq2[t], (double)s_stats[64 + t]);
    }
}

// ---- GEMM2 (fp32 f32x2, unchanged) ----
#define SMEM_F_BYTES ((16384 + 64*68 + 256 + 256) * 4)

__global__ __launch_bounds__(256) void k_gemm2(const float* __restrict__ W2,
                                               const float* __restrict__ b2) {
    extern __shared__ float sh[];
    float* s_W   = sh;
    float* s_At  = sh + 16384;
    float* s_sum = s_At + 64 * 68;
    float* s_sq  = s_sum + 256;
    int t = threadIdx.x;
    int row0 = blockIdx.x * 64;

    for (int e = t; e < 64 * 256; e += 256) s_W[e] = W2[e];
    for (int e = t; e < 64 * 64; e += 256) {
        int r = e >> 6, c = e & 63;
        float v = g_out2[(size_t)(row0 + r) * CMID + c];
        v = g_a2[c] * v + g_b2v[c];
        v = v >= 0.f ? v : SLOPE * v;
        s_At[c * 68 + r] = v;
    }
    s_sum[t] = 0.f; s_sq[t] = 0.f;
    __syncthreads();

    int tr = t >> 5;
    int tc = t & 31;
    ull acc[8][4];
#pragma unroll
    for (int i = 0; i < 8; i++)
#pragma unroll
        for (int j = 0; j < 4; j++) acc[i][j] = 0ull;

#pragma unroll 4
    for (int k = 0; k < 64; k++) {
        float4 a0 = *(const float4*)&s_At[k * 68 + tr * 8];
        float4 a1 = *(const float4*)&s_At[k * 68 + tr * 8 + 4];
        ulonglong2 w0 = *(const ulonglong2*)&s_W[k * 256 + tc * 8];
        ulonglong2 w1 = *(const ulonglong2*)&s_W[k * 256 + tc * 8 + 4];
        ull d;
        d = dup2(a0.x); fma2(acc[0][0], d, w0.x); fma2(acc[0][1], d, w0.y); fma2(acc[0][2], d, w1.x); fma2(acc[0][3], d, w1.y);
        d = dup2(a0.y); fma2(acc[1][0], d, w0.x); fma2(acc[1][1], d, w0.y); fma2(acc[1][2], d, w1.x); fma2(acc[1][3], d, w1.y);
        d = dup2(a0.z); fma2(acc[2][0], d, w0.x); fma2(acc[2][1], d, w0.y); fma2(acc[2][2], d, w1.x); fma2(acc[2][3], d, w1.y);
        d = dup2(a0.w); fma2(acc[3][0], d, w0.x); fma2(acc[3][1], d, w0.y); fma2(acc[3][2], d, w1.x); fma2(acc[3][3], d, w1.y);
        d = dup2(a1.x); fma2(acc[4][0], d, w0.x); fma2(acc[4][1], d, w0.y); fma2(acc[4][2], d, w1.x); fma2(acc[4][3], d, w1.y);
        d = dup2(a1.y); fma2(acc[5][0], d, w0.x); fma2(acc[5][1], d, w0.y); fma2(acc[5][2], d, w1.x); fma2(acc[5][3], d, w1.y);
        d = dup2(a1.z); fma2(acc[6][0], d, w0.x); fma2(acc[6][1], d, w0.y); fma2(acc[6][2], d, w1.x); fma2(acc[6][3], d, w1.y);
        d = dup2(a1.w); fma2(acc[7][0], d, w0.x); fma2(acc[7][1], d, w0.y); fma2(acc[7][2], d, w1.x); fma2(acc[7][3], d, w1.y);
    }
    float cs[8] = {0}, cq[8] = {0};
#pragma unroll
    for (int i = 0; i < 8; i++) {
        int r = row0 + tr * 8 + i;
        float2 v0 = up2(acc[i][0]), v1 = up2(acc[i][1]);
        float2 v2 = up2(acc[i][2]), v3 = up2(acc[i][3]);
        float v[8] = {v0.x, v0.y, v1.x, v1.y, v2.x, v2.y, v3.x, v3.y};
#pragma unroll
        for (int j = 0; j < 8; j++) {
            int cc = tc * 8 + j;
            v[j] += b2[cc];
            cs[j] += v[j]; cq[j] += v[j] * v[j];
        }
        float4* dst = (float4*)&g_y[(size_t)r * COUT + tc * 8];
        dst[0] = make_float4(v[0], v[1], v[2], v[3]);
        dst[1] = make_float4(v[4], v[5], v[6], v[7]);
    }
#pragma unroll
    for (int j = 0; j < 8; j++) {
        atomicAdd(&s_sum[tc * 8 + j], cs[j]);
        atomicAdd(&s_sq[tc * 8 + j], cq[j]);
    }
    __syncthreads();
    atomicAdd(&g_sum3[t], (double)s_sum[t]);
    atomicAdd(&g_sq3[t], (double)s_sq[t]);
}

// ---- final: out = leaky(GN3(y) + s_feats) ----
__global__ __launch_bounds__(256) void k_final(const float* __restrict__ sf,
                                               float* __restrict__ out) {
    int i = blockIdx.x * 256 + threadIdx.x;
    float4 y = ((const float4*)g_y)[i];
    float4 s = ((const float4*)sf)[i];
    int c = (i & 63) * 4;
    float4 r;
    r.x = g_a3[c + 0] * y.x + g_b3v[c + 0] + s.x;
    r.y = g_a3[c + 1] * y.y + g_b3v[c + 1] + s.y;
    r.z = g_a3[c + 2] * y.z + g_b3v[c + 2] + s.z;
    r.w = g_a3[c + 3] * y.w + g_b3v[c + 3] + s.w;
    r.x = r.x >= 0.f ? r.x : SLOPE * r.x;
    r.y = r.y >= 0.f ? r.y : SLOPE * r.y;
    r.z = r.z >= 0.f ? r.z : SLOPE * r.z;
    r.w = r.w >= 0.f ? r.w : SLOPE * r.w;
    ((float4*)out)[i] = r;
}

extern "C" void kernel_launch(void* const* d_in, const int* in_sizes, int n_in,
                              void* d_out, int out_size) {
    const float* s_feats  = (const float*)d_in[0];
    const float* q_points = (const float*)d_in[1];
    const float* s_points = (const float*)d_in[2];
    const int*   nbr      = (const int*)d_in[3];
    const float* W1       = (const float*)d_in[4];
    const float* b1       = (const float*)d_in[5];
    const float* g1       = (const float*)d_in[6];
    const float* beta1    = (const float*)d_in[7];
    const float* kpw      = (const float*)d_in[8];
    const float* kpb      = (const float*)d_in[9];
    const float* kpts     = (const float*)d_in[10];
    const float* gg       = (const float*)d_in[11];
    const float* gb       = (const float*)d_in[12];
    const float* W2       = (const float*)d_in[13];
    const float* b2       = (const float*)d_in[14];
    const float* g2       = (const float*)d_in[15];
    const float* beta2    = (const float*)d_in[16];
    float* out = (float*)d_out;

    cudaFuncSetAttribute(k_gemm1, cudaFuncAttributeMaxDynamicSharedMemorySize, G1_SMEM);
    cudaFuncSetAttribute(k_pgemm, cudaFuncAttributeMaxDynamicSharedMemorySize, PG_SMEM);
    cudaFuncSetAttribute(k_gemm2, cudaFuncAttributeMaxDynamicSharedMemorySize, SMEM_F_BYTES);

    k_zero<<<1, 256>>>();
    k_prepB<<<(64 * 960 + 255) / 256, 256>>>(kpw);
    k_gemm1<<<NPTS / 128, 256, G1_SMEM>>>(s_feats, W1, b1);
    k_finalize<<<1, 256>>>(0, g1, beta1);
    k_apply1<<<NPTS * CMID / 4 / 256, 256>>>();
    k_gather<<<NPTS / 8, 256>>>(q_points, s_points, nbr, kpts);
    k_pgemm<<<NPTS / 128, 256, PG_SMEM>>>(kpb);
    k_finalize<<<1, 256>>>(1, gg, gb);
    k_gemm2<<<NPTS / 64, 256, SMEM_F_BYTES>>>(W2, b2);
    k_finalize<<<1, 256>>>(2, g2, beta2);
    k_final<<<NPTS * COUT / 4 / 256, 256>>>(s_feats, out);
}

// round 10
// speedup vs baseline: 2.3898x; 1.0895x over previous
#include <cuda_runtime.h>
#include <cuda_bf16.h>
#include <mma.h>
#include <cstdint>

#define NPTS 65536
#define HN 32
#define CIN 256
#define CMID 64
#define COUT 256
#define KP 15
#define SLOPE 0.1f
#define EPSV 1e-5f

using ull = unsigned long long;
using namespace nvcuda;

// ---- packed f32x2 helpers ----
__device__ __forceinline__ ull pk2(float lo, float hi) {
    ull r; asm("mov.b64 %0, {%1,%2};" : "=l"(r) : "f"(lo), "f"(hi)); return r;
}
__device__ __forceinline__ ull dup2(float v) { return pk2(v, v); }
__device__ __forceinline__ void fma2(ull& d, ull a, ull b) {
    asm("fma.rn.f32x2 %0, %1, %2, %3;" : "=l"(d) : "l"(a), "l"(b), "l"(d));
}
__device__ __forceinline__ float2 up2(ull v) {
    float lo, hi; asm("mov.b64 {%0,%1}, %2;" : "=f"(lo), "=f"(hi) : "l"(v));
    return make_float2(lo, hi);
}

// ---- cp.async helpers ----
__device__ __forceinline__ void cp16(void* sdst, const void* gsrc) {
    uint32_t s = (uint32_t)__cvta_generic_to_shared(sdst);
    asm volatile("cp.async.cg.shared.global [%0], [%1], 16;" :: "r"(s), "l"(gsrc));
}
#define CP_COMMIT() asm volatile("cp.async.commit_group;" ::: "memory")
#define CP_WAIT(n)  asm volatile("cp.async.wait_group %0;" :: "n"(n) : "memory")

// ---- hi/lo split helper ----
__device__ __forceinline__ void split2(float x, float y, uint32_t& h, uint32_t& l) {
    __nv_bfloat162 hh = __floats2bfloat162_rn(x, y);
    __nv_bfloat162 ll = __floats2bfloat162_rn(x - __bfloat162float(hh.x),
                                              y - __bfloat162float(hh.y));
    h = *(uint32_t*)&hh;
    l = *(uint32_t*)&ll;
}

// ---- scratch (device globals; aligned for vector-cast access) ----
__device__ __align__(256) float g_x1[NPTS * CMID];            // 16 MB (raw, pre-GN1)
__device__ __align__(256) float g_out2[NPTS * CMID];          // 16 MB
__device__ __align__(256) float g_y[NPTS * COUT];             // 64 MB
__device__ __align__(256) __nv_bfloat16 g_Ahi[NPTS * 960];    // 126 MB
__device__ __align__(256) __nv_bfloat16 g_Alo[NPTS * 960];    // 126 MB
__device__ __align__(256) __nv_bfloat16 g_BhiT[64 * 960];
__device__ __align__(256) __nv_bfloat16 g_BloT[64 * 960];
__device__ float g_nnr[NPTS];
__device__ double g_sum1[CMID], g_sq1[CMID];
__device__ double g_sum2[CMID], g_sq2[CMID];
__device__ double g_sum3[COUT], g_sq3[COUT];
__device__ float g_a1[CMID], g_b1v[CMID];
__device__ float g_a2[CMID], g_b2v[CMID];
__device__ float g_a3[COUT], g_b3v[COUT];

// ---- k_prep: zero stats (block 0) + kw transpose/split ----
__global__ __launch_bounds__(256) void k_prep(const float* __restrict__ kw) {
    int t = threadIdx.x;
    if (blockIdx.x == 0) {
        if (t < CMID) { g_sum1[t] = 0.0; g_sq1[t] = 0.0; g_sum2[t] = 0.0; g_sq2[t] = 0.0; }
        if (t < COUT) { g_sum3[t] = 0.0; g_sq3[t] = 0.0; }
    }
    int idx = blockIdx.x * 256 + t;      // 61440 = 240*256 exactly
    int d = idx / 960;
    int r = idx % 960;
    float v = kw[r * 64 + d];
    __nv_bfloat16 h = __float2bfloat16(v);
    g_BhiT[d * 960 + r] = h;
    g_BloT[d * 960 + r] = __float2bfloat16(v - __bfloat162float(h));
}

// ---- GEMM1 (WMMA bf16 hi/lo): x1 = s_feats @ W1 + b1 ; GN1 stats ----
#define G1S 72
#define G1_SMEM (55296 + 512)

__global__ __launch_bounds__(256) void k_gemm1(const float* __restrict__ A,
                                               const float* __restrict__ W,
                                               const float* __restrict__ bias) {
    extern __shared__ __nv_bfloat16 sb1[];
    __nv_bfloat16* sAhi = sb1;
    __nv_bfloat16* sAlo = sb1 + 9216;
    __nv_bfloat16* sBhi = sb1 + 18432;
    __nv_bfloat16* sBlo = sb1 + 23040;
    float* s_stats = (float*)(sb1 + 27648);
    float* sOut = (float*)sb1;

    int t = threadIdx.x;
    int warp = t >> 5;
    int wr = warp >> 1, wc = warp & 1;
    int row0 = blockIdx.x * 128;
    if (t < 128) s_stats[t] = 0.f;

    wmma::fragment<wmma::accumulator, 16, 16, 16, float> acc[2][2];
#pragma unroll
    for (int i = 0; i < 2; i++)
#pragma unroll
        for (int j = 0; j < 2; j++) wmma::fill_fragment(acc[i][j], 0.0f);

    for (int ch = 0; ch < 4; ch++) {
        __syncthreads();
#pragma unroll
        for (int i = 0; i < 8; i++) {
            int e = t + i * 256;
            int r = e >> 4, j = e & 15;
            float4 v = *(const float4*)&A[(size_t)(row0 + r) * CIN + ch * 64 + j * 4];
            uint32_t h0, l0, h1, l1;
            split2(v.x, v.y, h0, l0);
            split2(v.z, v.w, h1, l1);
            *(uint2*)&sAhi[r * G1S + j * 4] = make_uint2(h0, h1);
            *(uint2*)&sAlo[r * G1S + j * 4] = make_uint2(l0, l1);
        }
#pragma unroll
        for (int i = 0; i < 4; i++) {
            int e = t + i * 256;
            int r = e >> 4, j = e & 15;
            float4 v = *(const float4*)&W[(size_t)(ch * 64 + r) * CMID + j * 4];
            uint32_t h0, l0, h1, l1;
            split2(v.x, v.y, h0, l0);
            split2(v.z, v.w, h1, l1);
            *(uint2*)&sBhi[r * G1S + j * 4] = make_uint2(h0, h1);
            *(uint2*)&sBlo[r * G1S + j * 4] = make_uint2(l0, l1);
        }
        __syncthreads();

#pragma unroll
        for (int kk = 0; kk < 4; kk++) {
            wmma::fragment<wmma::matrix_a, 16, 16, 16, __nv_bfloat16, wmma::row_major> a_hi[2], a_lo[2];
            wmma::fragment<wmma::matrix_b, 16, 16, 16, __nv_bfloat16, wmma::row_major> b_hi[2], b_lo[2];
#pragma unroll
            for (int i = 0; i < 2; i++) {
                wmma::load_matrix_sync(a_hi[i], &sAhi[(wr * 32 + i * 16) * G1S + kk * 16], G1S);
                wmma::load_matrix_sync(a_lo[i], &sAlo[(wr * 32 + i * 16) * G1S + kk * 16], G1S);
            }
#pragma unroll
            for (int j = 0; j < 2; j++) {
                wmma::load_matrix_sync(b_hi[j], &sBhi[(kk * 16) * G1S + wc * 32 + j * 16], G1S);
                wmma::load_matrix_sync(b_lo[j], &sBlo[(kk * 16) * G1S + wc * 32 + j * 16], G1S);
            }
#pragma unroll
            for (int i = 0; i < 2; i++)
#pragma unroll
                for (int j = 0; j < 2; j++) {
                    wmma::mma_sync(acc[i][j], a_hi[i], b_hi[j], acc[i][j]);
                    wmma::mma_sync(acc[i][j], a_lo[i], b_hi[j], acc[i][j]);
                    wmma::mma_sync(acc[i][j], a_hi[i], b_lo[j], acc[i][j]);
                }
        }
    }

    __syncthreads();
#pragma unroll
    for (int i = 0; i < 2; i++)
#pragma unroll
        for (int j = 0; j < 2; j++)
            wmma::store_matrix_sync(&sOut[(wr * 32 + i * 16) * G1S + wc * 32 + j * 16],
                                    acc[i][j], G1S, wmma::mem_row_major);
    __syncthreads();

    {
        int c4 = t & 15;
        float b0 = bias[c4 * 4 + 0], b1 = bias[c4 * 4 + 1];
        float b2 = bias[c4 * 4 + 2], b3 = bias[c4 * 4 + 3];
        float cs[4] = {0, 0, 0, 0}, cq[4] = {0, 0, 0, 0};
#pragma unroll
        for (int i = 0; i < 8; i++) {
            int r = (t >> 4) + i * 16;
            float4 v = *(const float4*)&sOut[r * G1S + c4 * 4];
            v.x += b0; v.y += b1; v.z += b2; v.w += b3;
            *(float4*)&g_x1[(size_t)(row0 + r) * CMID + c4 * 4] = v;
            cs[0] += v.x; cq[0] += v.x * v.x;
            cs[1] += v.y; cq[1] += v.y * v.y;
            cs[2] += v.z; cq[2] += v.z * v.z;
            cs[3] += v.w; cq[3] += v.w * v.w;
        }
#pragma unroll
        for (int j = 0; j < 4; j++) {
            atomicAdd(&s_stats[c4 * 4 + j], cs[j]);
            atomicAdd(&s_stats[64 + c4 * 4 + j], cq[j]);
        }
    }
    __syncthreads();
    if (t < 64) {
        atomicAdd(&g_sum1[t], (double)s_stats[t]);
        atomicAdd(&g_sq1[t], (double)s_stats[64 + t]);
    }
}

// ---- finalize GN stats ----
__global__ void k_finalize(int stage, const float* __restrict__ gamma,
                           const float* __restrict__ beta) {
    int c = threadIdx.x;
    if (stage < 2) {
        if (c >= CMID) return;
        const double* sum = (stage == 0) ? g_sum1 : g_sum2;
        const double* sq  = (stage == 0) ? g_sq1  : g_sq2;
        float* a = (stage == 0) ? g_a1 : g_a2;
        float* b = (stage == 0) ? g_b1v : g_b2v;
        int g = c >> 1;
        double s = sum[g * 2] + sum[g * 2 + 1];
        double q = sq[g * 2] + sq[g * 2 + 1];
        double cnt = 2.0 * (double)NPTS;
        double mean = s / cnt;
        double var = q / cnt - mean * mean;
        float inv = rsqrtf((float)var + EPSV);
        float av = gamma[c] * inv;
        a[c] = av;
        b[c] = beta[c] - (float)mean * av;
    } else {
        if (c >= COUT) return;
        int g = c >> 3;
        double s = 0.0, q = 0.0;
#pragma unroll
        for (int i = 0; i < 8; i++) { s += g_sum3[g * 8 + i]; q += g_sq3[g * 8 + i]; }
        double cnt = 8.0 * (double)NPTS;
        double mean = s / cnt;
        double var = q / cnt - mean * mean;
        float inv = rsqrtf((float)var + EPSV);
        float av = gamma[c] * inv;
        g_a3[c] = av;
        g_b3v[c] = beta[c] - (float)mean * av;
    }
}

// ---- k_gather: KPConv phases 1+2 with fused GN1+leaky on x1 read ----
__global__ __launch_bounds__(256, 3) void k_gather(
        const float* __restrict__ qp, const float* __restrict__ sp,
        const int* __restrict__ nbr, const float* __restrict__ kpts) {
    __shared__ float s_kp[48];
    __shared__ float s_w[8 * 32 * 16];
    __shared__ int s_nbr[256];

    int t = threadIdx.x;
    int p0 = blockIdx.x * 8;

    if (t < 45) s_kp[t] = kpts[t];
    __syncthreads();

    {
        int p = t >> 5, h = t & 31;
        int idx = nbr[(p0 + p) * HN + h];
        s_nbr[t] = idx;
        float dx, dy, dz;
        bool valid = (unsigned)idx < NPTS;
        if (valid) {
            dx = sp[idx * 3 + 0] - qp[(p0 + p) * 3 + 0];
            dy = sp[idx * 3 + 1] - qp[(p0 + p) * 3 + 1];
            dz = sp[idx * 3 + 2] - qp[(p0 + p) * 3 + 2];
        } else { dx = dy = dz = 1e10f; }
        unsigned m = __ballot_sync(0xffffffffu, valid);
        if ((t & 31) == 0) {
            int nn = __popc(m);
            g_nnr[p0 + p] = 1.0f / (float)(nn > 1 ? nn : 1);
        }
#pragma unroll
        for (int k = 0; k < KP; k++) {
            float ex = dx - s_kp[k * 3 + 0];
            float ey = dy - s_kp[k * 3 + 1];
            float ez = dz - s_kp[k * 3 + 2];
            float dist = sqrtf(ex * ex + ey * ey + ez * ez);
            s_w[t * 16 + k] = fmaxf(1.0f - dist, 0.0f);
        }
        s_w[t * 16 + 15] = 0.f;
    }
    __syncthreads();

    {
        int p = t >> 5;
        int c2 = (t & 31) * 2;
        float a1x = g_a1[c2], a1y = g_a1[c2 + 1];
        float b1x = g_b1v[c2], b1y = g_b1v[c2 + 1];
        ull acc[8][2];
#pragma unroll
        for (int a = 0; a < 8; a++) { acc[a][0] = 0ull; acc[a][1] = 0ull; }
#pragma unroll 4
        for (int h = 0; h < HN; h++) {
            int idx = s_nbr[p * 32 + h];
            float2 f = make_float2(0.f, 0.f);
            if ((unsigned)idx < NPTS) {
                float2 raw = *(const float2*)&g_x1[(size_t)idx * CMID + c2];
                f.x = a1x * raw.x + b1x;
                f.y = a1y * raw.y + b1y;
                f.x = f.x >= 0.f ? f.x : SLOPE * f.x;
                f.y = f.y >= 0.f ? f.y : SLOPE * f.y;
            }
            ull fd0 = dup2(f.x), fd1 = dup2(f.y);
            const ull* w2 = (const ull*)&s_w[(p * 32 + h) * 16];
#pragma unroll
            for (int kp2 = 0; kp2 < 8; kp2++) {
                ull wv = w2[kp2];
                fma2(acc[kp2][0], wv, fd0);
                fma2(acc[kp2][1], wv, fd1);
            }
        }
        int n = p0 + p;
        uint32_t* hiw = (uint32_t*)g_Ahi;
        uint32_t* low = (uint32_t*)g_Alo;
        int base = n * 480 + (c2 >> 1);
#pragma unroll
        for (int kp2 = 0; kp2 < 8; kp2++) {
            float2 a0 = up2(acc[kp2][0]);
            float2 a1 = up2(acc[kp2][1]);
            int k0 = kp2 * 2;
            {
                uint32_t h, l;
                split2(a0.x, a1.x, h, l);
                hiw[base + k0 * 32] = h;
                low[base + k0 * 32] = l;
            }
            if (k0 + 1 < KP) {
                uint32_t h, l;
                split2(a0.y, a1.y, h, l);
                hiw[base + (k0 + 1) * 32] = h;
                low[base + (k0 + 1) * 32] = l;
            }
        }
    }
}

// ---- k_pgemm: WMMA + cp.async double buffering + fused GN2 stats ----
#define PGS 72
#define PG_A(h, b) (sbp + (h) * 18432 + (b) * 9216)
#define PG_B(h, b) (sbp + 36864 + (h) * 9216 + (b) * 4608)
#define PG_SMEM (110592 + 512)

__global__ __launch_bounds__(256, 2) void k_pgemm(const float* __restrict__ kb) {
    extern __shared__ __nv_bfloat16 sbp[];
    float* s_stats = (float*)(sbp + 55296);
    float* sOut = (float*)sbp;

    int t = threadIdx.x;
    int warp = t >> 5;
    int wr = warp >> 1, wc = warp & 1;
    int row0 = blockIdx.x * 128;
    if (t < 128) s_stats[t] = 0.f;

    wmma::fragment<wmma::accumulator, 16, 16, 16, float> acc[2][2];
#pragma unroll
    for (int i = 0; i < 2; i++)
#pragma unroll
        for (int j = 0; j < 2; j++) wmma::fill_fragment(acc[i][j], 0.0f);

    const __nv_bfloat16* Ahi = g_Ahi + (size_t)row0 * 960;
    const __nv_bfloat16* Alo = g_Alo + (size_t)row0 * 960;

    auto fill = [&](int ch, int b) {
#pragma unroll
        for (int i = 0; i < 4; i++) {
            int e = t + i * 256;
            int r = e >> 3, j = e & 7;
            cp16(PG_A(0, b) + r * PGS + j * 8, Ahi + (size_t)r * 960 + ch * 64 + j * 8);
            cp16(PG_A(1, b) + r * PGS + j * 8, Alo + (size_t)r * 960 + ch * 64 + j * 8);
        }
#pragma unroll
        for (int i = 0; i < 2; i++) {
            int e = t + i * 256;
            int r = e >> 3, j = e & 7;
            cp16(PG_B(0, b) + r * PGS + j * 8, g_BhiT + (size_t)r * 960 + ch * 64 + j * 8);
            cp16(PG_B(1, b) + r * PGS + j * 8, g_BloT + (size_t)r * 960 + ch * 64 + j * 8);
        }
    };

    fill(0, 0);
    CP_COMMIT();

    for (int ch = 0; ch < 15; ch++) {
        int buf = ch & 1;
        if (ch < 14) {
            fill(ch + 1, buf ^ 1);
            CP_COMMIT();
            CP_WAIT(1);
        } else {
            CP_WAIT(0);
        }
        __syncthreads();

        __nv_bfloat16* sAhi = PG_A(0, buf);
        __nv_bfloat16* sAlo = PG_A(1, buf);
        __nv_bfloat16* sBhi = PG_B(0, buf);
        __nv_bfloat16* sBlo = PG_B(1, buf);
#pragma unroll
        for (int kk = 0; kk < 4; kk++) {
            wmma::fragment<wmma::matrix_a, 16, 16, 16, __nv_bfloat16, wmma::row_major> a_hi[2], a_lo[2];
            wmma::fragment<wmma::matrix_b, 16, 16, 16, __nv_bfloat16, wmma::col_major> b_hi[2], b_lo[2];
#pragma unroll
            for (int i = 0; i < 2; i++) {
                wmma::load_matrix_sync(a_hi[i], &sAhi[(wr * 32 + i * 16) * PGS + kk * 16], PGS);
                wmma::load_matrix_sync(a_lo[i], &sAlo[(wr * 32 + i * 16) * PGS + kk * 16], PGS);
            }
#pragma unroll
            for (int j = 0; j < 2; j++) {
                wmma::load_matrix_sync(b_hi[j], &sBhi[(wc * 32 + j * 16) * PGS + kk * 16], PGS);
                wmma::load_matrix_sync(b_lo[j], &sBlo[(wc * 32 + j * 16) * PGS + kk * 16], PGS);
            }
#pragma unroll
            for (int i = 0; i < 2; i++)
#pragma unroll
                for (int j = 0; j < 2; j++) {
                    wmma::mma_sync(acc[i][j], a_hi[i], b_hi[j], acc[i][j]);
                    wmma::mma_sync(acc[i][j], a_lo[i], b_hi[j], acc[i][j]);
                    wmma::mma_sync(acc[i][j], a_hi[i], b_lo[j], acc[i][j]);
                }
        }
        __syncthreads();
    }

#pragma unroll
    for (int i = 0; i < 2; i++)
#pragma unroll
        for (int j = 0; j < 2; j++)
            wmma::store_matrix_sync(&sOut[(wr * 32 + i * 16) * PGS + wc * 32 + j * 16],
                                    acc[i][j], PGS, wmma::mem_row_major);
    __syncthreads();

    {
        int c4 = t & 15;
        float b0 = kb[c4 * 4 + 0], b1 = kb[c4 * 4 + 1];
        float b2 = kb[c4 * 4 + 2], b3 = kb[c4 * 4 + 3];
        float cs[4] = {0, 0, 0, 0}, cq[4] = {0, 0, 0, 0};
#pragma unroll
        for (int i = 0; i < 8; i++) {
            int r = (t >> 4) + i * 16;
            float nnr = g_nnr[row0 + r];
            float4 v = *(const float4*)&sOut[r * PGS + c4 * 4];
            v.x = v.x * nnr + b0;
            v.y = v.y * nnr + b1;
            v.z = v.z * nnr + b2;
            v.w = v.w * nnr + b3;
            *(float4*)&g_out2[(size_t)(row0 + r) * CMID + c4 * 4] = v;
            cs[0] += v.x; cq[0] += v.x * v.x;
            cs[1] += v.y; cq[1] += v.y * v.y;
            cs[2] += v.z; cq[2] += v.z * v.z;
            cs[3] += v.w; cq[3] += v.w * v.w;
        }
#pragma unroll
        for (int j = 0; j < 4; j++) {
            atomicAdd(&s_stats[c4 * 4 + j], cs[j]);
            atomicAdd(&s_stats[64 + c4 * 4 + j], cq[j]);
        }
    }
    __syncthreads();
    if (t < 64) {
        atomicAdd(&g_sum2[t], (double)s_stats[t]);
        atomicAdd(&g_sq2[t], (double)s_stats[64 + t]);
    }
}

// ---- GEMM2 (WMMA bf16 hi/lo): y = leaky(GN2(out2)) @ W2 + b2 ; GN3 stats ----
// smem bf16: sAhi 64*72 @0 | sAlo @4608 | sBhi 64*264 @9216 | sBlo @26112 | stats 2KB @86016
#define G2AS 72
#define G2BS 264
#define G2_SMEM (86016 + 2048)

__global__ __launch_bounds__(256) void k_gemm2(const float* __restrict__ W2,
                                               const float* __restrict__ b2) {
    extern __shared__ __nv_bfloat16 sb2[];
    __nv_bfloat16* sAhi = sb2;
    __nv_bfloat16* sAlo = sb2 + 4608;
    __nv_bfloat16* sBhi = sb2 + 9216;
    __nv_bfloat16* sBlo = sb2 + 26112;
    float* s_stats = (float*)((char*)sb2 + 86016);   // 512 floats
    float* sOut = (float*)sb2;                       // 64*264 floats = 67584 B

    int t = threadIdx.x;
    int warp = t >> 5;
    int wr = warp >> 2, wc = warp & 3;   // 2x4 warp grid: rows wr*32..+31, cols wc*64..+63
    int row0 = blockIdx.x * 64;
    s_stats[t] = 0.f; s_stats[t + 256] = 0.f;

    // load A: out2 64x64 -> GN2 affine + leaky -> hi/lo
#pragma unroll
    for (int i = 0; i < 4; i++) {
        int e = t + i * 256;     // 1024 float4 units
        int r = e >> 4, j = e & 15;
        float4 v = *(const float4*)&g_out2[(size_t)(row0 + r) * CMID + j * 4];
        float a0 = g_a2[j * 4 + 0], a1 = g_a2[j * 4 + 1], a2 = g_a2[j * 4 + 2], a3 = g_a2[j * 4 + 3];
        float c0 = g_b2v[j * 4 + 0], c1 = g_b2v[j * 4 + 1], c2 = g_b2v[j * 4 + 2], c3 = g_b2v[j * 4 + 3];
        v.x = a0 * v.x + c0; v.x = v.x >= 0.f ? v.x : SLOPE * v.x;
        v.y = a1 * v.y + c1; v.y = v.y >= 0.f ? v.y : SLOPE * v.y;
        v.z = a2 * v.z + c2; v.z = v.z >= 0.f ? v.z : SLOPE * v.z;
        v.w = a3 * v.w + c3; v.w = v.w >= 0.f ? v.w : SLOPE * v.w;
        uint32_t h0, l0, h1, l1;
        split2(v.x, v.y, h0, l0);
        split2(v.z, v.w, h1, l1);
        *(uint2*)&sAhi[r * G2AS + j * 4] = make_uint2(h0, h1);
        *(uint2*)&sAlo[r * G2AS + j * 4] = make_uint2(l0, l1);
    }
    // load B: W2 64x256 -> hi/lo
#pragma unroll
    for (int i = 0; i < 16; i++) {
        int e = t + i * 256;     // 4096 float4 units
        int r = e >> 6, j = e & 63;
        float4 v = *(const float4*)&W2[(size_t)r * COUT + j * 4];
        uint32_t h0, l0, h1, l1;
        split2(v.x, v.y, h0, l0);
        split2(v.z, v.w, h1, l1);
        *(uint2*)&sBhi[r * G2BS + j * 4] = make_uint2(h0, h1);
        *(uint2*)&sBlo[r * G2BS + j * 4] = make_uint2(l0, l1);
    }
    __syncthreads();

    wmma::fragment<wmma::accumulator, 16, 16, 16, float> acc[2][4];
#pragma unroll
    for (int i = 0; i < 2; i++)
#pragma unroll
        for (int j = 0; j < 4; j++) wmma::fill_fragment(acc[i][j], 0.0f);

#pragma unroll
    for (int kk = 0; kk < 4; kk++) {
        wmma::fragment<wmma::matrix_a, 16, 16, 16, __nv_bfloat16, wmma::row_major> a_hi[2], a_lo[2];
        wmma::fragment<wmma::matrix_b, 16, 16, 16, __nv_bfloat16, wmma::row_major> b_hi[4], b_lo[4];
#pragma unroll
        for (int i = 0; i < 2; i++) {
            wmma::load_matrix_sync(a_hi[i], &sAhi[(wr * 32 + i * 16) * G2AS + kk * 16], G2AS);
            wmma::load_matrix_sync(a_lo[i], &sAlo[(wr * 32 + i * 16) * G2AS + kk * 16], G2AS);
        }
#pragma unroll
        for (int j = 0; j < 4; j++) {
            wmma::load_matrix_sync(b_hi[j], &sBhi[(kk * 16) * G2BS + wc * 64 + j * 16], G2BS);
            wmma::load_matrix_sync(b_lo[j], &sBlo[(kk * 16) * G2BS + wc * 64 + j * 16], G2BS);
        }
#pragma unroll
        for (int i = 0; i < 2; i++)
#pragma unroll
            for (int j = 0; j < 4; j++) {
                wmma::mma_sync(acc[i][j], a_hi[i], b_hi[j], acc[i][j]);
                wmma::mma_sync(acc[i][j], a_lo[i], b_hi[j], acc[i][j]);
                wmma::mma_sync(acc[i][j], a_hi[i], b_lo[j], acc[i][j]);
            }
    }

    __syncthreads();
#pragma unroll
    for (int i = 0; i < 2; i++)
#pragma unroll
        for (int j = 0; j < 4; j++)
            wmma::store_matrix_sync(&sOut[(wr * 32 + i * 16) * G2BS + wc * 64 + j * 16],
                                    acc[i][j], G2BS, wmma::mem_row_major);
    __syncthreads();

    // epilogue: +bias, write y, GN3 stats. thread: c4 = t & 63 fixed, rows (t>>6)+i*4
    {
        int c4 = t & 63;
        float b0 = b2[c4 * 4 + 0], b1 = b2[c4 * 4 + 1];
        float bb2 = b2[c4 * 4 + 2], b3 = b2[c4 * 4 + 3];
        float cs[4] = {0, 0, 0, 0}, cq[4] = {0, 0, 0, 0};
#pragma unroll
        for (int i = 0; i < 16; i++) {
            int r = (t >> 6) + i * 4;
            float4 v = *(const float4*)&sOut[r * G2BS + c4 * 4];
            v.x += b0; v.y += b1; v.z += bb2; v.w += b3;
            *(float4*)&g_y[(size_t)(row0 + r) * COUT + c4 * 4] = v;
            cs[0] += v.x; cq[0] += v.x * v.x;
            cs[1] += v.y; cq[1] += v.y * v.y;
            cs[2] += v.z; cq[2] += v.z * v.z;
            cs[3] += v.w; cq[3] += v.w * v.w;
        }
#pragma unroll
        for (int j = 0; j < 4; j++) {
            atomicAdd(&s_stats[c4 * 4 + j], cs[j]);
            atomicAdd(&s_stats[256 + c4 * 4 + j], cq[j]);
        }
    }
    __syncthreads();
    atomicAdd(&g_sum3[t], (double)s_stats[t]);
    atomicAdd(&g_sq3[t], (double)s_stats[256 + t]);
}

// ---- final: out = leaky(GN3(y) + s_feats), MLP-8 version ----
__global__ __launch_bounds__(256) void k_final(const float* __restrict__ sf,
                                               float* __restrict__ out) {
    int base = blockIdx.x * 1024 + threadIdx.x;   // 4 float4s per thread, stride 256
    int c = (base & 63) * 4;                      // constant across the 4 (stride%64==0)
    float a0 = g_a3[c + 0], a1 = g_a3[c + 1], a2 = g_a3[c + 2], a3 = g_a3[c + 3];
    float b0 = g_b3v[c + 0], b1 = g_b3v[c + 1], b2 = g_b3v[c + 2], b3 = g_b3v[c + 3];
    float4 y[4], s[4];
#pragma unroll
    for (int u = 0; u < 4; u++) {
        y[u] = ((const float4*)g_y)[base + u * 256];
        s[u] = ((const float4*)sf)[base + u * 256];
    }
#pragma unroll
    for (int u = 0; u < 4; u++) {
        float4 r;
        r.x = a0 * y[u].x + b0 + s[u].x;
        r.y = a1 * y[u].y + b1 + s[u].y;
        r.z = a2 * y[u].z + b2 + s[u].z;
        r.w = a3 * y[u].w + b3 + s[u].w;
        r.x = r.x >= 0.f ? r.x : SLOPE * r.x;
        r.y = r.y >= 0.f ? r.y : SLOPE * r.y;
        r.z = r.z >= 0.f ? r.z : SLOPE * r.z;
        r.w = r.w >= 0.f ? r.w : SLOPE * r.w;
        ((float4*)out)[base + u * 256] = r;
    }
}

extern "C" void kernel_launch(void* const* d_in, const int* in_sizes, int n_in,
                              void* d_out, int out_size) {
    const float* s_feats  = (const float*)d_in[0];
    const float* q_points = (const float*)d_in[1];
    const float* s_points = (const float*)d_in[2];
    const int*   nbr      = (const int*)d_in[3];
    const float* W1       = (const float*)d_in[4];
    const float* b1       = (const float*)d_in[5];
    const float* g1       = (const float*)d_in[6];
    const float* beta1    = (const float*)d_in[7];
    const float* kpw      = (const float*)d_in[8];
    const float* kpb      = (const float*)d_in[9];
    const float* kpts     = (const float*)d_in[10];
    const float* gg       = (const float*)d_in[11];
    const float* gb       = (const float*)d_in[12];
    const float* W2       = (const float*)d_in[13];
    const float* b2       = (const float*)d_in[14];
    const float* g2       = (const float*)d_in[15];
    const float* beta2    = (const float*)d_in[16];
    float* out = (float*)d_out;

    cudaFuncSetAttribute(k_gemm1, cudaFuncAttributeMaxDynamicSharedMemorySize, G1_SMEM);
    cudaFuncSetAttribute(k_pgemm, cudaFuncAttributeMaxDynamicSharedMemorySize, PG_SMEM);
    cudaFuncSetAttribute(k_gemm2, cudaFuncAttributeMaxDynamicSharedMemorySize, G2_SMEM);

    k_prep<<<240, 256>>>(kpw);
    k_gemm1<<<NPTS / 128, 256, G1_SMEM>>>(s_feats, W1, b1);
    k_finalize<<<1, 256>>>(0, g1, beta1);
    k_gather<<<NPTS / 8, 256>>>(q_points, s_points, nbr, kpts);
    k_pgemm<<<NPTS / 128, 256, PG_SMEM>>>(kpb);
    k_finalize<<<1, 256>>>(1, gg, gb);
    k_gemm2<<<NPTS / 64, 256, G2_SMEM>>>(W2, b2);
    k_finalize<<<1, 256>>>(2, g2, beta2);
    k_final<<<NPTS * COUT / 4 / 1024, 256>>>(s_feats, out);
}

// round 12
// speedup vs baseline: 2.5103x; 1.0504x over previous
#include <cuda_runtime.h>
#include <cuda_bf16.h>
#include <mma.h>
#include <cstdint>

#define NPTS 65536
#define HN 32
#define CIN 256
#define CMID 64
#define COUT 256
#define KP 15
#define SLOPE 0.1f
#define EPSV 1e-5f

using ull = unsigned long long;
using namespace nvcuda;

// ---- packed f32x2 helpers ----
__device__ __forceinline__ ull pk2(float lo, float hi) {
    ull r; asm("mov.b64 %0, {%1,%2};" : "=l"(r) : "f"(lo), "f"(hi)); return r;
}
__device__ __forceinline__ ull dup2(float v) { return pk2(v, v); }
__device__ __forceinline__ void fma2(ull& d, ull a, ull b) {
    asm("fma.rn.f32x2 %0, %1, %2, %3;" : "=l"(d) : "l"(a), "l"(b), "l"(d));
}
__device__ __forceinline__ float2 up2(ull v) {
    float lo, hi; asm("mov.b64 {%0,%1}, %2;" : "=f"(lo), "=f"(hi) : "l"(v));
    return make_float2(lo, hi);
}

// ---- cp.async helpers ----
__device__ __forceinline__ void cp16(void* sdst, const void* gsrc) {
    uint32_t s = (uint32_t)__cvta_generic_to_shared(sdst);
    asm volatile("cp.async.cg.shared.global [%0], [%1], 16;" :: "r"(s), "l"(gsrc));
}
#define CP_COMMIT() asm volatile("cp.async.commit_group;" ::: "memory")
#define CP_WAIT(n)  asm volatile("cp.async.wait_group %0;" :: "n"(n) : "memory")

// ---- hi/lo split helper ----
__device__ __forceinline__ void split2(float x, float y, uint32_t& h, uint32_t& l) {
    __nv_bfloat162 hh = __floats2bfloat162_rn(x, y);
    __nv_bfloat162 ll = __floats2bfloat162_rn(x - __bfloat162float(hh.x),
                                              y - __bfloat162float(hh.y));
    h = *(uint32_t*)&hh;
    l = *(uint32_t*)&ll;
}

// ---- scratch (device globals; aligned for vector-cast access) ----
__device__ __align__(256) float g_x1[NPTS * CMID];            // 16 MB (raw, pre-GN1)
__device__ __align__(256) float g_out2[NPTS * CMID];          // 16 MB
__device__ __align__(256) float g_y[NPTS * COUT];             // 64 MB
__device__ __align__(256) __nv_bfloat16 g_Ahi[NPTS * 960];    // 126 MB
__device__ __align__(256) __nv_bfloat16 g_Alo[NPTS * 960];    // 126 MB
__device__ __align__(256) __nv_bfloat16 g_BhiT[64 * 960];
__device__ __align__(256) __nv_bfloat16 g_BloT[64 * 960];
__device__ float g_nnr[NPTS];
__device__ double g_sum1[CMID], g_sq1[CMID];
__device__ double g_sum2[CMID], g_sq2[CMID];
__device__ double g_sum3[COUT], g_sq3[COUT];
__device__ float g_a1[CMID], g_b1v[CMID];
__device__ float g_a2[CMID], g_b2v[CMID];
__device__ float g_a3[COUT], g_b3v[COUT];

// ---- k_prep: zero stats (block 0) + kw transpose/split ----
__global__ __launch_bounds__(256) void k_prep(const float* __restrict__ kw) {
    int t = threadIdx.x;
    if (blockIdx.x == 0) {
        if (t < CMID) { g_sum1[t] = 0.0; g_sq1[t] = 0.0; g_sum2[t] = 0.0; g_sq2[t] = 0.0; }
        if (t < COUT) { g_sum3[t] = 0.0; g_sq3[t] = 0.0; }
    }
    int idx = blockIdx.x * 256 + t;      // 61440 = 240*256 exactly
    int d = idx / 960;
    int r = idx % 960;
    float v = kw[r * 64 + d];
    __nv_bfloat16 h = __float2bfloat16(v);
    g_BhiT[d * 960 + r] = h;
    g_BloT[d * 960 + r] = __float2bfloat16(v - __bfloat162float(h));
}

// ---- GEMM1 (WMMA bf16 hi/lo): x1 = s_feats @ W1 + b1 ; GN1 stats ----
#define G1S 72
#define G1_SMEM (55296 + 512)

__global__ __launch_bounds__(256) void k_gemm1(const float* __restrict__ A,
                                               const float* __restrict__ W,
                                               const float* __restrict__ bias) {
    extern __shared__ __nv_bfloat16 sb1[];
    __nv_bfloat16* sAhi = sb1;
    __nv_bfloat16* sAlo = sb1 + 9216;
    __nv_bfloat16* sBhi = sb1 + 18432;
    __nv_bfloat16* sBlo = sb1 + 23040;
    float* s_stats = (float*)(sb1 + 27648);
    float* sOut = (float*)sb1;

    int t = threadIdx.x;
    int warp = t >> 5;
    int wr = warp >> 1, wc = warp & 1;
    int row0 = blockIdx.x * 128;
    if (t < 128) s_stats[t] = 0.f;

    wmma::fragment<wmma::accumulator, 16, 16, 16, float> acc[2][2];
#pragma unroll
    for (int i = 0; i < 2; i++)
#pragma unroll
        for (int j = 0; j < 2; j++) wmma::fill_fragment(acc[i][j], 0.0f);

    for (int ch = 0; ch < 4; ch++) {
        __syncthreads();
#pragma unroll
        for (int i = 0; i < 8; i++) {
            int e = t + i * 256;
            int r = e >> 4, j = e & 15;
            float4 v = *(const float4*)&A[(size_t)(row0 + r) * CIN + ch * 64 + j * 4];
            uint32_t h0, l0, h1, l1;
            split2(v.x, v.y, h0, l0);
            split2(v.z, v.w, h1, l1);
            *(uint2*)&sAhi[r * G1S + j * 4] = make_uint2(h0, h1);
            *(uint2*)&sAlo[r * G1S + j * 4] = make_uint2(l0, l1);
        }
#pragma unroll
        for (int i = 0; i < 4; i++) {
            int e = t + i * 256;
            int r = e >> 4, j = e & 15;
            float4 v = *(const float4*)&W[(size_t)(ch * 64 + r) * CMID + j * 4];
            uint32_t h0, l0, h1, l1;
            split2(v.x, v.y, h0, l0);
            split2(v.z, v.w, h1, l1);
            *(uint2*)&sBhi[r * G1S + j * 4] = make_uint2(h0, h1);
            *(uint2*)&sBlo[r * G1S + j * 4] = make_uint2(l0, l1);
        }
        __syncthreads();

#pragma unroll
        for (int kk = 0; kk < 4; kk++) {
            wmma::fragment<wmma::matrix_a, 16, 16, 16, __nv_bfloat16, wmma::row_major> a_hi[2], a_lo[2];
            wmma::fragment<wmma::matrix_b, 16, 16, 16, __nv_bfloat16, wmma::row_major> b_hi[2], b_lo[2];
#pragma unroll
            for (int i = 0; i < 2; i++) {
                wmma::load_matrix_sync(a_hi[i], &sAhi[(wr * 32 + i * 16) * G1S + kk * 16], G1S);
                wmma::load_matrix_sync(a_lo[i], &sAlo[(wr * 32 + i * 16) * G1S + kk * 16], G1S);
            }
#pragma unroll
            for (int j = 0; j < 2; j++) {
                wmma::load_matrix_sync(b_hi[j], &sBhi[(kk * 16) * G1S + wc * 32 + j * 16], G1S);
                wmma::load_matrix_sync(b_lo[j], &sBlo[(kk * 16) * G1S + wc * 32 + j * 16], G1S);
            }
#pragma unroll
            for (int i = 0; i < 2; i++)
#pragma unroll
                for (int j = 0; j < 2; j++) {
                    wmma::mma_sync(acc[i][j], a_hi[i], b_hi[j], acc[i][j]);
                    wmma::mma_sync(acc[i][j], a_lo[i], b_hi[j], acc[i][j]);
                    wmma::mma_sync(acc[i][j], a_hi[i], b_lo[j], acc[i][j]);
                }
        }
    }

    __syncthreads();
#pragma unroll
    for (int i = 0; i < 2; i++)
#pragma unroll
        for (int j = 0; j < 2; j++)
            wmma::store_matrix_sync(&sOut[(wr * 32 + i * 16) * G1S + wc * 32 + j * 16],
                                    acc[i][j], G1S, wmma::mem_row_major);
    __syncthreads();

    {
        int c4 = t & 15;
        float b0 = bias[c4 * 4 + 0], b1 = bias[c4 * 4 + 1];
        float b2 = bias[c4 * 4 + 2], b3 = bias[c4 * 4 + 3];
        float cs[4] = {0, 0, 0, 0}, cq[4] = {0, 0, 0, 0};
#pragma unroll
        for (int i = 0; i < 8; i++) {
            int r = (t >> 4) + i * 16;
            float4 v = *(const float4*)&sOut[r * G1S + c4 * 4];
            v.x += b0; v.y += b1; v.z += b2; v.w += b3;
            *(float4*)&g_x1[(size_t)(row0 + r) * CMID + c4 * 4] = v;
            cs[0] += v.x; cq[0] += v.x * v.x;
            cs[1] += v.y; cq[1] += v.y * v.y;
            cs[2] += v.z; cq[2] += v.z * v.z;
            cs[3] += v.w; cq[3] += v.w * v.w;
        }
#pragma unroll
        for (int j = 0; j < 4; j++) {
            atomicAdd(&s_stats[c4 * 4 + j], cs[j]);
            atomicAdd(&s_stats[64 + c4 * 4 + j], cq[j]);
        }
    }
    __syncthreads();
    if (t < 64) {
        atomicAdd(&g_sum1[t], (double)s_stats[t]);
        atomicAdd(&g_sq1[t], (double)s_stats[64 + t]);
    }
}

// ---- finalize GN stats ----
__global__ void k_finalize(int stage, const float* __restrict__ gamma,
                           const float* __restrict__ beta) {
    int c = threadIdx.x;
    if (stage < 2) {
        if (c >= CMID) return;
        const double* sum = (stage == 0) ? g_sum1 : g_sum2;
        const double* sq  = (stage == 0) ? g_sq1  : g_sq2;
        float* a = (stage == 0) ? g_a1 : g_a2;
        float* b = (stage == 0) ? g_b1v : g_b2v;
        int g = c >> 1;
        double s = sum[g * 2] + sum[g * 2 + 1];
        double q = sq[g * 2] + sq[g * 2 + 1];
        double cnt = 2.0 * (double)NPTS;
        double mean = s / cnt;
        double var = q / cnt - mean * mean;
        float inv = rsqrtf((float)var + EPSV);
        float av = gamma[c] * inv;
        a[c] = av;
        b[c] = beta[c] - (float)mean * av;
    } else {
        if (c >= COUT) return;
        int g = c >> 3;
        double s = 0.0, q = 0.0;
#pragma unroll
        for (int i = 0; i < 8; i++) { s += g_sum3[g * 8 + i]; q += g_sq3[g * 8 + i]; }
        double cnt = 8.0 * (double)NPTS;
        double mean = s / cnt;
        double var = q / cnt - mean * mean;
        float inv = rsqrtf((float)var + EPSV);
        float av = gamma[c] * inv;
        g_a3[c] = av;
        g_b3v[c] = beta[c] - (float)mean * av;
    }
}

// ---- k_gather: KPConv phases 1+2, GN1+leaky fused, LDS.128 weight loads ----
__global__ __launch_bounds__(256, 3) void k_gather(
        const float* __restrict__ qp, const float* __restrict__ sp,
        const int* __restrict__ nbr, const float* __restrict__ kpts) {
    __shared__ float s_kp[48];
    __shared__ __align__(16) float s_w[8 * 32 * 16];
    __shared__ int s_off[256];     // precomputed x1 row offsets (idx*CMID), -1 if shadow

    int t = threadIdx.x;
    int p0 = blockIdx.x * 8;

    if (t < 45) s_kp[t] = kpts[t];
    __syncthreads();

    // phase 1: warp == point; also precompute gather offsets
    {
        int p = t >> 5, h = t & 31;
        int idx = nbr[(p0 + p) * HN + h];
        bool valid = (unsigned)idx < NPTS;
        s_off[t] = valid ? idx * CMID : -1;
        float dx, dy, dz;
        if (valid) {
            dx = sp[idx * 3 + 0] - qp[(p0 + p) * 3 + 0];
            dy = sp[idx * 3 + 1] - qp[(p0 + p) * 3 + 1];
            dz = sp[idx * 3 + 2] - qp[(p0 + p) * 3 + 2];
        } else { dx = dy = dz = 1e10f; }
        unsigned m = __ballot_sync(0xffffffffu, valid);
        if ((t & 31) == 0) {
            int nn = __popc(m);
            g_nnr[p0 + p] = 1.0f / (float)(nn > 1 ? nn : 1);
        }
#pragma unroll
        for (int k = 0; k < KP; k++) {
            float ex = dx - s_kp[k * 3 + 0];
            float ey = dy - s_kp[k * 3 + 1];
            float ez = dz - s_kp[k * 3 + 2];
            float dist = sqrtf(ex * ex + ey * ey + ez * ez);
            s_w[t * 16 + k] = fmaxf(1.0f - dist, 0.0f);
        }
        s_w[t * 16 + 15] = 0.f;
    }
    __syncthreads();

    // phase 2: thread = (p, 2 channels); weights via 4x LDS.128
    {
        int p = t >> 5;
        int c2 = (t & 31) * 2;
        float a1x = g_a1[c2], a1y = g_a1[c2 + 1];
        float b1x = g_b1v[c2], b1y = g_b1v[c2 + 1];
        ull acc[8][2];
#pragma unroll
        for (int a = 0; a < 8; a++) { acc[a][0] = 0ull; acc[a][1] = 0ull; }
#pragma unroll 4
        for (int h = 0; h < HN; h++) {
            int off = s_off[p * 32 + h];
            float2 f = make_float2(0.f, 0.f);
            if (off >= 0) {
                float2 raw = *(const float2*)&g_x1[(size_t)off + c2];
                f.x = a1x * raw.x + b1x;
                f.y = a1y * raw.y + b1y;
                f.x = f.x >= 0.f ? f.x : SLOPE * f.x;
                f.y = f.y >= 0.f ? f.y : SLOPE * f.y;
            }
            ull fd0 = dup2(f.x), fd1 = dup2(f.y);
            const ulonglong2* w4 = (const ulonglong2*)&s_w[(p * 32 + h) * 16];
            ulonglong2 wa = w4[0], wb = w4[1], wcc = w4[2], wd = w4[3];
            fma2(acc[0][0], wa.x, fd0);  fma2(acc[0][1], wa.x, fd1);
            fma2(acc[1][0], wa.y, fd0);  fma2(acc[1][1], wa.y, fd1);
            fma2(acc[2][0], wb.x, fd0);  fma2(acc[2][1], wb.x, fd1);
            fma2(acc[3][0], wb.y, fd0);  fma2(acc[3][1], wb.y, fd1);
            fma2(acc[4][0], wcc.x, fd0); fma2(acc[4][1], wcc.x, fd1);
            fma2(acc[5][0], wcc.y, fd0); fma2(acc[5][1], wcc.y, fd1);
            fma2(acc[6][0], wd.x, fd0);  fma2(acc[6][1], wd.x, fd1);
            fma2(acc[7][0], wd.y, fd0);  fma2(acc[7][1], wd.y, fd1);
        }
        int n = p0 + p;
        uint32_t* hiw = (uint32_t*)g_Ahi;
        uint32_t* low = (uint32_t*)g_Alo;
        int base = n * 480 + (c2 >> 1);
#pragma unroll
        for (int kp2 = 0; kp2 < 8; kp2++) {
            float2 a0 = up2(acc[kp2][0]);
            float2 a1 = up2(acc[kp2][1]);
            int k0 = kp2 * 2;
            {
                uint32_t h, l;
                split2(a0.x, a1.x, h, l);
                hiw[base + k0 * 32] = h;
                low[base + k0 * 32] = l;
            }
            if (k0 + 1 < KP) {
                uint32_t h, l;
                split2(a0.y, a1.y, h, l);
                hiw[base + (k0 + 1) * 32] = h;
                low[base + (k0 + 1) * 32] = l;
            }
        }
    }
}

// ---- k_pgemm: WMMA + cp.async double buffering + fused GN2 stats ----
#define PGS 72
#define PG_A(h, b) (sbp + (h) * 18432 + (b) * 9216)
#define PG_B(h, b) (sbp + 36864 + (h) * 9216 + (b) * 4608)
#define PG_SMEM (110592 + 512)

__global__ __launch_bounds__(256, 2) void k_pgemm(const float* __restrict__ kb) {
    extern __shared__ __nv_bfloat16 sbp[];
    float* s_stats = (float*)(sbp + 55296);
    float* sOut = (float*)sbp;

    int t = threadIdx.x;
    int warp = t >> 5;
    int wr = warp >> 1, wc = warp & 1;
    int row0 = blockIdx.x * 128;
    if (t < 128) s_stats[t] = 0.f;

    wmma::fragment<wmma::accumulator, 16, 16, 16, float> acc[2][2];
#pragma unroll
    for (int i = 0; i < 2; i++)
#pragma unroll
        for (int j = 0; j < 2; j++) wmma::fill_fragment(acc[i][j], 0.0f);

    const __nv_bfloat16* Ahi = g_Ahi + (size_t)row0 * 960;
    const __nv_bfloat16* Alo = g_Alo + (size_t)row0 * 960;

    auto fill = [&](int ch, int b) {
#pragma unroll
        for (int i = 0; i < 4; i++) {
            int e = t + i * 256;
            int r = e >> 3, j = e & 7;
            cp16(PG_A(0, b) + r * PGS + j * 8, Ahi + (size_t)r * 960 + ch * 64 + j * 8);
            cp16(PG_A(1, b) + r * PGS + j * 8, Alo + (size_t)r * 960 + ch * 64 + j * 8);
        }
#pragma unroll
        for (int i = 0; i < 2; i++) {
            int e = t + i * 256;
            int r = e >> 3, j = e & 7;
            cp16(PG_B(0, b) + r * PGS + j * 8, g_BhiT + (size_t)r * 960 + ch * 64 + j * 8);
            cp16(PG_B(1, b) + r * PGS + j * 8, g_BloT + (size_t)r * 960 + ch * 64 + j * 8);
        }
    };

    fill(0, 0);
    CP_COMMIT();

    for (int ch = 0; ch < 15; ch++) {
        int buf = ch & 1;
        if (ch < 14) {
            fill(ch + 1, buf ^ 1);
            CP_COMMIT();
            CP_WAIT(1);
        } else {
            CP_WAIT(0);
        }
        __syncthreads();

        __nv_bfloat16* sAhi = PG_A(0, buf);
        __nv_bfloat16* sAlo = PG_A(1, buf);
        __nv_bfloat16* sBhi = PG_B(0, buf);
        __nv_bfloat16* sBlo = PG_B(1, buf);
#pragma unroll
        for (int kk = 0; kk < 4; kk++) {
            wmma::fragment<wmma::matrix_a, 16, 16, 16, __nv_bfloat16, wmma::row_major> a_hi[2], a_lo[2];
            wmma::fragment<wmma::matrix_b, 16, 16, 16, __nv_bfloat16, wmma::col_major> b_hi[2], b_lo[2];
#pragma unroll
            for (int i = 0; i < 2; i++) {
                wmma::load_matrix_sync(a_hi[i], &sAhi[(wr * 32 + i * 16) * PGS + kk * 16], PGS);
                wmma::load_matrix_sync(a_lo[i], &sAlo[(wr * 32 + i * 16) * PGS + kk * 16], PGS);
            }
#pragma unroll
            for (int j = 0; j < 2; j++) {
                wmma::load_matrix_sync(b_hi[j], &sBhi[(wc * 32 + j * 16) * PGS + kk * 16], PGS);
                wmma::load_matrix_sync(b_lo[j], &sBlo[(wc * 32 + j * 16) * PGS + kk * 16], PGS);
            }
#pragma unroll
            for (int i = 0; i < 2; i++)
#pragma unroll
                for (int j = 0; j < 2; j++) {
                    wmma::mma_sync(acc[i][j], a_hi[i], b_hi[j], acc[i][j]);
                    wmma::mma_sync(acc[i][j], a_lo[i], b_hi[j], acc[i][j]);
                    wmma::mma_sync(acc[i][j], a_hi[i], b_lo[j], acc[i][j]);
                }
        }
        __syncthreads();
    }

#pragma unroll
    for (int i = 0; i < 2; i++)
#pragma unroll
        for (int j = 0; j < 2; j++)
            wmma::store_matrix_sync(&sOut[(wr * 32 + i * 16) * PGS + wc * 32 + j * 16],
                                    acc[i][j], PGS, wmma::mem_row_major);
    __syncthreads();

    {
        int c4 = t & 15;
        float b0 = kb[c4 * 4 + 0], b1 = kb[c4 * 4 + 1];
        float b2 = kb[c4 * 4 + 2], b3 = kb[c4 * 4 + 3];
        float cs[4] = {0, 0, 0, 0}, cq[4] = {0, 0, 0, 0};
#pragma unroll
        for (int i = 0; i < 8; i++) {
            int r = (t >> 4) + i * 16;
            float nnr = g_nnr[row0 + r];
            float4 v = *(const float4*)&sOut[r * PGS + c4 * 4];
            v.x = v.x * nnr + b0;
            v.y = v.y * nnr + b1;
            v.z = v.z * nnr + b2;
            v.w = v.w * nnr + b3;
            *(float4*)&g_out2[(size_t)(row0 + r) * CMID + c4 * 4] = v;
            cs[0] += v.x; cq[0] += v.x * v.x;
            cs[1] += v.y; cq[1] += v.y * v.y;
            cs[2] += v.z; cq[2] += v.z * v.z;
            cs[3] += v.w; cq[3] += v.w * v.w;
        }
#pragma unroll
        for (int j = 0; j < 4; j++) {
            atomicAdd(&s_stats[c4 * 4 + j], cs[j]);
            atomicAdd(&s_stats[64 + c4 * 4 + j], cq[j]);
        }
    }
    __syncthreads();
    if (t < 64) {
        atomicAdd(&g_sum2[t], (double)s_stats[t]);
        atomicAdd(&g_sq2[t], (double)s_stats[64 + t]);
    }
}

// ---- GEMM2 (WMMA bf16 hi/lo): y = leaky(GN2(out2)) @ W2 + b2 ; GN3 stats ----
#define G2AS 72
#define G2BS 264
#define G2_SMEM (86016 + 2048)

__global__ __launch_bounds__(256) void k_gemm2(const float* __restrict__ W2,
                                               const float* __restrict__ b2) {
    extern __shared__ __nv_bfloat16 sb2[];
    __nv_bfloat16* sAhi = sb2;
    __nv_bfloat16* sAlo = sb2 + 4608;
    __nv_bfloat16* sBhi = sb2 + 9216;
    __nv_bfloat16* sBlo = sb2 + 26112;
    float* s_stats = (float*)((char*)sb2 + 86016);
    float* sOut = (float*)sb2;

    int t = threadIdx.x;
    int warp = t >> 5;
    int wr = warp >> 2, wc = warp & 3;
    int row0 = blockIdx.x * 64;
    s_stats[t] = 0.f; s_stats[t + 256] = 0.f;

#pragma unroll
    for (int i = 0; i < 4; i++) {
        int e = t + i * 256;
        int r = e >> 4, j = e & 15;
        float4 v = *(const float4*)&g_out2[(size_t)(row0 + r) * CMID + j * 4];
        float a0 = g_a2[j * 4 + 0], a1 = g_a2[j * 4 + 1], a2 = g_a2[j * 4 + 2], a3 = g_a2[j * 4 + 3];
        float c0 = g_b2v[j * 4 + 0], c1 = g_b2v[j * 4 + 1], c2 = g_b2v[j * 4 + 2], c3 = g_b2v[j * 4 + 3];
        v.x = a0 * v.x + c0; v.x = v.x >= 0.f ? v.x : SLOPE * v.x;
        v.y = a1 * v.y + c1; v.y = v.y >= 0.f ? v.y : SLOPE * v.y;
        v.z = a2 * v.z + c2; v.z = v.z >= 0.f ? v.z : SLOPE * v.z;
        v.w = a3 * v.w + c3; v.w = v.w >= 0.f ? v.w : SLOPE * v.w;
        uint32_t h0, l0, h1, l1;
        split2(v.x, v.y, h0, l0);
        split2(v.z, v.w, h1, l1);
        *(uint2*)&sAhi[r * G2AS + j * 4] = make_uint2(h0, h1);
        *(uint2*)&sAlo[r * G2AS + j * 4] = make_uint2(l0, l1);
    }
#pragma unroll
    for (int i = 0; i < 16; i++) {
        int e = t + i * 256;
        int r = e >> 6, j = e & 63;
        float4 v = *(const float4*)&W2[(size_t)r * COUT + j * 4];
        uint32_t h0, l0, h1, l1;
        split2(v.x, v.y, h0, l0);
        split2(v.z, v.w, h1, l1);
        *(uint2*)&sBhi[r * G2BS + j * 4] = make_uint2(h0, h1);
        *(uint2*)&sBlo[r * G2BS + j * 4] = make_uint2(l0, l1);
    }
    __syncthreads();

    wmma::fragment<wmma::accumulator, 16, 16, 16, float> acc[2][4];
#pragma unroll
    for (int i = 0; i < 2; i++)
#pragma unroll
        for (int j = 0; j < 4; j++) wmma::fill_fragment(acc[i][j], 0.0f);

#pragma unroll
    for (int kk = 0; kk < 4; kk++) {
        wmma::fragment<wmma::matrix_a, 16, 16, 16, __nv_bfloat16, wmma::row_major> a_hi[2], a_lo[2];
        wmma::fragment<wmma::matrix_b, 16, 16, 16, __nv_bfloat16, wmma::row_major> b_hi[4], b_lo[4];
#pragma unroll
        for (int i = 0; i < 2; i++) {
            wmma::load_matrix_sync(a_hi[i], &sAhi[(wr * 32 + i * 16) * G2AS + kk * 16], G2AS);
            wmma::load_matrix_sync(a_lo[i], &sAlo[(wr * 32 + i * 16) * G2AS + kk * 16], G2AS);
        }
#pragma unroll
        for (int j = 0; j < 4; j++) {
            wmma::load_matrix_sync(b_hi[j], &sBhi[(kk * 16) * G2BS + wc * 64 + j * 16], G2BS);
            wmma::load_matrix_sync(b_lo[j], &sBlo[(kk * 16) * G2BS + wc * 64 + j * 16], G2BS);
        }
#pragma unroll
        for (int i = 0; i < 2; i++)
#pragma unroll
            for (int j = 0; j < 4; j++) {
                wmma::mma_sync(acc[i][j], a_hi[i], b_hi[j], acc[i][j]);
                wmma::mma_sync(acc[i][j], a_lo[i], b_hi[j], acc[i][j]);
                wmma::mma_sync(acc[i][j], a_hi[i], b_lo[j], acc[i][j]);
            }
    }

    __syncthreads();
#pragma unroll
    for (int i = 0; i < 2; i++)
#pragma unroll
        for (int j = 0; j < 4; j++)
            wmma::store_matrix_sync(&sOut[(wr * 32 + i * 16) * G2BS + wc * 64 + j * 16],
                                    acc[i][j], G2BS, wmma::mem_row_major);
    __syncthreads();

    {
        int c4 = t & 63;
        float b0 = b2[c4 * 4 + 0], b1 = b2[c4 * 4 + 1];
        float bb2 = b2[c4 * 4 + 2], b3 = b2[c4 * 4 + 3];
        float cs[4] = {0, 0, 0, 0}, cq[4] = {0, 0, 0, 0};
#pragma unroll
        for (int i = 0; i < 16; i++) {
            int r = (t >> 6) + i * 4;
            float4 v = *(const float4*)&sOut[r * G2BS + c4 * 4];
            v.x += b0; v.y += b1; v.z += bb2; v.w += b3;
            *(float4*)&g_y[(size_t)(row0 + r) * COUT + c4 * 4] = v;
            cs[0] += v.x; cq[0] += v.x * v.x;
            cs[1] += v.y; cq[1] += v.y * v.y;
            cs[2] += v.z; cq[2] += v.z * v.z;
            cs[3] += v.w; cq[3] += v.w * v.w;
        }
#pragma unroll
        for (int j = 0; j < 4; j++) {
            atomicAdd(&s_stats[c4 * 4 + j], cs[j]);
            atomicAdd(&s_stats[256 + c4 * 4 + j], cq[j]);
        }
    }
    __syncthreads();
    atomicAdd(&g_sum3[t], (double)s_stats[t]);
    atomicAdd(&g_sq3[t], (double)s_stats[256 + t]);
}

// ---- final: out = leaky(GN3(y) + s_feats), MLP-8 ----
__global__ __launch_bounds__(256) void k_final(const float* __restrict__ sf,
                                               float* __restrict__ out) {
    int base = blockIdx.x * 1024 + threadIdx.x;
    int c = (base & 63) * 4;
    float a0 = g_a3[c + 0], a1 = g_a3[c + 1], a2 = g_a3[c + 2], a3 = g_a3[c + 3];
    float b0 = g_b3v[c + 0], b1 = g_b3v[c + 1], b2 = g_b3v[c + 2], b3 = g_b3v[c + 3];
    float4 y[4], s[4];
#pragma unroll
    for (int u = 0; u < 4; u++) {
        y[u] = ((const float4*)g_y)[base + u * 256];
        s[u] = ((const float4*)sf)[base + u * 256];
    }
#pragma unroll
    for (int u = 0; u < 4; u++) {
        float4 r;
        r.x = a0 * y[u].x + b0 + s[u].x;
        r.y = a1 * y[u].y + b1 + s[u].y;
        r.z = a2 * y[u].z + b2 + s[u].z;
        r.w = a3 * y[u].w + b3 + s[u].w;
        r.x = r.x >= 0.f ? r.x : SLOPE * r.x;
        r.y = r.y >= 0.f ? r.y : SLOPE * r.y;
        r.z = r.z >= 0.f ? r.z : SLOPE * r.z;
        r.w = r.w >= 0.f ? r.w : SLOPE * r.w;
        ((float4*)out)[base + u * 256] = r;
    }
}

extern "C" void kernel_launch(void* const* d_in, const int* in_sizes, int n_in,
                              void* d_out, int out_size) {
    const float* s_feats  = (const float*)d_in[0];
    const float* q_points = (const float*)d_in[1];
    const float* s_points = (const float*)d_in[2];
    const int*   nbr      = (const int*)d_in[3];
    const float* W1       = (const float*)d_in[4];
    const float* b1       = (const float*)d_in[5];
    const float* g1       = (const float*)d_in[6];
    const float* beta1    = (const float*)d_in[7];
    const float* kpw      = (const float*)d_in[8];
    const float* kpb      = (const float*)d_in[9];
    const float* kpts     = (const float*)d_in[10];
    const float* gg       = (const float*)d_in[11];
    const float* gb       = (const float*)d_in[12];
    const float* W2       = (const float*)d_in[13];
    const float* b2       = (const float*)d_in[14];
    const float* g2       = (const float*)d_in[15];
    const float* beta2    = (const float*)d_in[16];
    float* out = (float*)d_out;

    cudaFuncSetAttribute(k_gemm1, cudaFuncAttributeMaxDynamicSharedMemorySize, G1_SMEM);
    cudaFuncSetAttribute(k_pgemm, cudaFuncAttributeMaxDynamicSharedMemorySize, PG_SMEM);
    cudaFuncSetAttribute(k_gemm2, cudaFuncAttributeMaxDynamicSharedMemorySize, G2_SMEM);

    k_prep<<<240, 256>>>(kpw);
    k_gemm1<<<NPTS / 128, 256, G1_SMEM>>>(s_feats, W1, b1);
    k_finalize<<<1, 256>>>(0, g1, beta1);
    k_gather<<<NPTS / 8, 256>>>(q_points, s_points, nbr, kpts);
    k_pgemm<<<NPTS / 128, 256, PG_SMEM>>>(kpb);
    k_finalize<<<1, 256>>>(1, gg, gb);
    k_gemm2<<<NPTS / 64, 256, G2_SMEM>>>(W2, b2);
    k_finalize<<<1, 256>>>(2, g2, beta2);
    k_final<<<NPTS * COUT / 4 / 1024, 256>>>(s_feats, out);
}

// round 13
// speedup vs baseline: 2.6559x; 1.0580x over previous
#include <cuda_runtime.h>
#include <cuda_bf16.h>
#include <mma.h>
#include <cstdint>

#define NPTS 65536
#define HN 32
#define CIN 256
#define CMID 64
#define COUT 256
#define KP 15
#define SLOPE 0.1f
#define EPSV 1e-5f

using ull = unsigned long long;
using namespace nvcuda;

// ---- packed f32x2 helpers ----
__device__ __forceinline__ ull pk2(float lo, float hi) {
    ull r; asm("mov.b64 %0, {%1,%2};" : "=l"(r) : "f"(lo), "f"(hi)); return r;
}
__device__ __forceinline__ ull dup2(float v) { return pk2(v, v); }
__device__ __forceinline__ void fma2(ull& d, ull a, ull b) {
    asm("fma.rn.f32x2 %0, %1, %2, %3;" : "=l"(d) : "l"(a), "l"(b), "l"(d));
}
__device__ __forceinline__ float2 up2(ull v) {
    float lo, hi; asm("mov.b64 {%0,%1}, %2;" : "=f"(lo), "=f"(hi) : "l"(v));
    return make_float2(lo, hi);
}

// ---- cp.async helpers ----
__device__ __forceinline__ void cp16(void* sdst, const void* gsrc) {
    uint32_t s = (uint32_t)__cvta_generic_to_shared(sdst);
    asm volatile("cp.async.cg.shared.global [%0], [%1], 16;" :: "r"(s), "l"(gsrc));
}
#define CP_COMMIT() asm volatile("cp.async.commit_group;" ::: "memory")
#define CP_WAIT(n)  asm volatile("cp.async.wait_group %0;" :: "n"(n) : "memory")

// ---- hi/lo split helper ----
__device__ __forceinline__ void split2(float x, float y, uint32_t& h, uint32_t& l) {
    __nv_bfloat162 hh = __floats2bfloat162_rn(x, y);
    __nv_bfloat162 ll = __floats2bfloat162_rn(x - __bfloat162float(hh.x),
                                              y - __bfloat162float(hh.y));
    h = *(uint32_t*)&hh;
    l = *(uint32_t*)&ll;
}

// ---- scratch (device globals; aligned for vector-cast access) ----
__device__ __align__(256) float g_x1[NPTS * CMID];            // 16 MB
__device__ __align__(256) float g_out2[NPTS * CMID];          // 16 MB
__device__ __align__(256) float g_y[NPTS * COUT];             // 64 MB
__device__ __align__(256) __nv_bfloat16 g_Ahi[NPTS * 960];    // 126 MB
__device__ __align__(256) __nv_bfloat16 g_Alo[NPTS * 960];    // 126 MB
__device__ __align__(256) __nv_bfloat16 g_BhiT[64 * 960];
__device__ __align__(256) __nv_bfloat16 g_BloT[64 * 960];
__device__ float g_nnr[NPTS];
__device__ double g_sum1[CMID], g_sq1[CMID];
__device__ double g_sum2[CMID], g_sq2[CMID];
__device__ double g_sum3[COUT], g_sq3[COUT];

// ---- k_prep: zero stats (block 0) + kw transpose/split ----
__global__ __launch_bounds__(256) void k_prep(const float* __restrict__ kw) {
    int t = threadIdx.x;
    if (blockIdx.x == 0) {
        if (t < CMID) { g_sum1[t] = 0.0; g_sq1[t] = 0.0; g_sum2[t] = 0.0; g_sq2[t] = 0.0; }
        if (t < COUT) { g_sum3[t] = 0.0; g_sq3[t] = 0.0; }
    }
    int idx = blockIdx.x * 256 + t;
    int d = idx / 960;
    int r = idx % 960;
    float v = kw[r * 64 + d];
    __nv_bfloat16 h = __float2bfloat16(v);
    g_BhiT[d * 960 + r] = h;
    g_BloT[d * 960 + r] = __float2bfloat16(v - __bfloat162float(h));
}

// ---- GEMM1 (WMMA bf16 hi/lo): x1 = s_feats @ W1 + b1 ; GN1 stats ----
#define G1S 72
#define G1_SMEM (55296 + 512)

__global__ __launch_bounds__(256) void k_gemm1(const float* __restrict__ A,
                                               const float* __restrict__ W,
                                               const float* __restrict__ bias) {
    extern __shared__ __nv_bfloat16 sb1[];
    __nv_bfloat16* sAhi = sb1;
    __nv_bfloat16* sAlo = sb1 + 9216;
    __nv_bfloat16* sBhi = sb1 + 18432;
    __nv_bfloat16* sBlo = sb1 + 23040;
    float* s_stats = (float*)(sb1 + 27648);
    float* sOut = (float*)sb1;

    int t = threadIdx.x;
    int warp = t >> 5;
    int wr = warp >> 1, wc = warp & 1;
    int row0 = blockIdx.x * 128;
    if (t < 128) s_stats[t] = 0.f;

    wmma::fragment<wmma::accumulator, 16, 16, 16, float> acc[2][2];
#pragma unroll
    for (int i = 0; i < 2; i++)
#pragma unroll
        for (int j = 0; j < 2; j++) wmma::fill_fragment(acc[i][j], 0.0f);

    for (int ch = 0; ch < 4; ch++) {
        __syncthreads();
#pragma unroll
        for (int i = 0; i < 8; i++) {
            int e = t + i * 256;
            int r = e >> 4, j = e & 15;
            float4 v = *(const float4*)&A[(size_t)(row0 + r) * CIN + ch * 64 + j * 4];
            uint32_t h0, l0, h1, l1;
            split2(v.x, v.y, h0, l0);
            split2(v.z, v.w, h1, l1);
            *(uint2*)&sAhi[r * G1S + j * 4] = make_uint2(h0, h1);
            *(uint2*)&sAlo[r * G1S + j * 4] = make_uint2(l0, l1);
        }
#pragma unroll
        for (int i = 0; i < 4; i++) {
            int e = t + i * 256;
            int r = e >> 4, j = e & 15;
            float4 v = *(const float4*)&W[(size_t)(ch * 64 + r) * CMID + j * 4];
            uint32_t h0, l0, h1, l1;
            split2(v.x, v.y, h0, l0);
            split2(v.z, v.w, h1, l1);
            *(uint2*)&sBhi[r * G1S + j * 4] = make_uint2(h0, h1);
            *(uint2*)&sBlo[r * G1S + j * 4] = make_uint2(l0, l1);
        }
        __syncthreads();

#pragma unroll
        for (int kk = 0; kk < 4; kk++) {
            wmma::fragment<wmma::matrix_a, 16, 16, 16, __nv_bfloat16, wmma::row_major> a_hi[2], a_lo[2];
            wmma::fragment<wmma::matrix_b, 16, 16, 16, __nv_bfloat16, wmma::row_major> b_hi[2], b_lo[2];
#pragma unroll
            for (int i = 0; i < 2; i++) {
                wmma::load_matrix_sync(a_hi[i], &sAhi[(wr * 32 + i * 16) * G1S + kk * 16], G1S);
                wmma::load_matrix_sync(a_lo[i], &sAlo[(wr * 32 + i * 16) * G1S + kk * 16], G1S);
            }
#pragma unroll
            for (int j = 0; j < 2; j++) {
                wmma::load_matrix_sync(b_hi[j], &sBhi[(kk * 16) * G1S + wc * 32 + j * 16], G1S);
                wmma::load_matrix_sync(b_lo[j], &sBlo[(kk * 16) * G1S + wc * 32 + j * 16], G1S);
            }
#pragma unroll
            for (int i = 0; i < 2; i++)
#pragma unroll
                for (int j = 0; j < 2; j++) {
                    wmma::mma_sync(acc[i][j], a_hi[i], b_hi[j], acc[i][j]);
                    wmma::mma_sync(acc[i][j], a_lo[i], b_hi[j], acc[i][j]);
                    wmma::mma_sync(acc[i][j], a_hi[i], b_lo[j], acc[i][j]);
                }
        }
    }

    __syncthreads();
#pragma unroll
    for (int i = 0; i < 2; i++)
#pragma unroll
        for (int j = 0; j < 2; j++)
            wmma::store_matrix_sync(&sOut[(wr * 32 + i * 16) * G1S + wc * 32 + j * 16],
                                    acc[i][j], G1S, wmma::mem_row_major);
    __syncthreads();

    {
        int c4 = t & 15;
        float b0 = bias[c4 * 4 + 0], b1 = bias[c4 * 4 + 1];
        float b2 = bias[c4 * 4 + 2], b3 = bias[c4 * 4 + 3];
        float cs[4] = {0, 0, 0, 0}, cq[4] = {0, 0, 0, 0};
#pragma unroll
        for (int i = 0; i < 8; i++) {
            int r = (t >> 4) + i * 16;
            float4 v = *(const float4*)&sOut[r * G1S + c4 * 4];
            v.x += b0; v.y += b1; v.z += b2; v.w += b3;
            *(float4*)&g_x1[(size_t)(row0 + r) * CMID + c4 * 4] = v;
            cs[0] += v.x; cq[0] += v.x * v.x;
            cs[1] += v.y; cq[1] += v.y * v.y;
            cs[2] += v.z; cq[2] += v.z * v.z;
            cs[3] += v.w; cq[3] += v.w * v.w;
        }
#pragma unroll
        for (int j = 0; j < 4; j++) {
            atomicAdd(&s_stats[c4 * 4 + j], cs[j]);
            atomicAdd(&s_stats[64 + c4 * 4 + j], cq[j]);
        }
    }
    __syncthreads();
    if (t < 64) {
        atomicAdd(&g_sum1[t], (double)s_stats[t]);
        atomicAdd(&g_sq1[t], (double)s_stats[64 + t]);
    }
}

// ---- k_apply1: GN1 + leaky in place on x1 (inline stat finalize, MLP-4) ----
__global__ __launch_bounds__(256) void k_apply1(const float* __restrict__ gamma,
                                                const float* __restrict__ beta) {
    __shared__ float s_a[64], s_b[64];
    int t = threadIdx.x;
    if (t < 64) {
        int g = t >> 1;
        double s = g_sum1[g * 2] + g_sum1[g * 2 + 1];
        double q = g_sq1[g * 2] + g_sq1[g * 2 + 1];
        double cnt = 2.0 * (double)NPTS;
        double mean = s / cnt;
        double var = q / cnt - mean * mean;
        float inv = rsqrtf((float)var + EPSV);
        float av = gamma[t] * inv;
        s_a[t] = av;
        s_b[t] = beta[t] - (float)mean * av;
    }
    __syncthreads();
    int base = blockIdx.x * 1024 + t;    // 4 float4s / thread, stride 256
    int c = (base & 15) * 4;             // constant across u (256 % 16 == 0)
    float a0 = s_a[c + 0], a1 = s_a[c + 1], a2 = s_a[c + 2], a3 = s_a[c + 3];
    float b0 = s_b[c + 0], b1 = s_b[c + 1], b2 = s_b[c + 2], b3 = s_b[c + 3];
    float4 v[4];
#pragma unroll
    for (int u = 0; u < 4; u++) v[u] = ((const float4*)g_x1)[base + u * 256];
#pragma unroll
    for (int u = 0; u < 4; u++) {
        float4 r;
        r.x = a0 * v[u].x + b0;
        r.y = a1 * v[u].y + b1;
        r.z = a2 * v[u].z + b2;
        r.w = a3 * v[u].w + b3;
        r.x = r.x >= 0.f ? r.x : SLOPE * r.x;
        r.y = r.y >= 0.f ? r.y : SLOPE * r.y;
        r.z = r.z >= 0.f ? r.z : SLOPE * r.z;
        r.w = r.w >= 0.f ? r.w : SLOPE * r.w;
        ((float4*)g_x1)[base + u * 256] = r;
    }
}

// ---- k_gather: KPConv phases 1+2, plain x1 reads, LDS.128 weight loads ----
__global__ __launch_bounds__(256, 3) void k_gather(
        const float* __restrict__ qp, const float* __restrict__ sp,
        const int* __restrict__ nbr, const float* __restrict__ kpts) {
    __shared__ float s_kp[48];
    __shared__ __align__(16) float s_w[8 * 32 * 16];
    __shared__ int s_off[256];

    int t = threadIdx.x;
    int p0 = blockIdx.x * 8;

    if (t < 45) s_kp[t] = kpts[t];
    __syncthreads();

    {
        int p = t >> 5, h = t & 31;
        int idx = nbr[(p0 + p) * HN + h];
        bool valid = (unsigned)idx < NPTS;
        s_off[t] = valid ? idx * CMID : -1;
        float dx, dy, dz;
        if (valid) {
            dx = sp[idx * 3 + 0] - qp[(p0 + p) * 3 + 0];
            dy = sp[idx * 3 + 1] - qp[(p0 + p) * 3 + 1];
            dz = sp[idx * 3 + 2] - qp[(p0 + p) * 3 + 2];
        } else { dx = dy = dz = 1e10f; }
        unsigned m = __ballot_sync(0xffffffffu, valid);
        if ((t & 31) == 0) {
            int nn = __popc(m);
            g_nnr[p0 + p] = 1.0f / (float)(nn > 1 ? nn : 1);
        }
#pragma unroll
        for (int k = 0; k < KP; k++) {
            float ex = dx - s_kp[k * 3 + 0];
            float ey = dy - s_kp[k * 3 + 1];
            float ez = dz - s_kp[k * 3 + 2];
            float dist = sqrtf(ex * ex + ey * ey + ez * ez);
            s_w[t * 16 + k] = fmaxf(1.0f - dist, 0.0f);
        }
        s_w[t * 16 + 15] = 0.f;
    }
    __syncthreads();

    {
        int p = t >> 5;
        int c2 = (t & 31) * 2;
        ull acc[8][2];
#pragma unroll
        for (int a = 0; a < 8; a++) { acc[a][0] = 0ull; acc[a][1] = 0ull; }
#pragma unroll 4
        for (int h = 0; h < HN; h++) {
            int off = s_off[p * 32 + h];
            float2 f = make_float2(0.f, 0.f);
            if (off >= 0) f = *(const float2*)&g_x1[(size_t)off + c2];
            ull fd0 = dup2(f.x), fd1 = dup2(f.y);
            const ulonglong2* w4 = (const ulonglong2*)&s_w[(p * 32 + h) * 16];
            ulonglong2 wa = w4[0], wb = w4[1], wcc = w4[2], wd = w4[3];
            fma2(acc[0][0], wa.x, fd0);  fma2(acc[0][1], wa.x, fd1);
            fma2(acc[1][0], wa.y, fd0);  fma2(acc[1][1], wa.y, fd1);
            fma2(acc[2][0], wb.x, fd0);  fma2(acc[2][1], wb.x, fd1);
            fma2(acc[3][0], wb.y, fd0);  fma2(acc[3][1], wb.y, fd1);
            fma2(acc[4][0], wcc.x, fd0); fma2(acc[4][1], wcc.x, fd1);
            fma2(acc[5][0], wcc.y, fd0); fma2(acc[5][1], wcc.y, fd1);
            fma2(acc[6][0], wd.x, fd0);  fma2(acc[6][1], wd.x, fd1);
            fma2(acc[7][0], wd.y, fd0);  fma2(acc[7][1], wd.y, fd1);
        }
        int n = p0 + p;
        uint32_t* hiw = (uint32_t*)g_Ahi;
        uint32_t* low = (uint32_t*)g_Alo;
        int base = n * 480 + (c2 >> 1);
#pragma unroll
        for (int kp2 = 0; kp2 < 8; kp2++) {
            float2 a0 = up2(acc[kp2][0]);
            float2 a1 = up2(acc[kp2][1]);
            int k0 = kp2 * 2;
            {
                uint32_t h, l;
                split2(a0.x, a1.x, h, l);
                hiw[base + k0 * 32] = h;
                low[base + k0 * 32] = l;
            }
            if (k0 + 1 < KP) {
                uint32_t h, l;
                split2(a0.y, a1.y, h, l);
                hiw[base + (k0 + 1) * 32] = h;
                low[base + (k0 + 1) * 32] = l;
            }
        }
    }
}

// ---- k_pgemm: WMMA + cp.async double buffering + fused GN2 stats ----
#define PGS 72
#define PG_A(h, b) (sbp + (h) * 18432 + (b) * 9216)
#define PG_B(h, b) (sbp + 36864 + (h) * 9216 + (b) * 4608)
#define PG_SMEM (110592 + 512)

__global__ __launch_bounds__(256, 2) void k_pgemm(const float* __restrict__ kb) {
    extern __shared__ __nv_bfloat16 sbp[];
    float* s_stats = (float*)(sbp + 55296);
    float* sOut = (float*)sbp;

    int t = threadIdx.x;
    int warp = t >> 5;
    int wr = warp >> 1, wc = warp & 1;
    int row0 = blockIdx.x * 128;
    if (t < 128) s_stats[t] = 0.f;

    wmma::fragment<wmma::accumulator, 16, 16, 16, float> acc[2][2];
#pragma unroll
    for (int i = 0; i < 2; i++)
#pragma unroll
        for (int j = 0; j < 2; j++) wmma::fill_fragment(acc[i][j], 0.0f);

    const __nv_bfloat16* Ahi = g_Ahi + (size_t)row0 * 960;
    const __nv_bfloat16* Alo = g_Alo + (size_t)row0 * 960;

    auto fill = [&](int ch, int b) {
#pragma unroll
        for (int i = 0; i < 4; i++) {
            int e = t + i * 256;
            int r = e >> 3, j = e & 7;
            cp16(PG_A(0, b) + r * PGS + j * 8, Ahi + (size_t)r * 960 + ch * 64 + j * 8);
            cp16(PG_A(1, b) + r * PGS + j * 8, Alo + (size_t)r * 960 + ch * 64 + j * 8);
        }
#pragma unroll
        for (int i = 0; i < 2; i++) {
            int e = t + i * 256;
            int r = e >> 3, j = e & 7;
            cp16(PG_B(0, b) + r * PGS + j * 8, g_BhiT + (size_t)r * 960 + ch * 64 + j * 8);
            cp16(PG_B(1, b) + r * PGS + j * 8, g_BloT + (size_t)r * 960 + ch * 64 + j * 8);
        }
    };

    fill(0, 0);
    CP_COMMIT();

    for (int ch = 0; ch < 15; ch++) {
        int buf = ch & 1;
        if (ch < 14) {
            fill(ch + 1, buf ^ 1);
            CP_COMMIT();
            CP_WAIT(1);
        } else {
            CP_WAIT(0);
        }
        __syncthreads();

        __nv_bfloat16* sAhi = PG_A(0, buf);
        __nv_bfloat16* sAlo = PG_A(1, buf);
        __nv_bfloat16* sBhi = PG_B(0, buf);
        __nv_bfloat16* sBlo = PG_B(1, buf);
#pragma unroll
        for (int kk = 0; kk < 4; kk++) {
            wmma::fragment<wmma::matrix_a, 16, 16, 16, __nv_bfloat16, wmma::row_major> a_hi[2], a_lo[2];
            wmma::fragment<wmma::matrix_b, 16, 16, 16, __nv_bfloat16, wmma::col_major> b_hi[2], b_lo[2];
#pragma unroll
            for (int i = 0; i < 2; i++) {
                wmma::load_matrix_sync(a_hi[i], &sAhi[(wr * 32 + i * 16) * PGS + kk * 16], PGS);
                wmma::load_matrix_sync(a_lo[i], &sAlo[(wr * 32 + i * 16) * PGS + kk * 16], PGS);
            }
#pragma unroll
            for (int j = 0; j < 2; j++) {
                wmma::load_matrix_sync(b_hi[j], &sBhi[(wc * 32 + j * 16) * PGS + kk * 16], PGS);
                wmma::load_matrix_sync(b_lo[j], &sBlo[(wc * 32 + j * 16) * PGS + kk * 16], PGS);
            }
#pragma unroll
            for (int i = 0; i < 2; i++)
#pragma unroll
                for (int j = 0; j < 2; j++) {
                    wmma::mma_sync(acc[i][j], a_hi[i], b_hi[j], acc[i][j]);
                    wmma::mma_sync(acc[i][j], a_lo[i], b_hi[j], acc[i][j]);
                    wmma::mma_sync(acc[i][j], a_hi[i], b_lo[j], acc[i][j]);
                }
        }
        __syncthreads();
    }

#pragma unroll
    for (int i = 0; i < 2; i++)
#pragma unroll
        for (int j = 0; j < 2; j++)
            wmma::store_matrix_sync(&sOut[(wr * 32 + i * 16) * PGS + wc * 32 + j * 16],
                                    acc[i][j], PGS, wmma::mem_row_major);
    __syncthreads();

    {
        int c4 = t & 15;
        float b0 = kb[c4 * 4 + 0], b1 = kb[c4 * 4 + 1];
        float b2 = kb[c4 * 4 + 2], b3 = kb[c4 * 4 + 3];
        float cs[4] = {0, 0, 0, 0}, cq[4] = {0, 0, 0, 0};
#pragma unroll
        for (int i = 0; i < 8; i++) {
            int r = (t >> 4) + i * 16;
            float nnr = g_nnr[row0 + r];
            float4 v = *(const float4*)&sOut[r * PGS + c4 * 4];
            v.x = v.x * nnr + b0;
            v.y = v.y * nnr + b1;
            v.z = v.z * nnr + b2;
            v.w = v.w * nnr + b3;
            *(float4*)&g_out2[(size_t)(row0 + r) * CMID + c4 * 4] = v;
            cs[0] += v.x; cq[0] += v.x * v.x;
            cs[1] += v.y; cq[1] += v.y * v.y;
            cs[2] += v.z; cq[2] += v.z * v.z;
            cs[3] += v.w; cq[3] += v.w * v.w;
        }
#pragma unroll
        for (int j = 0; j < 4; j++) {
            atomicAdd(&s_stats[c4 * 4 + j], cs[j]);
            atomicAdd(&s_stats[64 + c4 * 4 + j], cq[j]);
        }
    }
    __syncthreads();
    if (t < 64) {
        atomicAdd(&g_sum2[t], (double)s_stats[t]);
        atomicAdd(&g_sq2[t], (double)s_stats[64 + t]);
    }
}

// ---- GEMM2 (WMMA bf16 hi/lo): y = leaky(GN2(out2)) @ W2 + b2 ; GN3 stats ----
// inline GN2 finalize from g_sum2/g_sq2
#define G2AS 72
#define G2BS 264
#define G2_SMEM (86016 + 2048 + 512)

__global__ __launch_bounds__(256) void k_gemm2(const float* __restrict__ W2,
                                               const float* __restrict__ b2,
                                               const float* __restrict__ gg,
                                               const float* __restrict__ gb) {
    extern __shared__ __nv_bfloat16 sb2[];
    __nv_bfloat16* sAhi = sb2;
    __nv_bfloat16* sAlo = sb2 + 4608;
    __nv_bfloat16* sBhi = sb2 + 9216;
    __nv_bfloat16* sBlo = sb2 + 26112;
    float* s_stats = (float*)((char*)sb2 + 86016);   // 512 floats
    float* s_a2 = (float*)((char*)sb2 + 86016 + 2048);  // 64
    float* s_b2 = s_a2 + 64;                             // 64
    float* sOut = (float*)sb2;

    int t = threadIdx.x;
    int warp = t >> 5;
    int wr = warp >> 2, wc = warp & 3;
    int row0 = blockIdx.x * 64;
    s_stats[t] = 0.f; s_stats[t + 256] = 0.f;
    if (t < 64) {
        int g = t >> 1;
        double s = g_sum2[g * 2] + g_sum2[g * 2 + 1];
        double q = g_sq2[g * 2] + g_sq2[g * 2 + 1];
        double cnt = 2.0 * (double)NPTS;
        double mean = s / cnt;
        double var = q / cnt - mean * mean;
        float inv = rsqrtf((float)var + EPSV);
        float av = gg[t] * inv;
        s_a2[t] = av;
        s_b2[t] = gb[t] - (float)mean * av;
    }
    __syncthreads();

#pragma unroll
    for (int i = 0; i < 4; i++) {
        int e = t + i * 256;
        int r = e >> 4, j = e & 15;
        float4 v = *(const float4*)&g_out2[(size_t)(row0 + r) * CMID + j * 4];
        float a0 = s_a2[j * 4 + 0], a1 = s_a2[j * 4 + 1], a2 = s_a2[j * 4 + 2], a3 = s_a2[j * 4 + 3];
        float c0 = s_b2[j * 4 + 0], c1 = s_b2[j * 4 + 1], c2 = s_b2[j * 4 + 2], c3 = s_b2[j * 4 + 3];
        v.x = a0 * v.x + c0; v.x = v.x >= 0.f ? v.x : SLOPE * v.x;
        v.y = a1 * v.y + c1; v.y = v.y >= 0.f ? v.y : SLOPE * v.y;
        v.z = a2 * v.z + c2; v.z = v.z >= 0.f ? v.z : SLOPE * v.z;
        v.w = a3 * v.w + c3; v.w = v.w >= 0.f ? v.w : SLOPE * v.w;
        uint32_t h0, l0, h1, l1;
        split2(v.x, v.y, h0, l0);
        split2(v.z, v.w, h1, l1);
        *(uint2*)&sAhi[r * G2AS + j * 4] = make_uint2(h0, h1);
        *(uint2*)&sAlo[r * G2AS + j * 4] = make_uint2(l0, l1);
    }
#pragma unroll
    for (int i = 0; i < 16; i++) {
        int e = t + i * 256;
        int r = e >> 6, j = e & 63;
        float4 v = *(const float4*)&W2[(size_t)r * COUT + j * 4];
        uint32_t h0, l0, h1, l1;
        split2(v.x, v.y, h0, l0);
        split2(v.z, v.w, h1, l1);
        *(uint2*)&sBhi[r * G2BS + j * 4] = make_uint2(h0, h1);
        *(uint2*)&sBlo[r * G2BS + j * 4] = make_uint2(l0, l1);
    }
    __syncthreads();

    wmma::fragment<wmma::accumulator, 16, 16, 16, float> acc[2][4];
#pragma unroll
    for (int i = 0; i < 2; i++)
#pragma unroll
        for (int j = 0; j < 4; j++) wmma::fill_fragment(acc[i][j], 0.0f);

#pragma unroll
    for (int kk = 0; kk < 4; kk++) {
        wmma::fragment<wmma::matrix_a, 16, 16, 16, __nv_bfloat16, wmma::row_major> a_hi[2], a_lo[2];
        wmma::fragment<wmma::matrix_b, 16, 16, 16, __nv_bfloat16, wmma::row_major> b_hi[4], b_lo[4];
#pragma unroll
        for (int i = 0; i < 2; i++) {
            wmma::load_matrix_sync(a_hi[i], &sAhi[(wr * 32 + i * 16) * G2AS + kk * 16], G2AS);
            wmma::load_matrix_sync(a_lo[i], &sAlo[(wr * 32 + i * 16) * G2AS + kk * 16], G2AS);
        }
#pragma unroll
        for (int j = 0; j < 4; j++) {
            wmma::load_matrix_sync(b_hi[j], &sBhi[(kk * 16) * G2BS + wc * 64 + j * 16], G2BS);
            wmma::load_matrix_sync(b_lo[j], &sBlo[(kk * 16) * G2BS + wc * 64 + j * 16], G2BS);
        }
#pragma unroll
        for (int i = 0; i < 2; i++)
#pragma unroll
            for (int j = 0; j < 4; j++) {
                wmma::mma_sync(acc[i][j], a_hi[i], b_hi[j], acc[i][j]);
                wmma::mma_sync(acc[i][j], a_lo[i], b_hi[j], acc[i][j]);
                wmma::mma_sync(acc[i][j], a_hi[i], b_lo[j], acc[i][j]);
            }
    }

    __syncthreads();
#pragma unroll
    for (int i = 0; i < 2; i++)
#pragma unroll
        for (int j = 0; j < 4; j++)
            wmma::store_matrix_sync(&sOut[(wr * 32 + i * 16) * G2BS + wc * 64 + j * 16],
                                    acc[i][j], G2BS, wmma::mem_row_major);
    __syncthreads();

    {
        int c4 = t & 63;
        float b0 = b2[c4 * 4 + 0], b1 = b2[c4 * 4 + 1];
        float bb2 = b2[c4 * 4 + 2], b3 = b2[c4 * 4 + 3];
        float cs[4] = {0, 0, 0, 0}, cq[4] = {0, 0, 0, 0};
#pragma unroll
        for (int i = 0; i < 16; i++) {
            int r = (t >> 6) + i * 4;
            float4 v = *(const float4*)&sOut[r * G2BS + c4 * 4];
            v.x += b0; v.y += b1; v.z += bb2; v.w += b3;
            *(float4*)&g_y[(size_t)(row0 + r) * COUT + c4 * 4] = v;
            cs[0] += v.x; cq[0] += v.x * v.x;
            cs[1] += v.y; cq[1] += v.y * v.y;
            cs[2] += v.z; cq[2] += v.z * v.z;
            cs[3] += v.w; cq[3] += v.w * v.w;
        }
#pragma unroll
        for (int j = 0; j < 4; j++) {
            atomicAdd(&s_stats[c4 * 4 + j], cs[j]);
            atomicAdd(&s_stats[256 + c4 * 4 + j], cq[j]);
        }
    }
    __syncthreads();
    atomicAdd(&g_sum3[t], (double)s_stats[t]);
    atomicAdd(&g_sq3[t], (double)s_stats[256 + t]);
}

// ---- final: out = leaky(GN3(y) + s_feats), inline GN3 finalize, MLP-8 ----
__global__ __launch_bounds__(256) void k_final(const float* __restrict__ sf,
                                               const float* __restrict__ g2f,
                                               const float* __restrict__ beta2f,
                                               float* __restrict__ out) {
    __shared__ float s_a[256], s_b[256];
    int t = threadIdx.x;
    {
        int g = t >> 3;
        double s = 0.0, q = 0.0;
#pragma unroll
        for (int i = 0; i < 8; i++) { s += g_sum3[g * 8 + i]; q += g_sq3[g * 8 + i]; }
        double cnt = 8.0 * (double)NPTS;
        double mean = s / cnt;
        double var = q / cnt - mean * mean;
        float inv = rsqrtf((float)var + EPSV);
        float av = g2f[t] * inv;
        s_a[t] = av;
        s_b[t] = beta2f[t] - (float)mean * av;
    }
    __syncthreads();
    int base = blockIdx.x * 1024 + t;
    int c = (base & 63) * 4;
    float a0 = s_a[c + 0], a1 = s_a[c + 1], a2 = s_a[c + 2], a3 = s_a[c + 3];
    float b0 = s_b[c + 0], b1 = s_b[c + 1], b2 = s_b[c + 2], b3 = s_b[c + 3];
    float4 y[4], s[4];
#pragma unroll
    for (int u = 0; u < 4; u++) {
        y[u] = ((const float4*)g_y)[base + u * 256];
        s[u] = ((const float4*)sf)[base + u * 256];
    }
#pragma unroll
    for (int u = 0; u < 4; u++) {
        float4 r;
        r.x = a0 * y[u].x + b0 + s[u].x;
        r.y = a1 * y[u].y + b1 + s[u].y;
        r.z = a2 * y[u].z + b2 + s[u].z;
        r.w = a3 * y[u].w + b3 + s[u].w;
        r.x = r.x >= 0.f ? r.x : SLOPE * r.x;
        r.y = r.y >= 0.f ? r.y : SLOPE * r.y;
        r.z = r.z >= 0.f ? r.z : SLOPE * r.z;
        r.w = r.w >= 0.f ? r.w : SLOPE * r.w;
        ((float4*)out)[base + u * 256] = r;
    }
}

extern "C" void kernel_launch(void* const* d_in, const int* in_sizes, int n_in,
                              void* d_out, int out_size) {
    const float* s_feats  = (const float*)d_in[0];
    const float* q_points = (const float*)d_in[1];
    const float* s_points = (const float*)d_in[2];
    const int*   nbr      = (const int*)d_in[3];
    const float* W1       = (const float*)d_in[4];
    const float* b1       = (const float*)d_in[5];
    const float* g1       = (const float*)d_in[6];
    const float* beta1    = (const float*)d_in[7];
    const float* kpw      = (const float*)d_in[8];
    const float* kpb      = (const float*)d_in[9];
    const float* kpts     = (const float*)d_in[10];
    const float* gg       = (const float*)d_in[11];
    const float* gb       = (const float*)d_in[12];
    const float* W2       = (const float*)d_in[13];
    const float* b2       = (const float*)d_in[14];
    const float* g2       = (const float*)d_in[15];
    const float* beta2    = (const float*)d_in[16];
    float* out = (float*)d_out;

    cudaFuncSetAttribute(k_gemm1, cudaFuncAttributeMaxDynamicSharedMemorySize, G1_SMEM);
    cudaFuncSetAttribute(k_pgemm, cudaFuncAttributeMaxDynamicSharedMemorySize, PG_SMEM);
    cudaFuncSetAttribute(k_gemm2, cudaFuncAttributeMaxDynamicSharedMemorySize, G2_SMEM);

    k_prep<<<240, 256>>>(kpw);
    k_gemm1<<<NPTS / 128, 256, G1_SMEM>>>(s_feats, W1, b1);
    k_apply1<<<NPTS * CMID / 4 / 1024, 256>>>(g1, beta1);
    k_gather<<<NPTS / 8, 256>>>(q_points, s_points, nbr, kpts);
    k_pgemm<<<NPTS / 128, 256, PG_SMEM>>>(kpb);
    k_gemm2<<<NPTS / 64, 256, G2_SMEM>>>(W2, b2, gg, gb);
    k_final<<<NPTS * COUT / 4 / 1024, 256>>>(s_feats, g2, beta2, out);
}